// round 11
// baseline (speedup 1.0000x reference)
#include <cuda_runtime.h>
#include <cuda_bf16.h>
#include <math.h>
#include <float.h>
#include <stdint.h>

#define BB    32
#define CC    384
#define HH    56
#define WW    56
#define NN    3136
#define TOPK  98
#define NTOK  99
#define NHEAD 8
#define HDIM  48
#define EPSB  1e-5f
#define MTOK  (BB*NTOK)   // 3168 tokens
#define NTIL  (NN/64)     // 49
#define CTIL  (CC/64)     // 6

// ===================== PTX helpers (sm_80-era, legal at compute_103) =====================
__device__ __forceinline__ uint32_t smem_to_u32(const void* smem_ptr) {
    uint32_t addr;
    asm("{ .reg .u64 tmp; cvta.to.shared.u64 tmp, %1; cvt.u32.u64 %0, tmp; }"
        : "=r"(addr) : "l"(smem_ptr));
    return addr;
}
#define CP_ASYNC16(dst, src, sz) \
    asm volatile("cp.async.cg.shared.global [%0], [%1], 16, %2;" \
        :: "r"((uint32_t)(dst)), "l"(src), "r"((uint32_t)(sz)) : "memory")
#define CP_ASYNC_COMMIT() asm volatile("cp.async.commit_group;" ::: "memory")
#define CP_ASYNC_WAIT(n)  asm volatile("cp.async.wait_group %0;" :: "n"(n) : "memory")

__device__ __forceinline__ void ldsm_x4(uint32_t (&r)[4], uint32_t addr){
    asm volatile("ldmatrix.sync.aligned.m8n8.x4.shared.b16 {%0,%1,%2,%3}, [%4];"
        : "=r"(r[0]),"=r"(r[1]),"=r"(r[2]),"=r"(r[3]) : "r"(addr));
}
__device__ __forceinline__ void mma16816(float (&d)[4], const uint32_t (&a)[4],
                                         uint32_t b0, uint32_t b1){
    asm volatile("mma.sync.aligned.m16n8k16.row.col.f32.bf16.bf16.f32 "
        "{%0,%1,%2,%3}, {%4,%5,%6,%7}, {%8,%9}, {%0,%1,%2,%3};"
        : "+f"(d[0]),"+f"(d[1]),"+f"(d[2]),"+f"(d[3])
        : "r"(a[0]),"r"(a[1]),"r"(a[2]),"r"(a[3]), "r"(b0),"r"(b1));
}

// ===================== device scratch =====================
__device__ float g_h1[(size_t)BB*CC*NN];            // gelu(fc1(bn(x)))  [b][c][n] fp32
__device__ __nv_bfloat16 g_xth[(size_t)BB*NN*CC];   // [b][n][c] bf16 hi (x, then dwconv out)
__device__ __nv_bfloat16 g_xtl[(size_t)BB*NN*CC];   // [b][n][c] bf16 lo
__device__ float g_scores[BB*NN];
__device__ float g_scores_p[(size_t)BB*CTIL*NN];    // partial scores per c-tile
__device__ float g_sumx_p [(size_t)BB*NTIL*CC];     // partial col sums per n-tile
__device__ float g_sumx2_p[(size_t)BB*NTIL*CC];
__device__ float g_sumx [BB*CC];
__device__ float g_sumx2[BB*CC];
__device__ int   g_topidx[BB*TOPK];
__device__ float g_qkv    [(size_t)MTOK*3*CC];
__device__ float g_attnout[MTOK*CC];
__device__ float g_ptok   [MTOK*CC];
__device__ __nv_bfloat16 g_W1h[CC*CC], g_W1l[CC*CC];
__device__ __nv_bfloat16 g_W2h[CC*CC], g_W2l[CC*CC];
__device__ __nv_bfloat16 g_tokh[MTOK*CC], g_tokl[MTOK*CC];
__device__ __nv_bfloat16 g_aoh [MTOK*CC], g_aol [MTOK*CC];
__device__ __nv_bfloat16 g_qwh [3*CC*CC], g_qwl [3*CC*CC];
__device__ __nv_bfloat16 g_pwh [CC*CC],   g_pwl [CC*CC];
__device__ float g_b1[CC];
__device__ float g_b2[CC];

__device__ __forceinline__ float gelu_exact(float v){
    return 0.5f * v * (1.0f + erff(v * 0.70710678118654752440f));
}
__device__ __forceinline__ void split_bf16(float v, __nv_bfloat16& h, __nv_bfloat16& l){
    h = __float2bfloat16(v);
    l = __float2bfloat16(v - __bfloat162float(h));
}
__device__ __forceinline__ void split_pack2(float v0, float v1, uint32_t& ph, uint32_t& pl){
    __nv_bfloat16 h0, l0, h1, l1;
    split_bf16(v0, h0, l0);
    split_bf16(v1, h1, l1);
    ph = (uint32_t)__bfloat16_as_ushort(h0) | ((uint32_t)__bfloat16_as_ushort(h1) << 16);
    pl = (uint32_t)__bfloat16_as_ushort(l0) | ((uint32_t)__bfloat16_as_ushort(l1) << 16);
}

// ======= fused pass over x: transpose+split AND partial stats (deterministic) =======
__global__ void k_xpass(const float* __restrict__ src,
                        __nv_bfloat16* __restrict__ dh, __nv_bfloat16* __restrict__ dl){
    __shared__ float sm[64][65];
    int b = blockIdx.z;
    int nx = blockIdx.x, cy = blockIdx.y;
    int n0 = nx * 64, c0 = cy * 64;
    const float* sp = src + (size_t)b * CC * NN;
    int t = threadIdx.x;
    #pragma unroll
    for (int p = 0; p < 4; p++){
        int row = (t >> 4) + p * 16;         // c offset
        int col = (t & 15) * 4;              // n offset
        float4 v = *(const float4*)&sp[(size_t)(c0 + row) * NN + n0 + col];
        sm[row][col+0] = v.x; sm[row][col+1] = v.y;
        sm[row][col+2] = v.z; sm[row][col+3] = v.w;
        float rs  = v.x + v.y + v.z + v.w;
        float rs2 = v.x*v.x + v.y*v.y + v.z*v.z + v.w*v.w;
        #pragma unroll
        for (int o = 8; o; o >>= 1){
            rs  += __shfl_down_sync(~0u, rs , o, 16);
            rs2 += __shfl_down_sync(~0u, rs2, o, 16);
        }
        if ((t & 15) == 0){
            size_t idx = ((size_t)b * NTIL + nx) * CC + c0 + row;
            g_sumx_p [idx] = rs;
            g_sumx2_p[idx] = rs2;
        }
    }
    __syncthreads();
    uint32_t* dh32 = (uint32_t*)(dh + (size_t)b * NN * CC);
    uint32_t* dl32 = (uint32_t*)(dl + (size_t)b * NN * CC);
    #pragma unroll
    for (int p = 0; p < 8; p++){
        int nr = (t >> 5) + p * 8;           // n offset
        int cu = t & 31;                     // packed c pair
        float v0 = sm[2*cu][nr], v1 = sm[2*cu+1][nr];
        uint32_t ph, pl;
        split_pack2(v0, v1, ph, pl);
        size_t o = ((size_t)(n0 + nr) * CC + c0) / 2 + cu;
        dh32[o] = ph; dl32[o] = pl;
        float sc = v0*v0 + v1*v1;
        #pragma unroll
        for (int of = 16; of; of >>= 1) sc += __shfl_down_sync(~0u, sc, of);
        if (cu == 0) g_scores_p[((size_t)b * CTIL + cy) * NN + n0 + nr] = sc;
    }
}

__global__ void k_redstats(){
    int i = blockIdx.x * 256 + threadIdx.x;
    if (i >= BB*CC) return;
    int b = i / CC, c = i % CC;
    float s = 0.f, s2 = 0.f;
    #pragma unroll 7
    for (int k = 0; k < NTIL; k++){
        size_t idx = ((size_t)b * NTIL + k) * CC + c;
        s += g_sumx_p[idx]; s2 += g_sumx2_p[idx];
    }
    g_sumx[i] = s; g_sumx2[i] = s2;
}
__global__ void k_scores_red(){
    int i = blockIdx.x * 256 + threadIdx.x;
    if (i >= BB*NN) return;
    int b = i / NN, n = i % NN;
    float s = 0.f;
    #pragma unroll
    for (int k = 0; k < CTIL; k++)
        s += g_scores_p[((size_t)b * CTIL + k) * NN + n];
    g_scores[i] = s;
}

// ===================== prep kernels =====================
__global__ void k_prepW1(const float* __restrict__ fc1_w, const float* __restrict__ fc1_b,
                         const float* __restrict__ bn_g, const float* __restrict__ bn_b){
    int o = blockIdx.x, c = threadIdx.x;
    float s = 0.f, s2 = 0.f;
    #pragma unroll 8
    for (int bb2 = 0; bb2 < BB; bb2++){ s += g_sumx[bb2*CC + c]; s2 += g_sumx2[bb2*CC + c]; }
    float inv = 1.f / ((float)BB * (float)NN);
    float mu  = s * inv;
    float var = s2 * inv - mu * mu;
    float a   = bn_g[c] * rsqrtf(var + EPSB);
    float bnC = bn_b[c] - mu * a;
    float w = fc1_w[o*CC + c];
    float w1 = w * a;
    __nv_bfloat16 h, l; split_bf16(w1, h, l);
    g_W1h[o*CC + c] = h; g_W1l[o*CC + c] = l;
    __shared__ float red[CC];
    red[c] = w * bnC;
    __syncthreads();
    for (int sft = 256; sft > 0; sft >>= 1){
        if (c < sft && c + sft < CC) red[c] += red[c + sft];
        __syncthreads();
    }
    if (c == 0) g_b1[o] = fc1_b[o] + red[0];
}

__global__ void k_prepW2(const float* __restrict__ proj_w, const float* __restrict__ fc2_w,
                         const float* __restrict__ fc2_b, const float* __restrict__ proj_b){
    int o = blockIdx.x, c = threadIdx.x;
    const float* pr = proj_w + o*CC;
    float acc = 0.f;
    for (int k = 0; k < CC; k++)
        acc = fmaf(pr[k], fc2_w[k*CC + c], acc);
    __nv_bfloat16 h, l; split_bf16(acc, h, l);
    g_W2h[o*CC + c] = h; g_W2l[o*CC + c] = l;
    __shared__ float red[CC];
    red[c] = pr[c] * fc2_b[c];
    __syncthreads();
    for (int s = 256; s > 0; s >>= 1){
        if (c < s && c + s < CC) red[c] += red[c + s];
        __syncthreads();
    }
    if (c == 0) g_b2[o] = proj_b[o] + red[0];
}

__global__ void k_split_rows(const float* __restrict__ src, __nv_bfloat16* __restrict__ dh,
                             __nv_bfloat16* __restrict__ dl, int n){
    int i = blockIdx.x * 256 + threadIdx.x;
    if (i < n){
        __nv_bfloat16 h, l; split_bf16(src[i], h, l);
        dh[i] = h; dl[i] = l;
    }
}

// ===================== topk + token gather =====================
__global__ void k_topk(){
    int b = blockIdx.x;
    __shared__ float sv[NN];
    for (int n = threadIdx.x; n < NN; n += blockDim.x) sv[n] = g_scores[b*NN + n];
    __syncthreads();
    __shared__ float rv[32];
    __shared__ int   ri[32];
    int lane = threadIdx.x & 31, w = threadIdx.x >> 5;
    for (int it = 0; it < TOPK; ++it){
        float best = -FLT_MAX; int bi = NN;
        for (int n = threadIdx.x; n < NN; n += blockDim.x){
            float v = sv[n];
            if (v > best){ best = v; bi = n; }
        }
        for (int o = 16; o; o >>= 1){
            float ov = __shfl_down_sync(~0u, best, o);
            int   oi = __shfl_down_sync(~0u, bi , o);
            if (ov > best || (ov == best && oi < bi)){ best = ov; bi = oi; }
        }
        if (lane == 0){ rv[w] = best; ri[w] = bi; }
        __syncthreads();
        if (w == 0){
            best = rv[lane]; bi = ri[lane];
            for (int o = 16; o; o >>= 1){
                float ov = __shfl_down_sync(~0u, best, o);
                int   oi = __shfl_down_sync(~0u, bi , o);
                if (ov > best || (ov == best && oi < bi)){ best = ov; bi = oi; }
            }
            if (lane == 0){
                g_topidx[b*TOPK + it] = bi;
                sv[bi] = -FLT_MAX;
            }
        }
        __syncthreads();
    }
}

// coalesced token gather from the transposed split planes
__global__ void k_gather_tok(const __nv_bfloat16* __restrict__ xth,
                             const __nv_bfloat16* __restrict__ xtl){
    int j = blockIdx.x, b = blockIdx.y;
    int t = threadIdx.x;                     // 192 threads, 1 uint32 each
    int idx = g_topidx[b*TOPK + j];
    const uint32_t* sh = (const uint32_t*)(xth + ((size_t)b*NN + idx)*CC);
    const uint32_t* sl = (const uint32_t*)(xtl + ((size_t)b*NN + idx)*CC);
    uint32_t* dh = (uint32_t*)(g_tokh + ((size_t)b*NTOK + j)*CC);
    uint32_t* dl = (uint32_t*)(g_tokl + ((size_t)b*NTOK + j)*CC);
    dh[t] = sh[t];
    dl[t] = sl[t];
}

// bg token: (sumx - sum of top tokens)/(N-K), from hi+lo reconstruction
__global__ void k_bgtok(){
    int b = blockIdx.x, c = threadIdx.x;
    const __nv_bfloat16* th = g_tokh + (size_t)b*NTOK*CC + c;
    const __nv_bfloat16* tl = g_tokl + (size_t)b*NTOK*CC + c;
    float s = 0.f;
    #pragma unroll 7
    for (int j = 0; j < TOPK; j++)
        s += __bfloat162float(th[(size_t)j*CC]) + __bfloat162float(tl[(size_t)j*CC]);
    float bg = (g_sumx[b*CC + c] - s) * (1.f / (float)(NN - TOPK));
    __nv_bfloat16 h, l; split_bf16(bg, h, l);
    g_tokh[((size_t)b*NTOK + TOPK)*CC + c] = h;
    g_tokl[((size_t)b*NTOK + TOPK)*CC + c] = l;
}

// ===================== attention over 99 tokens =====================
__global__ void k_attention(){
    int b = blockIdx.x / NHEAD, h = blockIdx.x % NHEAD;
    __shared__ float Ks[NTOK][HDIM];
    __shared__ float Vs[NTOK][HDIM];
    __shared__ float Qs[4][HDIM];
    __shared__ float Ps[4][NTOK];
    int tid = threadIdx.x;
    const float* qkvb = g_qkv + (size_t)b * NTOK * 3 * CC;
    for (int i = tid; i < NTOK*HDIM; i += blockDim.x){
        int t = i / HDIM, d = i % HDIM;
        Ks[t][d] = qkvb[(size_t)t*3*CC +   CC + h*HDIM + d];
        Vs[t][d] = qkvb[(size_t)t*3*CC + 2*CC + h*HDIM + d];
    }
    __syncthreads();
    int w = tid >> 5, lane = tid & 31;
    const float scale = rsqrtf((float)HDIM);
    for (int t = w; t < NTOK; t += 4){
        const float* qp = qkvb + (size_t)t*3*CC + h*HDIM;
        Qs[w][lane] = qp[lane];
        if (lane < HDIM - 32) Qs[w][lane + 32] = qp[lane + 32];
        __syncwarp();
        float sc[4]; float mx = -FLT_MAX;
        #pragma unroll
        for (int r = 0; r < 4; r++){
            int m = lane + r*32;
            float s = -FLT_MAX;
            if (m < NTOK){
                s = 0.f;
                #pragma unroll
                for (int d = 0; d < HDIM; d++) s = fmaf(Qs[w][d], Ks[m][d], s);
                s *= scale;
            }
            sc[r] = s; mx = fmaxf(mx, s);
        }
        for (int o = 16; o; o >>= 1) mx = fmaxf(mx, __shfl_xor_sync(~0u, mx, o));
        float sum = 0.f;
        #pragma unroll
        for (int r = 0; r < 4; r++){
            int m = lane + r*32;
            float e = (m < NTOK) ? expf(sc[r] - mx) : 0.f;
            sc[r] = e; sum += e;
        }
        for (int o = 16; o; o >>= 1) sum += __shfl_xor_sync(~0u, sum, o);
        float inv = 1.f / sum;
        #pragma unroll
        for (int r = 0; r < 4; r++){
            int m = lane + r*32;
            if (m < NTOK) Ps[w][m] = sc[r] * inv;
        }
        __syncwarp();
        for (int d = lane; d < HDIM; d += 32){
            float o = 0.f;
            for (int m = 0; m < NTOK; m++) o = fmaf(Ps[w][m], Vs[m][d], o);
            g_attnout[((size_t)b*NTOK + t)*CC + h*HDIM + d] = o;
        }
        __syncwarp();
    }
}

// ===================== depthwise 3x3 + transpose + split fused (packed stores) ==========
__global__ void k_dwconv_t(const float* __restrict__ dw_w, const float* __restrict__ dw_b,
                           __nv_bfloat16* __restrict__ dh, __nv_bfloat16* __restrict__ dl){
    __shared__ float t[32][33];
    int b = blockIdx.z, c0 = blockIdx.y * 32, n0 = blockIdx.x * 32;
    int tid = threadIdx.y * 32 + threadIdx.x;
    for (int r = threadIdx.y; r < 32; r += 8){
        int c = c0 + r;
        int n = n0 + threadIdx.x;
        const float* src = g_h1 + ((size_t)b * CC + c) * NN;
        int y = n / WW, xp = n % WW;
        const float* w = dw_w + c * 9;
        float acc = dw_b[c];
        #pragma unroll
        for (int dy = -1; dy <= 1; dy++){
            int yy = y + dy;
            if (yy < 0 || yy >= HH) continue;
            #pragma unroll
            for (int dx = -1; dx <= 1; dx++){
                int xw = xp + dx;
                if (xw < 0 || xw >= WW) continue;
                acc = fmaf(src[yy*WW + xw], w[(dy+1)*3 + (dx+1)], acc);
            }
        }
        t[r][threadIdx.x] = acc;
    }
    __syncthreads();
    uint32_t* dh32 = (uint32_t*)(dh + (size_t)b * NN * CC);
    uint32_t* dl32 = (uint32_t*)(dl + (size_t)b * NN * CC);
    for (int idx = tid; idx < 32 * 16; idx += 256){
        int nr = idx >> 4, cu = idx & 15;
        uint32_t ph, pl;
        split_pack2(t[2*cu][nr], t[2*cu+1][nr], ph, pl);
        size_t o = ((size_t)(n0 + nr) * CC + c0) / 2 + cu;
        dh32[o] = ph; dl32[o] = pl;
    }
}

// ====== warp-mma bf16-split GEMM (128x64 tile, 128 threads, 4 warps 2m x 2n, 64x32/warp) ==
// 3 CTAs/SM (smem 60KB/CTA), 12 warps/SM. Stage: Ah[0:128) Al[128:256) Bh[256:320) Bl[320:384) rows.
#define LDS_B 80
#define STG   (384*LDS_B)            // 30720 B per stage
#define MM_SMEM (2*STG)              // 61440 B -> 3 CTAs/SM
#define EPITCH 68
#define JSTRIDE (32*CC*2)            // 24576 bytes: 32-row stride in bf16 planes

template<int MODE>
__global__ void __launch_bounds__(128, 3)
k_mm(const __nv_bfloat16* __restrict__ Aph, const __nv_bfloat16* __restrict__ Apl,
     const __nv_bfloat16* __restrict__ Bh_, const __nv_bfloat16* __restrict__ Bl_,
     float* __restrict__ Out, const float* __restrict__ bias,
     int Mrows, int Nrows){
    extern __shared__ char smem[];
    uint32_t sb = smem_to_u32(smem);
    int tid = threadIdx.x, wid = tid >> 5, lane = tid & 31;
    // m fastest: the 3 m-CTAs sharing a B tile are adjacent in launch order (L2 reuse)
    int m0 = blockIdx.x * 128, n0 = blockIdx.y * 64;
    int b = blockIdx.z;
    const __nv_bfloat16* Bph = Bh_;
    const __nv_bfloat16* Bpl = Bl_;
    if (MODE <= 1){ Bph += (size_t)b * NN * CC; Bpl += (size_t)b * NN * CC; }

    // ---- fast-path per-thread load pointers (full tiles) ----
    int r0 = tid >> 2, cu4 = tid & 3;
    const char* fAh = (const char*)Aph + ((size_t)(m0 + r0) * CC) * 2 + cu4 * 16;
    const char* fAl = (const char*)Apl + ((size_t)(m0 + r0) * CC) * 2 + cu4 * 16;
    const char* fBh = (const char*)Bph + ((size_t)(n0 + r0) * CC) * 2 + cu4 * 16;
    const char* fBl = (const char*)Bpl + ((size_t)(n0 + r0) * CC) * 2 + cu4 * 16;
    uint32_t d0 = (uint32_t)(r0 * LDS_B + cu4 * 16);
    bool fast = (m0 + 128 <= Mrows) && (n0 + 64 <= Nrows);

    #define LOADC_F(ch, st) do {                                                  \
        uint32_t s0w = sb + (st) * STG;                                           \
        int kb = (ch) * 64;                                                       \
        _Pragma("unroll")                                                         \
        for (int q = 0; q < 4; q++){                                              \
            CP_ASYNC16(s0w + d0 + q*(32*LDS_B),              fAh + kb + q*JSTRIDE, 16); \
            CP_ASYNC16(s0w + d0 + q*(32*LDS_B) + 128*LDS_B,  fAl + kb + q*JSTRIDE, 16); \
        }                                                                         \
        _Pragma("unroll")                                                         \
        for (int q = 0; q < 2; q++){                                              \
            CP_ASYNC16(s0w + d0 + q*(32*LDS_B) + 256*LDS_B,  fBh + kb + q*JSTRIDE, 16); \
            CP_ASYNC16(s0w + d0 + q*(32*LDS_B) + 320*LDS_B,  fBl + kb + q*JSTRIDE, 16); \
        }                                                                         \
        CP_ASYNC_COMMIT();                                                        \
    } while(0)

    #define LOADC_S(ch, st) do {                                                  \
        int k0 = (ch) * 32;                                                       \
        uint32_t s0w = sb + (st) * STG;                                           \
        _Pragma("unroll")                                                         \
        for (int i = tid; i < 1536; i += 128){                                    \
            int r = i >> 2, cu = i & 3;                                           \
            uint32_t dst = s0w + (uint32_t)(r * LDS_B + cu * 16);                 \
            const char* src; uint32_t sz;                                         \
            if (r < 256){                                                         \
                int rr = r & 127;                                                 \
                int gm = m0 + rr;                                                 \
                sz = (gm < Mrows) ? 16u : 0u;                                     \
                int gmc = (gm < Mrows) ? gm : 0;                                  \
                const __nv_bfloat16* base = (r < 128) ? Aph : Apl;                \
                src = (const char*)(base + (size_t)gmc*CC + k0) + cu*16;          \
            } else {                                                              \
                int rr = (r - 256) & 63;                                          \
                int gn = n0 + rr;                                                 \
                sz = (gn < Nrows) ? 16u : 0u;                                     \
                int gnc = (gn < Nrows) ? gn : 0;                                  \
                const __nv_bfloat16* base = (r < 320) ? Bph : Bpl;                \
                src = (const char*)(base + (size_t)gnc*CC + k0) + cu*16;          \
            }                                                                     \
            CP_ASYNC16(dst, src, sz);                                             \
        }                                                                         \
        CP_ASYNC_COMMIT();                                                        \
    } while(0)

    float acc[4][4][4] = {};
    if (fast){ LOADC_F(0, 0); LOADC_F(1, 1); }
    else     { LOADC_S(0, 0); LOADC_S(1, 1); }

    int wm = (wid >> 1) * 64, wn = (wid & 1) * 32;
    uint32_t a_off = (uint32_t)(wm + (lane & 15)) * LDS_B + ((lane >> 4) & 1) * 16;
    uint32_t b_off = (uint32_t)(wn + (lane & 7) + ((lane >> 4) & 1) * 8) * LDS_B
                   + ((lane >> 3) & 1) * 16;

    #pragma unroll 1
    for (int c = 0; c < 12; c++){
        CP_ASYNC_WAIT(1);
        __syncthreads();
        uint32_t s0 = sb + (c & 1) * STG;
        #pragma unroll
        for (int kk = 0; kk < 2; kk++){
            uint32_t ah[4][4], al[4][4];
            #pragma unroll
            for (int i = 0; i < 4; i++){
                uint32_t ra = s0 + a_off + (uint32_t)(i * 16 * LDS_B) + kk * 32;
                ldsm_x4(ah[i], ra);
                ldsm_x4(al[i], ra + 128 * LDS_B);
            }
            #pragma unroll
            for (int j = 0; j < 2; j++){
                uint32_t bh[4], bl[4];
                uint32_t rb = s0 + 256 * LDS_B + b_off + (uint32_t)(j * 16 * LDS_B) + kk * 32;
                ldsm_x4(bh, rb);
                ldsm_x4(bl, rb + 64 * LDS_B);
                // product-major ordering: 8 independent mmas between acc reuses
                #pragma unroll
                for (int i = 0; i < 4; i++) mma16816(acc[i][j*2+0], ah[i], bh[0], bh[1]);
                #pragma unroll
                for (int i = 0; i < 4; i++) mma16816(acc[i][j*2+1], ah[i], bh[2], bh[3]);
                #pragma unroll
                for (int i = 0; i < 4; i++) mma16816(acc[i][j*2+0], ah[i], bl[0], bl[1]);
                #pragma unroll
                for (int i = 0; i < 4; i++) mma16816(acc[i][j*2+1], ah[i], bl[2], bl[3]);
                #pragma unroll
                for (int i = 0; i < 4; i++) mma16816(acc[i][j*2+0], al[i], bh[0], bh[1]);
                #pragma unroll
                for (int i = 0; i < 4; i++) mma16816(acc[i][j*2+1], al[i], bh[2], bh[3]);
            }
        }
        __syncthreads();
        if (c + 2 < 12){
            if (fast) LOADC_F(c + 2, c & 1);
            else      LOADC_S(c + 2, c & 1);
        } else CP_ASYNC_COMMIT();
    }
    CP_ASYNC_WAIT(0);
    __syncthreads();

    // ---- stage accumulators in smem, then coalesced float4 stores ----
    float* eps = (float*)smem;
    int rbase = wm + (lane >> 2);
    int cbase = wn + (lane & 3) * 2;
    #pragma unroll
    for (int i = 0; i < 4; i++)
        #pragma unroll
        for (int half = 0; half < 2; half++){
            int ml = rbase + i * 16 + half * 8;
            #pragma unroll
            for (int j = 0; j < 4; j++){
                int nl = cbase + j * 8;
                eps[ml * EPITCH + nl    ] = acc[i][j][half*2+0];
                eps[ml * EPITCH + nl + 1] = acc[i][j][half*2+1];
            }
        }
    __syncthreads();
    for (int idx = tid; idx < 128 * 16; idx += 128){
        int ml = idx >> 4, nl = (idx & 15) * 4;
        float4 v = *(const float4*)&eps[ml * EPITCH + nl];
        int m = m0 + ml, n = n0 + nl;
        if (MODE <= 1){
            if (n >= Nrows) continue;
            float bs = bias[m];
            if (MODE == 1) bs += g_ptok[((size_t)b*NTOK + TOPK)*CC + m];
            v.x += bs; v.y += bs; v.z += bs; v.w += bs;
            if (MODE == 0){
                v.x = gelu_exact(v.x); v.y = gelu_exact(v.y);
                v.z = gelu_exact(v.z); v.w = gelu_exact(v.w);
            }
            *(float4*)&Out[((size_t)b*CC + m)*NN + n] = v;
        } else {
            if (m >= Mrows || n >= Nrows) continue;
            if (MODE == 2){
                v.x += bias[n]; v.y += bias[n+1]; v.z += bias[n+2]; v.w += bias[n+3];
            }
            *(float4*)&Out[(size_t)m * (MODE == 2 ? 3*CC : CC) + n] = v;
        }
    }
    #undef LOADC_F
    #undef LOADC_S
}

// ===================== scatter projected top tokens =====================
__global__ void k_scatter(float* __restrict__ out){
    int b = blockIdx.x / TOPK, j = blockIdx.x % TOPK;
    int o = threadIdx.x;
    int n = g_topidx[b*TOPK + j];
    float d = g_ptok[((size_t)b*NTOK + j   )*CC + o]
            - g_ptok[((size_t)b*NTOK + TOPK)*CC + o];
    out[((size_t)b*CC + o)*NN + n] += d;
}

// ===================== host launch =====================
extern "C" void kernel_launch(void* const* d_in, const int* in_sizes, int n_in,
                              void* d_out, int out_size){
    const float* x      = (const float*)d_in[0];
    const float* qkv_w  = (const float*)d_in[1];
    const float* qkv_b  = (const float*)d_in[2];
    const float* proj_w = (const float*)d_in[3];
    const float* proj_b = (const float*)d_in[4];
    const float* bn_g   = (const float*)d_in[5];
    const float* bn_b   = (const float*)d_in[6];
    const float* fc1_w  = (const float*)d_in[7];
    const float* fc1_b  = (const float*)d_in[8];
    const float* fc2_w  = (const float*)d_in[9];
    const float* fc2_b  = (const float*)d_in[10];
    const float* dw_w   = (const float*)d_in[11];
    const float* dw_b   = (const float*)d_in[12];
    float* out = (float*)d_out;

    float *p_qkv, *p_attnout, *p_ptok, *p_b1, *p_b2, *p_h1;
    __nv_bfloat16 *p_W1h, *p_W1l, *p_W2h, *p_W2l, *p_xth, *p_xtl;
    __nv_bfloat16 *p_tokh, *p_tokl, *p_aoh, *p_aol, *p_qwh, *p_qwl, *p_pwh, *p_pwl;
    cudaGetSymbolAddress((void**)&p_qkv    , g_qkv);
    cudaGetSymbolAddress((void**)&p_attnout, g_attnout);
    cudaGetSymbolAddress((void**)&p_ptok   , g_ptok);
    cudaGetSymbolAddress((void**)&p_b1     , g_b1);
    cudaGetSymbolAddress((void**)&p_b2     , g_b2);
    cudaGetSymbolAddress((void**)&p_h1     , g_h1);
    cudaGetSymbolAddress((void**)&p_W1h    , g_W1h);
    cudaGetSymbolAddress((void**)&p_W1l    , g_W1l);
    cudaGetSymbolAddress((void**)&p_W2h    , g_W2h);
    cudaGetSymbolAddress((void**)&p_W2l    , g_W2l);
    cudaGetSymbolAddress((void**)&p_xth    , g_xth);
    cudaGetSymbolAddress((void**)&p_xtl    , g_xtl);
    cudaGetSymbolAddress((void**)&p_tokh   , g_tokh);
    cudaGetSymbolAddress((void**)&p_tokl   , g_tokl);
    cudaGetSymbolAddress((void**)&p_aoh    , g_aoh);
    cudaGetSymbolAddress((void**)&p_aol    , g_aol);
    cudaGetSymbolAddress((void**)&p_qwh    , g_qwh);
    cudaGetSymbolAddress((void**)&p_qwl    , g_qwl);
    cudaGetSymbolAddress((void**)&p_pwh    , g_pwh);
    cudaGetSymbolAddress((void**)&p_pwl    , g_pwl);

    cudaFuncSetAttribute(k_mm<0>, cudaFuncAttributeMaxDynamicSharedMemorySize, MM_SMEM);
    cudaFuncSetAttribute(k_mm<1>, cudaFuncAttributeMaxDynamicSharedMemorySize, MM_SMEM);
    cudaFuncSetAttribute(k_mm<2>, cudaFuncAttributeMaxDynamicSharedMemorySize, MM_SMEM);
    cudaFuncSetAttribute(k_mm<3>, cudaFuncAttributeMaxDynamicSharedMemorySize, MM_SMEM);

    // ---- single fused pass over x, then the big GEMM as the 4th launch ----
    k_xpass   <<<dim3(NTIL, CTIL, BB), 256>>>(x, p_xth, p_xtl);             // 1
    k_redstats<<<(BB*CC + 255)/256, 256>>>();                               // 2
    k_prepW1  <<<CC, CC>>>(fc1_w, fc1_b, bn_g, bn_b);                       // 3
    dim3 gbig(CC/128, NN/64, BB);            // m fast, n slow: B-tile L2 reuse
    k_mm<0><<<gbig, 128, MM_SMEM>>>(p_W1h, p_W1l, p_xth, p_xtl, p_h1, p_b1, CC, NN); // 4

    // remaining prep + salience branch
    k_scores_red<<<(BB*NN + 255)/256, 256>>>();
    k_prepW2  <<<CC, CC>>>(proj_w, fc2_w, fc2_b, proj_b);
    k_split_rows<<<(3*CC*CC + 255)/256, 256>>>(qkv_w,  p_qwh, p_qwl, 3*CC*CC);
    k_split_rows<<<(CC*CC   + 255)/256, 256>>>(proj_w, p_pwh, p_pwl, CC*CC);
    k_topk      <<<BB, 1024>>>();
    k_gather_tok<<<dim3(TOPK, BB), 192>>>(p_xth, p_xtl);
    k_bgtok     <<<BB, CC>>>();
    k_mm<2><<<dim3((MTOK + 127)/128, (3*CC)/64, 1), 128, MM_SMEM>>>(
        p_tokh, p_tokl, p_qwh, p_qwl, p_qkv, qkv_b, MTOK, 3*CC);
    k_attention <<<BB*NHEAD, 128>>>();
    k_split_rows<<<(MTOK*CC + 255)/256, 256>>>(p_attnout, p_aoh, p_aol, MTOK*CC);
    k_mm<3><<<dim3((MTOK + 127)/128, CC/64, 1), 128, MM_SMEM>>>(
        p_aoh, p_aol, p_pwh, p_pwl, p_ptok, (const float*)nullptr, MTOK, CC);

    // conv-mixer tail
    k_dwconv_t<<<dim3(NN/32, CC/32, BB), dim3(32, 8)>>>(dw_w, dw_b, p_xth, p_xtl);
    k_mm<1><<<gbig, 128, MM_SMEM>>>(p_W2h, p_W2l, p_xth, p_xtl, out, p_b2, CC, NN);

    // rank-99 correction at top-token positions
    k_scatter<<<BB*TOPK, CC>>>(out);
}

// round 12
// speedup vs baseline: 1.0656x; 1.0656x over previous
#include <cuda_runtime.h>
#include <cuda_bf16.h>
#include <math.h>
#include <float.h>
#include <stdint.h>

#define BB    32
#define CC    384
#define HH    56
#define WW    56
#define NN    3136
#define TOPK  98
#define NTOK  99
#define NHEAD 8
#define HDIM  48
#define EPSB  1e-5f
#define MTOK  (BB*NTOK)   // 3168 tokens
#define NTIL  (NN/64)     // 49
#define CTIL  (CC/64)     // 6

// ===================== PTX helpers (sm_80-era, legal at compute_103) =====================
__device__ __forceinline__ uint32_t smem_to_u32(const void* smem_ptr) {
    uint32_t addr;
    asm("{ .reg .u64 tmp; cvta.to.shared.u64 tmp, %1; cvt.u32.u64 %0, tmp; }"
        : "=r"(addr) : "l"(smem_ptr));
    return addr;
}
#define CP_ASYNC16(dst, src, sz) \
    asm volatile("cp.async.cg.shared.global [%0], [%1], 16, %2;" \
        :: "r"((uint32_t)(dst)), "l"(src), "r"((uint32_t)(sz)) : "memory")
#define CP_ASYNC_COMMIT() asm volatile("cp.async.commit_group;" ::: "memory")
#define CP_ASYNC_WAIT(n)  asm volatile("cp.async.wait_group %0;" :: "n"(n) : "memory")

__device__ __forceinline__ void ldsm_x4(uint32_t (&r)[4], uint32_t addr){
    asm volatile("ldmatrix.sync.aligned.m8n8.x4.shared.b16 {%0,%1,%2,%3}, [%4];"
        : "=r"(r[0]),"=r"(r[1]),"=r"(r[2]),"=r"(r[3]) : "r"(addr));
}
__device__ __forceinline__ void mma16816(float (&d)[4], const uint32_t (&a)[4],
                                         uint32_t b0, uint32_t b1){
    asm volatile("mma.sync.aligned.m16n8k16.row.col.f32.bf16.bf16.f32 "
        "{%0,%1,%2,%3}, {%4,%5,%6,%7}, {%8,%9}, {%0,%1,%2,%3};"
        : "+f"(d[0]),"+f"(d[1]),"+f"(d[2]),"+f"(d[3])
        : "r"(a[0]),"r"(a[1]),"r"(a[2]),"r"(a[3]), "r"(b0),"r"(b1));
}

// ===================== device scratch =====================
__device__ float g_h1[(size_t)BB*CC*NN];            // gelu(fc1(bn(x)))  [b][c][n] fp32
__device__ __nv_bfloat16 g_xth[(size_t)BB*NN*CC];   // [b][n][c] bf16 hi (x, then dwconv out)
__device__ __nv_bfloat16 g_xtl[(size_t)BB*NN*CC];   // [b][n][c] bf16 lo
__device__ float g_scores[BB*NN];
__device__ float g_scores_p[(size_t)BB*CTIL*NN];    // partial scores per c-tile
__device__ float g_sumx_p [(size_t)BB*NTIL*CC];     // partial col sums per n-tile
__device__ float g_sumx2_p[(size_t)BB*NTIL*CC];
__device__ float g_sumx [BB*CC];
__device__ float g_sumx2[BB*CC];
__device__ int   g_topidx[BB*TOPK];
__device__ float g_qkv    [(size_t)MTOK*3*CC];
__device__ float g_attnout[MTOK*CC];
__device__ float g_ptok   [MTOK*CC];
__device__ __nv_bfloat16 g_W1h[CC*CC], g_W1l[CC*CC];
__device__ __nv_bfloat16 g_W2h[CC*CC], g_W2l[CC*CC];
__device__ __nv_bfloat16 g_tokh[MTOK*CC], g_tokl[MTOK*CC];
__device__ __nv_bfloat16 g_aoh [MTOK*CC], g_aol [MTOK*CC];
__device__ __nv_bfloat16 g_qwh [3*CC*CC], g_qwl [3*CC*CC];
__device__ __nv_bfloat16 g_pwh [CC*CC],   g_pwl [CC*CC];
__device__ float g_b1[CC];
__device__ float g_b2[CC];

__device__ __forceinline__ float gelu_exact(float v){
    return 0.5f * v * (1.0f + erff(v * 0.70710678118654752440f));
}
__device__ __forceinline__ void split_bf16(float v, __nv_bfloat16& h, __nv_bfloat16& l){
    h = __float2bfloat16(v);
    l = __float2bfloat16(v - __bfloat162float(h));
}
__device__ __forceinline__ void split_pack2(float v0, float v1, uint32_t& ph, uint32_t& pl){
    __nv_bfloat16 h0, l0, h1, l1;
    split_bf16(v0, h0, l0);
    split_bf16(v1, h1, l1);
    ph = (uint32_t)__bfloat16_as_ushort(h0) | ((uint32_t)__bfloat16_as_ushort(h1) << 16);
    pl = (uint32_t)__bfloat16_as_ushort(l0) | ((uint32_t)__bfloat16_as_ushort(l1) << 16);
}

// ======= fused pass over x: transpose+split AND partial stats (deterministic) =======
__global__ void k_xpass(const float* __restrict__ src,
                        __nv_bfloat16* __restrict__ dh, __nv_bfloat16* __restrict__ dl){
    __shared__ float sm[64][65];
    int b = blockIdx.z;
    int nx = blockIdx.x, cy = blockIdx.y;
    int n0 = nx * 64, c0 = cy * 64;
    const float* sp = src + (size_t)b * CC * NN;
    int t = threadIdx.x;
    #pragma unroll
    for (int p = 0; p < 4; p++){
        int row = (t >> 4) + p * 16;         // c offset
        int col = (t & 15) * 4;              // n offset
        float4 v = *(const float4*)&sp[(size_t)(c0 + row) * NN + n0 + col];
        sm[row][col+0] = v.x; sm[row][col+1] = v.y;
        sm[row][col+2] = v.z; sm[row][col+3] = v.w;
        float rs  = v.x + v.y + v.z + v.w;
        float rs2 = v.x*v.x + v.y*v.y + v.z*v.z + v.w*v.w;
        #pragma unroll
        for (int o = 8; o; o >>= 1){
            rs  += __shfl_down_sync(~0u, rs , o, 16);
            rs2 += __shfl_down_sync(~0u, rs2, o, 16);
        }
        if ((t & 15) == 0){
            size_t idx = ((size_t)b * NTIL + nx) * CC + c0 + row;
            g_sumx_p [idx] = rs;
            g_sumx2_p[idx] = rs2;
        }
    }
    __syncthreads();
    uint32_t* dh32 = (uint32_t*)(dh + (size_t)b * NN * CC);
    uint32_t* dl32 = (uint32_t*)(dl + (size_t)b * NN * CC);
    #pragma unroll
    for (int p = 0; p < 8; p++){
        int nr = (t >> 5) + p * 8;           // n offset
        int cu = t & 31;                     // packed c pair
        float v0 = sm[2*cu][nr], v1 = sm[2*cu+1][nr];
        uint32_t ph, pl;
        split_pack2(v0, v1, ph, pl);
        size_t o = ((size_t)(n0 + nr) * CC + c0) / 2 + cu;
        dh32[o] = ph; dl32[o] = pl;
        float sc = v0*v0 + v1*v1;
        #pragma unroll
        for (int of = 16; of; of >>= 1) sc += __shfl_down_sync(~0u, sc, of);
        if (cu == 0) g_scores_p[((size_t)b * CTIL + cy) * NN + n0 + nr] = sc;
    }
}

__global__ void k_redstats(){
    int i = blockIdx.x * 256 + threadIdx.x;
    if (i >= BB*CC) return;
    int b = i / CC, c = i % CC;
    float s = 0.f, s2 = 0.f;
    #pragma unroll 7
    for (int k = 0; k < NTIL; k++){
        size_t idx = ((size_t)b * NTIL + k) * CC + c;
        s += g_sumx_p[idx]; s2 += g_sumx2_p[idx];
    }
    g_sumx[i] = s; g_sumx2[i] = s2;
}
__global__ void k_scores_red(){
    int i = blockIdx.x * 256 + threadIdx.x;
    if (i >= BB*NN) return;
    int b = i / NN, n = i % NN;
    float s = 0.f;
    #pragma unroll
    for (int k = 0; k < CTIL; k++)
        s += g_scores_p[((size_t)b * CTIL + k) * NN + n];
    g_scores[i] = s;
}

// ===================== prep kernels =====================
__global__ void k_prepW1(const float* __restrict__ fc1_w, const float* __restrict__ fc1_b,
                         const float* __restrict__ bn_g, const float* __restrict__ bn_b){
    int o = blockIdx.x, c = threadIdx.x;
    float s = 0.f, s2 = 0.f;
    #pragma unroll 8
    for (int bb2 = 0; bb2 < BB; bb2++){ s += g_sumx[bb2*CC + c]; s2 += g_sumx2[bb2*CC + c]; }
    float inv = 1.f / ((float)BB * (float)NN);
    float mu  = s * inv;
    float var = s2 * inv - mu * mu;
    float a   = bn_g[c] * rsqrtf(var + EPSB);
    float bnC = bn_b[c] - mu * a;
    float w = fc1_w[o*CC + c];
    float w1 = w * a;
    __nv_bfloat16 h, l; split_bf16(w1, h, l);
    g_W1h[o*CC + c] = h; g_W1l[o*CC + c] = l;
    __shared__ float red[CC];
    red[c] = w * bnC;
    __syncthreads();
    for (int sft = 256; sft > 0; sft >>= 1){
        if (c < sft && c + sft < CC) red[c] += red[c + sft];
        __syncthreads();
    }
    if (c == 0) g_b1[o] = fc1_b[o] + red[0];
}

__global__ void k_prepW2(const float* __restrict__ proj_w, const float* __restrict__ fc2_w,
                         const float* __restrict__ fc2_b, const float* __restrict__ proj_b){
    int o = blockIdx.x, c = threadIdx.x;
    const float* pr = proj_w + o*CC;
    float acc = 0.f;
    for (int k = 0; k < CC; k++)
        acc = fmaf(pr[k], fc2_w[k*CC + c], acc);
    __nv_bfloat16 h, l; split_bf16(acc, h, l);
    g_W2h[o*CC + c] = h; g_W2l[o*CC + c] = l;
    __shared__ float red[CC];
    red[c] = pr[c] * fc2_b[c];
    __syncthreads();
    for (int s = 256; s > 0; s >>= 1){
        if (c < s && c + s < CC) red[c] += red[c + s];
        __syncthreads();
    }
    if (c == 0) g_b2[o] = proj_b[o] + red[0];
}

__global__ void k_split_rows(const float* __restrict__ src, __nv_bfloat16* __restrict__ dh,
                             __nv_bfloat16* __restrict__ dl, int n){
    int i = blockIdx.x * 256 + threadIdx.x;
    if (i < n){
        __nv_bfloat16 h, l; split_bf16(src[i], h, l);
        dh[i] = h; dl[i] = l;
    }
}

// ===================== radix-select topk (scores >= 0 -> bits monotonic) =====================
__global__ void k_topk(){
    int b = blockIdx.x, tid = threadIdx.x;
    const float* sc = g_scores + b*NN;
    __shared__ uint32_t hist[256];
    __shared__ uint32_t s_prefix, s_k;
    __shared__ int s_cnt, s_neq;
    __shared__ int eqidx[128];
    if (tid == 0){ s_prefix = 0u; s_k = TOPK; }
    __syncthreads();
    #pragma unroll 1
    for (int pass = 0; pass < 4; pass++){
        int shift = 24 - pass*8;
        uint32_t pmask = (pass == 0) ? 0u : (0xFFFFFFFFu << (shift + 8));
        for (int i = tid; i < 256; i += 256) hist[i] = 0;
        __syncthreads();
        uint32_t pref = s_prefix;
        for (int n = tid; n < NN; n += 256){
            uint32_t v = __float_as_uint(sc[n]);
            if ((v & pmask) == pref) atomicAdd(&hist[(v >> shift) & 255], 1);
        }
        __syncthreads();
        if (tid == 0){
            uint32_t k = s_k, cum = 0; int Bn = 0;
            for (int bn = 255; bn >= 0; bn--){
                if (cum + hist[bn] >= k){ Bn = bn; break; }
                cum += hist[bn];
            }
            s_k = k - cum;
            s_prefix = pref | ((uint32_t)Bn << shift);
        }
        __syncthreads();
    }
    if (tid == 0){ s_cnt = 0; s_neq = 0; }
    __syncthreads();
    float thrf = __uint_as_float(s_prefix);
    for (int n = tid; n < NN; n += 256){
        float v = sc[n];
        if (v > thrf){
            int p = atomicAdd(&s_cnt, 1);
            g_topidx[b*TOPK + p] = n;
        } else if (v == thrf){
            int p = atomicAdd(&s_neq, 1);
            if (p < 128) eqidx[p] = n;
        }
    }
    __syncthreads();
    if (tid == 0){
        int have = s_cnt;
        int need = TOPK - have;                 // == s_k (count of thr-equal to take)
        int ne = s_neq < 128 ? s_neq : 128;
        for (int t = 0; t < need; t++){
            int best = 1 << 30, bi = 0;
            for (int i = 0; i < ne; i++)
                if (eqidx[i] < best){ best = eqidx[i]; bi = i; }
            g_topidx[b*TOPK + have + t] = best;
            eqidx[bi] = 1 << 30;
        }
    }
}

// coalesced token gather from the transposed split planes
__global__ void k_gather_tok(const __nv_bfloat16* __restrict__ xth,
                             const __nv_bfloat16* __restrict__ xtl){
    int j = blockIdx.x, b = blockIdx.y;
    int t = threadIdx.x;                     // 192 threads, 1 uint32 each
    int idx = g_topidx[b*TOPK + j];
    const uint32_t* sh = (const uint32_t*)(xth + ((size_t)b*NN + idx)*CC);
    const uint32_t* sl = (const uint32_t*)(xtl + ((size_t)b*NN + idx)*CC);
    uint32_t* dh = (uint32_t*)(g_tokh + ((size_t)b*NTOK + j)*CC);
    uint32_t* dl = (uint32_t*)(g_tokl + ((size_t)b*NTOK + j)*CC);
    dh[t] = sh[t];
    dl[t] = sl[t];
}

// bg token: (sumx - sum of top tokens)/(N-K), from hi+lo reconstruction
__global__ void k_bgtok(){
    int b = blockIdx.x, c = threadIdx.x;
    const __nv_bfloat16* th = g_tokh + (size_t)b*NTOK*CC + c;
    const __nv_bfloat16* tl = g_tokl + (size_t)b*NTOK*CC + c;
    float s = 0.f;
    #pragma unroll 7
    for (int j = 0; j < TOPK; j++)
        s += __bfloat162float(th[(size_t)j*CC]) + __bfloat162float(tl[(size_t)j*CC]);
    float bg = (g_sumx[b*CC + c] - s) * (1.f / (float)(NN - TOPK));
    __nv_bfloat16 h, l; split_bf16(bg, h, l);
    g_tokh[((size_t)b*NTOK + TOPK)*CC + c] = h;
    g_tokl[((size_t)b*NTOK + TOPK)*CC + c] = l;
}

// ===================== attention over 99 tokens =====================
__global__ void k_attention(){
    int b = blockIdx.x / NHEAD, h = blockIdx.x % NHEAD;
    __shared__ float Ks[NTOK][HDIM];
    __shared__ float Vs[NTOK][HDIM];
    __shared__ float Qs[4][HDIM];
    __shared__ float Ps[4][NTOK];
    int tid = threadIdx.x;
    const float* qkvb = g_qkv + (size_t)b * NTOK * 3 * CC;
    for (int i = tid; i < NTOK*HDIM; i += blockDim.x){
        int t = i / HDIM, d = i % HDIM;
        Ks[t][d] = qkvb[(size_t)t*3*CC +   CC + h*HDIM + d];
        Vs[t][d] = qkvb[(size_t)t*3*CC + 2*CC + h*HDIM + d];
    }
    __syncthreads();
    int w = tid >> 5, lane = tid & 31;
    const float scale = rsqrtf((float)HDIM);
    for (int t = w; t < NTOK; t += 4){
        const float* qp = qkvb + (size_t)t*3*CC + h*HDIM;
        Qs[w][lane] = qp[lane];
        if (lane < HDIM - 32) Qs[w][lane + 32] = qp[lane + 32];
        __syncwarp();
        float sc[4]; float mx = -FLT_MAX;
        #pragma unroll
        for (int r = 0; r < 4; r++){
            int m = lane + r*32;
            float s = -FLT_MAX;
            if (m < NTOK){
                s = 0.f;
                #pragma unroll
                for (int d = 0; d < HDIM; d++) s = fmaf(Qs[w][d], Ks[m][d], s);
                s *= scale;
            }
            sc[r] = s; mx = fmaxf(mx, s);
        }
        for (int o = 16; o; o >>= 1) mx = fmaxf(mx, __shfl_xor_sync(~0u, mx, o));
        float sum = 0.f;
        #pragma unroll
        for (int r = 0; r < 4; r++){
            int m = lane + r*32;
            float e = (m < NTOK) ? expf(sc[r] - mx) : 0.f;
            sc[r] = e; sum += e;
        }
        for (int o = 16; o; o >>= 1) sum += __shfl_xor_sync(~0u, sum, o);
        float inv = 1.f / sum;
        #pragma unroll
        for (int r = 0; r < 4; r++){
            int m = lane + r*32;
            if (m < NTOK) Ps[w][m] = sc[r] * inv;
        }
        __syncwarp();
        for (int d = lane; d < HDIM; d += 32){
            float o = 0.f;
            for (int m = 0; m < NTOK; m++) o = fmaf(Ps[w][m], Vs[m][d], o);
            g_attnout[((size_t)b*NTOK + t)*CC + h*HDIM + d] = o;
        }
        __syncwarp();
    }
}

// ===================== depthwise 3x3 + transpose + split fused (packed stores) ==========
__global__ void k_dwconv_t(const float* __restrict__ dw_w, const float* __restrict__ dw_b,
                           __nv_bfloat16* __restrict__ dh, __nv_bfloat16* __restrict__ dl){
    __shared__ float t[32][33];
    int b = blockIdx.z, c0 = blockIdx.y * 32, n0 = blockIdx.x * 32;
    int tid = threadIdx.y * 32 + threadIdx.x;
    for (int r = threadIdx.y; r < 32; r += 8){
        int c = c0 + r;
        int n = n0 + threadIdx.x;
        const float* src = g_h1 + ((size_t)b * CC + c) * NN;
        int y = n / WW, xp = n % WW;
        const float* w = dw_w + c * 9;
        float acc = dw_b[c];
        #pragma unroll
        for (int dy = -1; dy <= 1; dy++){
            int yy = y + dy;
            if (yy < 0 || yy >= HH) continue;
            #pragma unroll
            for (int dx = -1; dx <= 1; dx++){
                int xw = xp + dx;
                if (xw < 0 || xw >= WW) continue;
                acc = fmaf(src[yy*WW + xw], w[(dy+1)*3 + (dx+1)], acc);
            }
        }
        t[r][threadIdx.x] = acc;
    }
    __syncthreads();
    uint32_t* dh32 = (uint32_t*)(dh + (size_t)b * NN * CC);
    uint32_t* dl32 = (uint32_t*)(dl + (size_t)b * NN * CC);
    for (int idx = tid; idx < 32 * 16; idx += 256){
        int nr = idx >> 4, cu = idx & 15;
        uint32_t ph, pl;
        split_pack2(t[2*cu][nr], t[2*cu+1][nr], ph, pl);
        size_t o = ((size_t)(n0 + nr) * CC + c0) / 2 + cu;
        dh32[o] = ph; dl32[o] = pl;
    }
}

// ====== warp-mma bf16-split GEMM (128x128 tile, 128 threads, 4 warps 2x2, 64x64/warp) ====
#define LDS_B 80
#define STG   (512*LDS_B)            // 40960 B per stage
#define MM_SMEM (2*STG)              // 81920 B -> 2 CTAs/SM
#define EPITCH 132
#define JSTRIDE (32*CC*2)            // 24576 bytes: 32-row stride in bf16 planes

template<int MODE>
__global__ void __launch_bounds__(128)
k_mm(const __nv_bfloat16* __restrict__ Aph, const __nv_bfloat16* __restrict__ Apl,
     const __nv_bfloat16* __restrict__ Bh_, const __nv_bfloat16* __restrict__ Bl_,
     float* __restrict__ Out, const float* __restrict__ bias,
     int Mrows, int Nrows){
    extern __shared__ char smem[];
    uint32_t sb = smem_to_u32(smem);
    int tid = threadIdx.x, wid = tid >> 5, lane = tid & 31;
    // m fastest: the m-CTAs sharing a B tile are adjacent in launch order (L2 reuse)
    int m0 = blockIdx.x * 128, n0 = blockIdx.y * 128;
    int b = blockIdx.z;
    const __nv_bfloat16* Bph = Bh_;
    const __nv_bfloat16* Bpl = Bl_;
    if (MODE <= 1){ Bph += (size_t)b * NN * CC; Bpl += (size_t)b * NN * CC; }

    // ---- fast-path per-thread load pointers (full tiles) ----
    int r0 = tid >> 2, cu4 = tid & 3;
    const char* fAh = (const char*)Aph + ((size_t)(m0 + r0) * CC) * 2 + cu4 * 16;
    const char* fAl = (const char*)Apl + ((size_t)(m0 + r0) * CC) * 2 + cu4 * 16;
    const char* fBh = (const char*)Bph + ((size_t)(n0 + r0) * CC) * 2 + cu4 * 16;
    const char* fBl = (const char*)Bpl + ((size_t)(n0 + r0) * CC) * 2 + cu4 * 16;
    uint32_t d0 = (uint32_t)(r0 * LDS_B + cu4 * 16);
    bool fast = (m0 + 128 <= Mrows) && (n0 + 128 <= Nrows);

    #define LOADC_F(ch, st) do {                                                  \
        uint32_t s0w = sb + (st) * STG;                                           \
        int kb = (ch) * 64;                                                       \
        _Pragma("unroll")                                                         \
        for (int j = 0; j < 4; j++){                                              \
            CP_ASYNC16(s0w + d0 + j*(32*LDS_B),               fAh + kb + j*JSTRIDE, 16); \
            CP_ASYNC16(s0w + d0 + j*(32*LDS_B) + 128*LDS_B,   fAl + kb + j*JSTRIDE, 16); \
            CP_ASYNC16(s0w + d0 + j*(32*LDS_B) + 256*LDS_B,   fBh + kb + j*JSTRIDE, 16); \
            CP_ASYNC16(s0w + d0 + j*(32*LDS_B) + 384*LDS_B,   fBl + kb + j*JSTRIDE, 16); \
        }                                                                         \
        CP_ASYNC_COMMIT();                                                        \
    } while(0)

    #define LOADC_S(ch, st) do {                                                  \
        int k0 = (ch) * 32;                                                       \
        uint32_t s0w = sb + (st) * STG;                                           \
        _Pragma("unroll")                                                         \
        for (int i = tid; i < 2048; i += 128){                                    \
            int r = i >> 2, cu = i & 3;                                           \
            uint32_t dst = s0w + (uint32_t)(r * LDS_B + cu * 16);                 \
            const char* src; uint32_t sz;                                         \
            if (r < 256){                                                         \
                int rr = r & 127;                                                 \
                int gm = m0 + rr;                                                 \
                sz = (gm < Mrows) ? 16u : 0u;                                     \
                int gmc = (gm < Mrows) ? gm : 0;                                  \
                const __nv_bfloat16* base = (r < 128) ? Aph : Apl;                \
                src = (const char*)(base + (size_t)gmc*CC + k0) + cu*16;          \
            } else {                                                              \
                int rr = r & 127;                                                 \
                int gn = n0 + rr;                                                 \
                sz = (gn < Nrows) ? 16u : 0u;                                     \
                int gnc = (gn < Nrows) ? gn : 0;                                  \
                const __nv_bfloat16* base = (r < 384) ? Bph : Bpl;                \
                src = (const char*)(base + (size_t)gnc*CC + k0) + cu*16;          \
            }                                                                     \
            CP_ASYNC16(dst, src, sz);                                             \
        }                                                                         \
        CP_ASYNC_COMMIT();                                                        \
    } while(0)

    float acc[4][8][4] = {};
    if (fast){ LOADC_F(0, 0); LOADC_F(1, 1); }
    else     { LOADC_S(0, 0); LOADC_S(1, 1); }

    int wm = (wid >> 1) * 64, wn = (wid & 1) * 64;
    uint32_t a_off = (uint32_t)(wm + (lane & 15)) * LDS_B + ((lane >> 4) & 1) * 16;
    uint32_t b_off = (uint32_t)(wn + (lane & 7) + ((lane >> 4) & 1) * 8) * LDS_B
                   + ((lane >> 3) & 1) * 16;

    #pragma unroll 1
    for (int c = 0; c < 12; c++){
        CP_ASYNC_WAIT(1);
        __syncthreads();
        uint32_t s0 = sb + (c & 1) * STG;
        #pragma unroll
        for (int kk = 0; kk < 2; kk++){
            uint32_t ah[4][4], al[4][4];
            #pragma unroll
            for (int i = 0; i < 4; i++){
                uint32_t ra = s0 + a_off + (uint32_t)(i * 16 * LDS_B) + kk * 32;
                ldsm_x4(ah[i], ra);
                ldsm_x4(al[i], ra + 128 * LDS_B);
            }
            #pragma unroll
            for (int j = 0; j < 4; j++){
                uint32_t bh[4], bl[4];
                uint32_t rb = s0 + 256 * LDS_B + b_off + (uint32_t)(j * 16 * LDS_B) + kk * 32;
                ldsm_x4(bh, rb);
                ldsm_x4(bl, rb + 128 * LDS_B);
                // product-major ordering: 8 independent mmas between acc reuses
                #pragma unroll
                for (int i = 0; i < 4; i++) mma16816(acc[i][j*2+0], ah[i], bh[0], bh[1]);
                #pragma unroll
                for (int i = 0; i < 4; i++) mma16816(acc[i][j*2+1], ah[i], bh[2], bh[3]);
                #pragma unroll
                for (int i = 0; i < 4; i++) mma16816(acc[i][j*2+0], ah[i], bl[0], bl[1]);
                #pragma unroll
                for (int i = 0; i < 4; i++) mma16816(acc[i][j*2+1], ah[i], bl[2], bl[3]);
                #pragma unroll
                for (int i = 0; i < 4; i++) mma16816(acc[i][j*2+0], al[i], bh[0], bh[1]);
                #pragma unroll
                for (int i = 0; i < 4; i++) mma16816(acc[i][j*2+1], al[i], bh[2], bh[3]);
            }
        }
        __syncthreads();
        if (c + 2 < 12){
            if (fast) LOADC_F(c + 2, c & 1);
            else      LOADC_S(c + 2, c & 1);
        } else CP_ASYNC_COMMIT();
    }
    CP_ASYNC_WAIT(0);
    __syncthreads();

    // ---- stage accumulators in smem, then coalesced float4 stores ----
    float* eps = (float*)smem;
    int rbase = wm + (lane >> 2);
    int cbase = wn + (lane & 3) * 2;
    #pragma unroll
    for (int i = 0; i < 4; i++)
        #pragma unroll
        for (int half = 0; half < 2; half++){
            int ml = rbase + i * 16 + half * 8;
            #pragma unroll
            for (int j = 0; j < 8; j++){
                int nl = cbase + j * 8;
                eps[ml * EPITCH + nl    ] = acc[i][j][half*2+0];
                eps[ml * EPITCH + nl + 1] = acc[i][j][half*2+1];
            }
        }
    __syncthreads();
    for (int idx = tid; idx < 128 * 32; idx += 128){
        int ml = idx >> 5, nl = (idx & 31) * 4;
        float4 v = *(const float4*)&eps[ml * EPITCH + nl];
        int m = m0 + ml, n = n0 + nl;
        if (MODE <= 1){
            if (n >= Nrows) continue;
            float bs = bias[m];
            if (MODE == 1) bs += g_ptok[((size_t)b*NTOK + TOPK)*CC + m];
            v.x += bs; v.y += bs; v.z += bs; v.w += bs;
            if (MODE == 0){
                v.x = gelu_exact(v.x); v.y = gelu_exact(v.y);
                v.z = gelu_exact(v.z); v.w = gelu_exact(v.w);
            }
            *(float4*)&Out[((size_t)b*CC + m)*NN + n] = v;
        } else {
            if (m >= Mrows || n >= Nrows) continue;
            if (MODE == 2){
                v.x += bias[n]; v.y += bias[n+1]; v.z += bias[n+2]; v.w += bias[n+3];
            }
            *(float4*)&Out[(size_t)m * (MODE == 2 ? 3*CC : CC) + n] = v;
        }
    }
    #undef LOADC_F
    #undef LOADC_S
}

// ===================== scatter projected top tokens =====================
__global__ void k_scatter(float* __restrict__ out){
    int b = blockIdx.x / TOPK, j = blockIdx.x % TOPK;
    int o = threadIdx.x;
    int n = g_topidx[b*TOPK + j];
    float d = g_ptok[((size_t)b*NTOK + j   )*CC + o]
            - g_ptok[((size_t)b*NTOK + TOPK)*CC + o];
    out[((size_t)b*CC + o)*NN + n] += d;
}

// ===================== host launch =====================
extern "C" void kernel_launch(void* const* d_in, const int* in_sizes, int n_in,
                              void* d_out, int out_size){
    const float* x      = (const float*)d_in[0];
    const float* qkv_w  = (const float*)d_in[1];
    const float* qkv_b  = (const float*)d_in[2];
    const float* proj_w = (const float*)d_in[3];
    const float* proj_b = (const float*)d_in[4];
    const float* bn_g   = (const float*)d_in[5];
    const float* bn_b   = (const float*)d_in[6];
    const float* fc1_w  = (const float*)d_in[7];
    const float* fc1_b  = (const float*)d_in[8];
    const float* fc2_w  = (const float*)d_in[9];
    const float* fc2_b  = (const float*)d_in[10];
    const float* dw_w   = (const float*)d_in[11];
    const float* dw_b   = (const float*)d_in[12];
    float* out = (float*)d_out;

    float *p_qkv, *p_attnout, *p_ptok, *p_b1, *p_b2, *p_h1;
    __nv_bfloat16 *p_W1h, *p_W1l, *p_W2h, *p_W2l, *p_xth, *p_xtl;
    __nv_bfloat16 *p_tokh, *p_tokl, *p_aoh, *p_aol, *p_qwh, *p_qwl, *p_pwh, *p_pwl;
    cudaGetSymbolAddress((void**)&p_qkv    , g_qkv);
    cudaGetSymbolAddress((void**)&p_attnout, g_attnout);
    cudaGetSymbolAddress((void**)&p_ptok   , g_ptok);
    cudaGetSymbolAddress((void**)&p_b1     , g_b1);
    cudaGetSymbolAddress((void**)&p_b2     , g_b2);
    cudaGetSymbolAddress((void**)&p_h1     , g_h1);
    cudaGetSymbolAddress((void**)&p_W1h    , g_W1h);
    cudaGetSymbolAddress((void**)&p_W1l    , g_W1l);
    cudaGetSymbolAddress((void**)&p_W2h    , g_W2h);
    cudaGetSymbolAddress((void**)&p_W2l    , g_W2l);
    cudaGetSymbolAddress((void**)&p_xth    , g_xth);
    cudaGetSymbolAddress((void**)&p_xtl    , g_xtl);
    cudaGetSymbolAddress((void**)&p_tokh   , g_tokh);
    cudaGetSymbolAddress((void**)&p_tokl   , g_tokl);
    cudaGetSymbolAddress((void**)&p_aoh    , g_aoh);
    cudaGetSymbolAddress((void**)&p_aol    , g_aol);
    cudaGetSymbolAddress((void**)&p_qwh    , g_qwh);
    cudaGetSymbolAddress((void**)&p_qwl    , g_qwl);
    cudaGetSymbolAddress((void**)&p_pwh    , g_pwh);
    cudaGetSymbolAddress((void**)&p_pwl    , g_pwl);

    cudaFuncSetAttribute(k_mm<0>, cudaFuncAttributeMaxDynamicSharedMemorySize, MM_SMEM);
    cudaFuncSetAttribute(k_mm<1>, cudaFuncAttributeMaxDynamicSharedMemorySize, MM_SMEM);
    cudaFuncSetAttribute(k_mm<2>, cudaFuncAttributeMaxDynamicSharedMemorySize, MM_SMEM);
    cudaFuncSetAttribute(k_mm<3>, cudaFuncAttributeMaxDynamicSharedMemorySize, MM_SMEM);

    // ---- single fused pass over x, then the big GEMM as the 4th launch ----
    k_xpass   <<<dim3(NTIL, CTIL, BB), 256>>>(x, p_xth, p_xtl);             // 1
    k_redstats<<<(BB*CC + 255)/256, 256>>>();                               // 2
    k_prepW1  <<<CC, CC>>>(fc1_w, fc1_b, bn_g, bn_b);                       // 3
    dim3 gbig(CC/128, (NN + 127)/128, BB);   // m fast, n slow: B-tile L2 reuse
    k_mm<0><<<gbig, 128, MM_SMEM>>>(p_W1h, p_W1l, p_xth, p_xtl, p_h1, p_b1, CC, NN); // 4

    // remaining prep + salience branch
    k_scores_red<<<(BB*NN + 255)/256, 256>>>();
    k_prepW2  <<<CC, CC>>>(proj_w, fc2_w, fc2_b, proj_b);
    k_split_rows<<<(3*CC*CC + 255)/256, 256>>>(qkv_w,  p_qwh, p_qwl, 3*CC*CC);
    k_split_rows<<<(CC*CC   + 255)/256, 256>>>(proj_w, p_pwh, p_pwl, CC*CC);
    k_topk      <<<BB, 256>>>();
    k_gather_tok<<<dim3(TOPK, BB), 192>>>(p_xth, p_xtl);
    k_bgtok     <<<BB, CC>>>();
    k_mm<2><<<dim3((MTOK + 127)/128, (3*CC + 127)/128, 1), 128, MM_SMEM>>>(
        p_tokh, p_tokl, p_qwh, p_qwl, p_qkv, qkv_b, MTOK, 3*CC);
    k_attention <<<BB*NHEAD, 128>>>();
    k_split_rows<<<(MTOK*CC + 255)/256, 256>>>(p_attnout, p_aoh, p_aol, MTOK*CC);
    k_mm<3><<<dim3((MTOK + 127)/128, CC/128, 1), 128, MM_SMEM>>>(
        p_aoh, p_aol, p_pwh, p_pwl, p_ptok, (const float*)nullptr, MTOK, CC);

    // conv-mixer tail
    k_dwconv_t<<<dim3(NN/32, CC/32, BB), dim3(32, 8)>>>(dw_w, dw_b, p_xth, p_xtl);
    k_mm<1><<<gbig, 128, MM_SMEM>>>(p_W2h, p_W2l, p_xth, p_xtl, out, p_b2, CC, NN);

    // rank-99 correction at top-token positions
    k_scatter<<<BB*TOPK, CC>>>(out);
}

// round 14
// speedup vs baseline: 1.2308x; 1.1550x over previous
#include <cuda_runtime.h>
#include <cuda_fp16.h>
#include <math.h>
#include <float.h>
#include <stdint.h>

#define BB    32
#define CC    384
#define HH    56
#define WW    56
#define NN    3136
#define TOPK  98
#define NTOK  99
#define NHEAD 8
#define HDIM  48
#define EPSB  1e-5f
#define MTOK  (BB*NTOK)   // 3168 tokens
#define NTIL  (NN/64)     // 49
#define CTIL  (CC/64)     // 6
#define WSCALE   64.0f
#define INVWSC   0.015625f

// ===================== PTX helpers (sm_80-era, legal at compute_103) =====================
__device__ __forceinline__ uint32_t smem_to_u32(const void* smem_ptr) {
    uint32_t addr;
    asm("{ .reg .u64 tmp; cvta.to.shared.u64 tmp, %1; cvt.u32.u64 %0, tmp; }"
        : "=r"(addr) : "l"(smem_ptr));
    return addr;
}
#define CP_ASYNC16(dst, src, sz) \
    asm volatile("cp.async.cg.shared.global [%0], [%1], 16, %2;" \
        :: "r"((uint32_t)(dst)), "l"(src), "r"((uint32_t)(sz)) : "memory")
#define CP_ASYNC_COMMIT() asm volatile("cp.async.commit_group;" ::: "memory")
#define CP_ASYNC_WAIT(n)  asm volatile("cp.async.wait_group %0;" :: "n"(n) : "memory")

__device__ __forceinline__ void ldsm_x4(uint32_t (&r)[4], uint32_t addr){
    asm volatile("ldmatrix.sync.aligned.m8n8.x4.shared.b16 {%0,%1,%2,%3}, [%4];"
        : "=r"(r[0]),"=r"(r[1]),"=r"(r[2]),"=r"(r[3]) : "r"(addr));
}
__device__ __forceinline__ void mma16816h(float (&d)[4], const uint32_t (&a)[4],
                                          uint32_t b0, uint32_t b1){
    asm volatile("mma.sync.aligned.m16n8k16.row.col.f32.f16.f16.f32 "
        "{%0,%1,%2,%3}, {%4,%5,%6,%7}, {%8,%9}, {%0,%1,%2,%3};"
        : "+f"(d[0]),"+f"(d[1]),"+f"(d[2]),"+f"(d[3])
        : "r"(a[0]),"r"(a[1]),"r"(a[2]),"r"(a[3]), "r"(b0),"r"(b1));
}

// ===================== device scratch =====================
__device__ float g_h1[(size_t)BB*CC*NN];        // gelu(fc1(bn(x)))  [b][c][n] fp32
__device__ __half g_xth[(size_t)BB*NN*CC];      // [b][n][c] fp16 hi (x, then dwconv out)
__device__ __half g_xtl[(size_t)BB*NN*CC];      // [b][n][c] fp16 lo (x only)
__device__ float g_scores[BB*NN];
__device__ float g_scores_p[(size_t)BB*CTIL*NN];
__device__ float g_sumx_p [(size_t)BB*NTIL*CC];
__device__ float g_sumx2_p[(size_t)BB*NTIL*CC];
__device__ float g_sumx [BB*CC];
__device__ float g_sumx2[BB*CC];
__device__ int   g_topidx[BB*TOPK];
__device__ float g_qkv    [(size_t)MTOK*3*CC];
__device__ float g_attnout[MTOK*CC];
__device__ float g_ptok   [MTOK*CC];
__device__ __half g_W1h[CC*CC], g_W1l[CC*CC];   // fc1 (BN-folded), x64, fp16 hi/lo
__device__ __half g_W2h[CC*CC], g_W2l[CC*CC];   // proj@fc2, x64, fp16 hi/lo
__device__ __half g_tokh[MTOK*CC], g_tokl[MTOK*CC];
__device__ __half g_aoh [MTOK*CC], g_aol [MTOK*CC];
__device__ __half g_qw16[3*CC*CC];              // qkv_w x64 fp16
__device__ __half g_pw16[CC*CC];                // proj_w x64 fp16
__device__ float g_b1[CC];
__device__ float g_b2[CC];

__device__ __forceinline__ float gelu_exact(float v){
    return 0.5f * v * (1.0f + erff(v * 0.70710678118654752440f));
}
__device__ __forceinline__ void split_fp16(float v, __half& h, __half& l){
    h = __float2half_rn(v);
    l = __float2half_rn(v - __half2float(h));
}
__device__ __forceinline__ void split_pack2h(float v0, float v1, uint32_t& ph, uint32_t& pl){
    __half h0, l0, h1, l1;
    split_fp16(v0, h0, l0);
    split_fp16(v1, h1, l1);
    ph = (uint32_t)__half_as_ushort(h0) | ((uint32_t)__half_as_ushort(h1) << 16);
    pl = (uint32_t)__half_as_ushort(l0) | ((uint32_t)__half_as_ushort(l1) << 16);
}

// ======= fused pass over x: transpose + fp16 split AND partial stats =======
__global__ void k_xpass(const float* __restrict__ src,
                        __half* __restrict__ dh, __half* __restrict__ dl){
    __shared__ float sm[64][65];
    int b = blockIdx.z;
    int nx = blockIdx.x, cy = blockIdx.y;
    int n0 = nx * 64, c0 = cy * 64;
    const float* sp = src + (size_t)b * CC * NN;
    int t = threadIdx.x;
    #pragma unroll
    for (int p = 0; p < 4; p++){
        int row = (t >> 4) + p * 16;
        int col = (t & 15) * 4;
        float4 v = *(const float4*)&sp[(size_t)(c0 + row) * NN + n0 + col];
        sm[row][col+0] = v.x; sm[row][col+1] = v.y;
        sm[row][col+2] = v.z; sm[row][col+3] = v.w;
        float rs  = v.x + v.y + v.z + v.w;
        float rs2 = v.x*v.x + v.y*v.y + v.z*v.z + v.w*v.w;
        #pragma unroll
        for (int o = 8; o; o >>= 1){
            rs  += __shfl_down_sync(~0u, rs , o, 16);
            rs2 += __shfl_down_sync(~0u, rs2, o, 16);
        }
        if ((t & 15) == 0){
            size_t idx = ((size_t)b * NTIL + nx) * CC + c0 + row;
            g_sumx_p [idx] = rs;
            g_sumx2_p[idx] = rs2;
        }
    }
    __syncthreads();
    uint32_t* dh32 = (uint32_t*)(dh + (size_t)b * NN * CC);
    uint32_t* dl32 = (uint32_t*)(dl + (size_t)b * NN * CC);
    #pragma unroll
    for (int p = 0; p < 8; p++){
        int nr = (t >> 5) + p * 8;
        int cu = t & 31;
        float v0 = sm[2*cu][nr], v1 = sm[2*cu+1][nr];
        uint32_t ph, pl;
        split_pack2h(v0, v1, ph, pl);
        size_t o = ((size_t)(n0 + nr) * CC + c0) / 2 + cu;
        dh32[o] = ph; dl32[o] = pl;
        float sc = v0*v0 + v1*v1;
        #pragma unroll
        for (int of = 16; of; of >>= 1) sc += __shfl_down_sync(~0u, sc, of);
        if (cu == 0) g_scores_p[((size_t)b * CTIL + cy) * NN + n0 + nr] = sc;
    }
}

__global__ void k_redstats(){
    int i = blockIdx.x * 256 + threadIdx.x;
    if (i >= BB*CC) return;
    int b = i / CC, c = i % CC;
    float s = 0.f, s2 = 0.f;
    #pragma unroll 7
    for (int k = 0; k < NTIL; k++){
        size_t idx = ((size_t)b * NTIL + k) * CC + c;
        s += g_sumx_p[idx]; s2 += g_sumx2_p[idx];
    }
    g_sumx[i] = s; g_sumx2[i] = s2;
}
__global__ void k_scores_red(){
    int i = blockIdx.x * 256 + threadIdx.x;
    if (i >= BB*NN) return;
    int b = i / NN, n = i % NN;
    float s = 0.f;
    #pragma unroll
    for (int k = 0; k < CTIL; k++)
        s += g_scores_p[((size_t)b * CTIL + k) * NN + n];
    g_scores[i] = s;
}

// ===================== prep kernels =====================
__global__ void k_prepW1(const float* __restrict__ fc1_w, const float* __restrict__ fc1_b,
                         const float* __restrict__ bn_g, const float* __restrict__ bn_b){
    int o = blockIdx.x, c = threadIdx.x;
    float s = 0.f, s2 = 0.f;
    #pragma unroll 8
    for (int bb2 = 0; bb2 < BB; bb2++){ s += g_sumx[bb2*CC + c]; s2 += g_sumx2[bb2*CC + c]; }
    float inv = 1.f / ((float)BB * (float)NN);
    float mu  = s * inv;
    float var = s2 * inv - mu * mu;
    float a   = bn_g[c] * rsqrtf(var + EPSB);
    float bnC = bn_b[c] - mu * a;
    float w = fc1_w[o*CC + c];
    float w1 = w * a * WSCALE;
    __half h, l; split_fp16(w1, h, l);
    g_W1h[o*CC + c] = h; g_W1l[o*CC + c] = l;
    __shared__ float red[CC];
    red[c] = w * bnC;
    __syncthreads();
    for (int sft = 256; sft > 0; sft >>= 1){
        if (c < sft && c + sft < CC) red[c] += red[c + sft];
        __syncthreads();
    }
    if (c == 0) g_b1[o] = fc1_b[o] + red[0];
}

__global__ void k_prepW2(const float* __restrict__ proj_w, const float* __restrict__ fc2_w,
                         const float* __restrict__ fc2_b, const float* __restrict__ proj_b){
    int o = blockIdx.x, c = threadIdx.x;
    const float* pr = proj_w + o*CC;
    float acc = 0.f;
    for (int k = 0; k < CC; k++)
        acc = fmaf(pr[k], fc2_w[k*CC + c], acc);
    __half h, l; split_fp16(acc * WSCALE, h, l);
    g_W2h[o*CC + c] = h; g_W2l[o*CC + c] = l;
    __shared__ float red[CC];
    red[c] = pr[c] * fc2_b[c];
    __syncthreads();
    for (int s = 256; s > 0; s >>= 1){
        if (c < s && c + s < CC) red[c] += red[c + s];
        __syncthreads();
    }
    if (c == 0) g_b2[o] = proj_b[o] + red[0];
}

// weights -> single scaled fp16 plane (B operand)
__global__ void k_prep_w16(const float* __restrict__ src, __half* __restrict__ dst, int n){
    int i = blockIdx.x * 256 + threadIdx.x;
    if (i < n) dst[i] = __float2half_rn(src[i] * WSCALE);
}

// fp32 rows -> fp16 hi/lo (A operand of mode 3)
__global__ void k_split_rows(const float* __restrict__ src, __half* __restrict__ dh,
                             __half* __restrict__ dl, int n){
    int i = blockIdx.x * 256 + threadIdx.x;
    if (i < n){
        __half h, l; split_fp16(src[i], h, l);
        dh[i] = h; dl[i] = l;
    }
}

// ===================== radix-select topk (scores >= 0 -> bits monotonic) ===============
__global__ void k_topk(){
    int b = blockIdx.x, tid = threadIdx.x;
    const float* sc = g_scores + b*NN;
    __shared__ uint32_t hist[256];
    __shared__ uint32_t s_prefix, s_k;
    __shared__ int s_cnt, s_neq;
    __shared__ int eqidx[128];
    if (tid == 0){ s_prefix = 0u; s_k = TOPK; }
    __syncthreads();
    #pragma unroll 1
    for (int pass = 0; pass < 4; pass++){
        int shift = 24 - pass*8;
        uint32_t pmask = (pass == 0) ? 0u : (0xFFFFFFFFu << (shift + 8));
        for (int i = tid; i < 256; i += 256) hist[i] = 0;
        __syncthreads();
        uint32_t pref = s_prefix;
        for (int n = tid; n < NN; n += 256){
            uint32_t v = __float_as_uint(sc[n]);
            if ((v & pmask) == pref) atomicAdd(&hist[(v >> shift) & 255], 1);
        }
        __syncthreads();
        if (tid == 0){
            uint32_t k = s_k, cum = 0; int Bn = 0;
            for (int bn = 255; bn >= 0; bn--){
                if (cum + hist[bn] >= k){ Bn = bn; break; }
                cum += hist[bn];
            }
            s_k = k - cum;
            s_prefix = pref | ((uint32_t)Bn << shift);
        }
        __syncthreads();
    }
    if (tid == 0){ s_cnt = 0; s_neq = 0; }
    __syncthreads();
    float thrf = __uint_as_float(s_prefix);
    for (int n = tid; n < NN; n += 256){
        float v = sc[n];
        if (v > thrf){
            int p = atomicAdd(&s_cnt, 1);
            g_topidx[b*TOPK + p] = n;
        } else if (v == thrf){
            int p = atomicAdd(&s_neq, 1);
            if (p < 128) eqidx[p] = n;
        }
    }
    __syncthreads();
    if (tid == 0){
        int have = s_cnt;
        int need = TOPK - have;
        int ne = s_neq < 128 ? s_neq : 128;
        for (int t = 0; t < need; t++){
            int best = 1 << 30, bi = 0;
            for (int i = 0; i < ne; i++)
                if (eqidx[i] < best){ best = eqidx[i]; bi = i; }
            g_topidx[b*TOPK + have + t] = best;
            eqidx[bi] = 1 << 30;
        }
    }
}

// coalesced token gather from the transposed split planes
__global__ void k_gather_tok(const __half* __restrict__ xth,
                             const __half* __restrict__ xtl){
    int j = blockIdx.x, b = blockIdx.y;
    int t = threadIdx.x;                     // 192 threads, 1 uint32 each
    int idx = g_topidx[b*TOPK + j];
    const uint32_t* sh = (const uint32_t*)(xth + ((size_t)b*NN + idx)*CC);
    const uint32_t* sl = (const uint32_t*)(xtl + ((size_t)b*NN + idx)*CC);
    uint32_t* dh = (uint32_t*)(g_tokh + ((size_t)b*NTOK + j)*CC);
    uint32_t* dl = (uint32_t*)(g_tokl + ((size_t)b*NTOK + j)*CC);
    dh[t] = sh[t];
    dl[t] = sl[t];
}

// bg token
__global__ void k_bgtok(){
    int b = blockIdx.x, c = threadIdx.x;
    const __half* th = g_tokh + (size_t)b*NTOK*CC + c;
    const __half* tl = g_tokl + (size_t)b*NTOK*CC + c;
    float s = 0.f;
    #pragma unroll 7
    for (int j = 0; j < TOPK; j++)
        s += __half2float(th[(size_t)j*CC]) + __half2float(tl[(size_t)j*CC]);
    float bg = (g_sumx[b*CC + c] - s) * (1.f / (float)(NN - TOPK));
    __half h, l; split_fp16(bg, h, l);
    g_tokh[((size_t)b*NTOK + TOPK)*CC + c] = h;
    g_tokl[((size_t)b*NTOK + TOPK)*CC + c] = l;
}

// ===================== attention over 99 tokens =====================
__global__ void k_attention(){
    int b = blockIdx.x / NHEAD, h = blockIdx.x % NHEAD;
    __shared__ float Ks[NTOK][HDIM];
    __shared__ float Vs[NTOK][HDIM];
    __shared__ float Qs[4][HDIM];
    __shared__ float Ps[4][NTOK];
    int tid = threadIdx.x;
    const float* qkvb = g_qkv + (size_t)b * NTOK * 3 * CC;
    for (int i = tid; i < NTOK*HDIM; i += blockDim.x){
        int t = i / HDIM, d = i % HDIM;
        Ks[t][d] = qkvb[(size_t)t*3*CC +   CC + h*HDIM + d];
        Vs[t][d] = qkvb[(size_t)t*3*CC + 2*CC + h*HDIM + d];
    }
    __syncthreads();
    int w = tid >> 5, lane = tid & 31;
    const float scale = rsqrtf((float)HDIM);
    for (int t = w; t < NTOK; t += 4){
        const float* qp = qkvb + (size_t)t*3*CC + h*HDIM;
        Qs[w][lane] = qp[lane];
        if (lane < HDIM - 32) Qs[w][lane + 32] = qp[lane + 32];
        __syncwarp();
        float sc[4]; float mx = -FLT_MAX;
        #pragma unroll
        for (int r = 0; r < 4; r++){
            int m = lane + r*32;
            float s = -FLT_MAX;
            if (m < NTOK){
                s = 0.f;
                #pragma unroll
                for (int d = 0; d < HDIM; d++) s = fmaf(Qs[w][d], Ks[m][d], s);
                s *= scale;
            }
            sc[r] = s; mx = fmaxf(mx, s);
        }
        for (int o = 16; o; o >>= 1) mx = fmaxf(mx, __shfl_xor_sync(~0u, mx, o));
        float sum = 0.f;
        #pragma unroll
        for (int r = 0; r < 4; r++){
            int m = lane + r*32;
            float e = (m < NTOK) ? expf(sc[r] - mx) : 0.f;
            sc[r] = e; sum += e;
        }
        for (int o = 16; o; o >>= 1) sum += __shfl_xor_sync(~0u, sum, o);
        float inv = 1.f / sum;
        #pragma unroll
        for (int r = 0; r < 4; r++){
            int m = lane + r*32;
            if (m < NTOK) Ps[w][m] = sc[r] * inv;
        }
        __syncwarp();
        for (int d = lane; d < HDIM; d += 32){
            float o = 0.f;
            for (int m = 0; m < NTOK; m++) o = fmaf(Ps[w][m], Vs[m][d], o);
            g_attnout[((size_t)b*NTOK + t)*CC + h*HDIM + d] = o;
        }
        __syncwarp();
    }
}

// ===================== depthwise 3x3 + transpose + fp16 store (single plane) ==========
__global__ void k_dwconv_t(const float* __restrict__ dw_w, const float* __restrict__ dw_b,
                           __half* __restrict__ dh){
    __shared__ float t[32][33];
    int b = blockIdx.z, c0 = blockIdx.y * 32, n0 = blockIdx.x * 32;
    int tid = threadIdx.y * 32 + threadIdx.x;
    for (int r = threadIdx.y; r < 32; r += 8){
        int c = c0 + r;
        int n = n0 + threadIdx.x;
        const float* src = g_h1 + ((size_t)b * CC + c) * NN;
        int y = n / WW, xp = n % WW;
        const float* w = dw_w + c * 9;
        float acc = dw_b[c];
        #pragma unroll
        for (int dy = -1; dy <= 1; dy++){
            int yy = y + dy;
            if (yy < 0 || yy >= HH) continue;
            #pragma unroll
            for (int dx = -1; dx <= 1; dx++){
                int xw = xp + dx;
                if (xw < 0 || xw >= WW) continue;
                acc = fmaf(src[yy*WW + xw], w[(dy+1)*3 + (dx+1)], acc);
            }
        }
        t[r][threadIdx.x] = acc;
    }
    __syncthreads();
    uint32_t* dh32 = (uint32_t*)(dh + (size_t)b * NN * CC);
    for (int idx = tid; idx < 32 * 16; idx += 256){
        int nr = idx >> 4, cu = idx & 15;
        uint32_t ph = (uint32_t)__half_as_ushort(__float2half_rn(t[2*cu][nr]))
                    | ((uint32_t)__half_as_ushort(__float2half_rn(t[2*cu+1][nr])) << 16);
        size_t o = ((size_t)(n0 + nr) * CC + c0) / 2 + cu;
        dh32[o] = ph;
    }
}

// ====== warp-mma fp16 2-product GEMM (128x128 tile, 128 threads, 4 warps 2x2) ====
// D = (Ah+Al) * Bh^T, fp32 accum. A pre-scaled by 64 when it's a weight; epilogue /64.
// MODE 0: h1 = gelu(acc/64 + b1[m]);  MODE 1: out = acc/64 + b2[m] + ptok_bg
// MODE 2: qkv = acc/64 + qkv_b[n];    MODE 3: ptok = acc/64
#define LDS_B 80
#define STG   (384*LDS_B)            // 30720 B per stage (Ah|Al|Bh, 128 rows each)
#define EPITCH 132
#define MM_SMEM (128*EPITCH*4)       // 67584 B >= 2*STG(61440); epilogue staging bound
#define JSTRIDE (32*CC*2)            // 32-row stride in fp16 planes

template<int MODE>
__global__ void __launch_bounds__(128)
k_mm(const __half* __restrict__ Aph, const __half* __restrict__ Apl,
     const __half* __restrict__ Bh_,
     float* __restrict__ Out, const float* __restrict__ bias,
     int Mrows, int Nrows){
    extern __shared__ char smem[];
    uint32_t sb = smem_to_u32(smem);
    int tid = threadIdx.x, wid = tid >> 5, lane = tid & 31;
    int m0 = blockIdx.x * 128, n0 = blockIdx.y * 128;
    int b = blockIdx.z;
    const __half* Bph = Bh_;
    if (MODE <= 1) Bph += (size_t)b * NN * CC;

    int r0 = tid >> 2, cu4 = tid & 3;
    const char* fAh = (const char*)Aph + ((size_t)(m0 + r0) * CC) * 2 + cu4 * 16;
    const char* fAl = (const char*)Apl + ((size_t)(m0 + r0) * CC) * 2 + cu4 * 16;
    const char* fBh = (const char*)Bph + ((size_t)(n0 + r0) * CC) * 2 + cu4 * 16;
    uint32_t d0 = (uint32_t)(r0 * LDS_B + cu4 * 16);
    bool fast = (m0 + 128 <= Mrows) && (n0 + 128 <= Nrows);

    #define LOADC_F(ch, st) do {                                                  \
        uint32_t s0w = sb + (st) * STG;                                           \
        int kb = (ch) * 64;                                                       \
        _Pragma("unroll")                                                         \
        for (int q = 0; q < 4; q++){                                              \
            CP_ASYNC16(s0w + d0 + q*(32*LDS_B),               fAh + kb + q*JSTRIDE, 16); \
            CP_ASYNC16(s0w + d0 + q*(32*LDS_B) + 128*LDS_B,   fAl + kb + q*JSTRIDE, 16); \
            CP_ASYNC16(s0w + d0 + q*(32*LDS_B) + 256*LDS_B,   fBh + kb + q*JSTRIDE, 16); \
        }                                                                         \
        CP_ASYNC_COMMIT();                                                        \
    } while(0)

    #define LOADC_S(ch, st) do {                                                  \
        int k0 = (ch) * 32;                                                       \
        uint32_t s0w = sb + (st) * STG;                                           \
        _Pragma("unroll")                                                         \
        for (int i = tid; i < 1536; i += 128){                                    \
            int r = i >> 2, cu = i & 3;                                           \
            uint32_t dst = s0w + (uint32_t)(r * LDS_B + cu * 16);                 \
            const char* src; uint32_t sz;                                         \
            if (r < 256){                                                         \
                int rr = r & 127;                                                 \
                int gm = m0 + rr;                                                 \
                sz = (gm < Mrows) ? 16u : 0u;                                     \
                int gmc = (gm < Mrows) ? gm : 0;                                  \
                const __half* base = (r < 128) ? Aph : Apl;                       \
                src = (const char*)(base + (size_t)gmc*CC + k0) + cu*16;          \
            } else {                                                              \
                int rr = r & 127;                                                 \
                int gn = n0 + rr;                                                 \
                sz = (gn < Nrows) ? 16u : 0u;                                     \
                int gnc = (gn < Nrows) ? gn : 0;                                  \
                src = (const char*)(Bph + (size_t)gnc*CC + k0) + cu*16;           \
            }                                                                     \
            CP_ASYNC16(dst, src, sz);                                             \
        }                                                                         \
        CP_ASYNC_COMMIT();                                                        \
    } while(0)

    float acc[4][8][4] = {};
    if (fast){ LOADC_F(0, 0); LOADC_F(1, 1); }
    else     { LOADC_S(0, 0); LOADC_S(1, 1); }

    int wm = (wid >> 1) * 64, wn = (wid & 1) * 64;
    uint32_t a_off = (uint32_t)(wm + (lane & 15)) * LDS_B + ((lane >> 4) & 1) * 16;
    uint32_t b_off = (uint32_t)(wn + (lane & 7) + ((lane >> 4) & 1) * 8) * LDS_B
                   + ((lane >> 3) & 1) * 16;

    #pragma unroll 1
    for (int c = 0; c < 12; c++){
        CP_ASYNC_WAIT(1);
        __syncthreads();
        uint32_t s0 = sb + (c & 1) * STG;
        #pragma unroll
        for (int kk = 0; kk < 2; kk++){
            uint32_t ah[4][4], al[4][4];
            #pragma unroll
            for (int i = 0; i < 4; i++){
                uint32_t ra = s0 + a_off + (uint32_t)(i * 16 * LDS_B) + kk * 32;
                ldsm_x4(ah[i], ra);
                ldsm_x4(al[i], ra + 128 * LDS_B);
            }
            #pragma unroll
            for (int j = 0; j < 4; j++){
                uint32_t bh[4];
                uint32_t rb = s0 + 256 * LDS_B + b_off + (uint32_t)(j * 16 * LDS_B) + kk * 32;
                ldsm_x4(bh, rb);
                #pragma unroll
                for (int i = 0; i < 4; i++) mma16816h(acc[i][j*2+0], ah[i], bh[0], bh[1]);
                #pragma unroll
                for (int i = 0; i < 4; i++) mma16816h(acc[i][j*2+1], ah[i], bh[2], bh[3]);
                #pragma unroll
                for (int i = 0; i < 4; i++) mma16816h(acc[i][j*2+0], al[i], bh[0], bh[1]);
                #pragma unroll
                for (int i = 0; i < 4; i++) mma16816h(acc[i][j*2+1], al[i], bh[2], bh[3]);
            }
        }
        __syncthreads();
        if (c + 2 < 12){
            if (fast) LOADC_F(c + 2, c & 1);
            else      LOADC_S(c + 2, c & 1);
        } else CP_ASYNC_COMMIT();
    }
    CP_ASYNC_WAIT(0);
    __syncthreads();

    // ---- stage accumulators in smem, then coalesced float4 stores ----
    float* eps = (float*)smem;
    int rbase = wm + (lane >> 2);
    int cbase = wn + (lane & 3) * 2;
    #pragma unroll
    for (int i = 0; i < 4; i++)
        #pragma unroll
        for (int half = 0; half < 2; half++){
            int ml = rbase + i * 16 + half * 8;
            #pragma unroll
            for (int j = 0; j < 8; j++){
                int nl = cbase + j * 8;
                eps[ml * EPITCH + nl    ] = acc[i][j][half*2+0];
                eps[ml * EPITCH + nl + 1] = acc[i][j][half*2+1];
            }
        }
    __syncthreads();
    for (int idx = tid; idx < 128 * 32; idx += 128){
        int ml = idx >> 5, nl = (idx & 31) * 4;
        float4 v = *(const float4*)&eps[ml * EPITCH + nl];
        int m = m0 + ml, n = n0 + nl;
        v.x *= INVWSC; v.y *= INVWSC; v.z *= INVWSC; v.w *= INVWSC;
        if (MODE <= 1){
            if (n >= Nrows) continue;
            float bs = bias[m];
            if (MODE == 1) bs += g_ptok[((size_t)b*NTOK + TOPK)*CC + m];
            v.x += bs; v.y += bs; v.z += bs; v.w += bs;
            if (MODE == 0){
                v.x = gelu_exact(v.x); v.y = gelu_exact(v.y);
                v.z = gelu_exact(v.z); v.w = gelu_exact(v.w);
            }
            *(float4*)&Out[((size_t)b*CC + m)*NN + n] = v;
        } else {
            if (m >= Mrows || n >= Nrows) continue;
            if (MODE == 2){
                v.x += bias[n]; v.y += bias[n+1]; v.z += bias[n+2]; v.w += bias[n+3];
            }
            *(float4*)&Out[(size_t)m * (MODE == 2 ? 3*CC : CC) + n] = v;
        }
    }
    #undef LOADC_F
    #undef LOADC_S
}

// ===================== scatter projected top tokens =====================
__global__ void k_scatter(float* __restrict__ out){
    int b = blockIdx.x / TOPK, j = blockIdx.x % TOPK;
    int o = threadIdx.x;
    int n = g_topidx[b*TOPK + j];
    float d = g_ptok[((size_t)b*NTOK + j   )*CC + o]
            - g_ptok[((size_t)b*NTOK + TOPK)*CC + o];
    out[((size_t)b*CC + o)*NN + n] += d;
}

// ===================== host launch =====================
extern "C" void kernel_launch(void* const* d_in, const int* in_sizes, int n_in,
                              void* d_out, int out_size){
    const float* x      = (const float*)d_in[0];
    const float* qkv_w  = (const float*)d_in[1];
    const float* qkv_b  = (const float*)d_in[2];
    const float* proj_w = (const float*)d_in[3];
    const float* proj_b = (const float*)d_in[4];
    const float* bn_g   = (const float*)d_in[5];
    const float* bn_b   = (const float*)d_in[6];
    const float* fc1_w  = (const float*)d_in[7];
    const float* fc1_b  = (const float*)d_in[8];
    const float* fc2_w  = (const float*)d_in[9];
    const float* fc2_b  = (const float*)d_in[10];
    const float* dw_w   = (const float*)d_in[11];
    const float* dw_b   = (const float*)d_in[12];
    float* out = (float*)d_out;

    float *p_qkv, *p_attnout, *p_ptok, *p_b1, *p_b2, *p_h1;
    __half *p_W1h, *p_W1l, *p_W2h, *p_W2l, *p_xth, *p_xtl;
    __half *p_tokh, *p_tokl, *p_aoh, *p_aol, *p_qw16, *p_pw16;
    cudaGetSymbolAddress((void**)&p_qkv    , g_qkv);
    cudaGetSymbolAddress((void**)&p_attnout, g_attnout);
    cudaGetSymbolAddress((void**)&p_ptok   , g_ptok);
    cudaGetSymbolAddress((void**)&p_b1     , g_b1);
    cudaGetSymbolAddress((void**)&p_b2     , g_b2);
    cudaGetSymbolAddress((void**)&p_h1     , g_h1);
    cudaGetSymbolAddress((void**)&p_W1h    , g_W1h);
    cudaGetSymbolAddress((void**)&p_W1l    , g_W1l);
    cudaGetSymbolAddress((void**)&p_W2h    , g_W2h);
    cudaGetSymbolAddress((void**)&p_W2l    , g_W2l);
    cudaGetSymbolAddress((void**)&p_xth    , g_xth);
    cudaGetSymbolAddress((void**)&p_xtl    , g_xtl);
    cudaGetSymbolAddress((void**)&p_tokh   , g_tokh);
    cudaGetSymbolAddress((void**)&p_tokl   , g_tokl);
    cudaGetSymbolAddress((void**)&p_aoh    , g_aoh);
    cudaGetSymbolAddress((void**)&p_aol    , g_aol);
    cudaGetSymbolAddress((void**)&p_qw16   , g_qw16);
    cudaGetSymbolAddress((void**)&p_pw16   , g_pw16);

    cudaFuncSetAttribute(k_mm<0>, cudaFuncAttributeMaxDynamicSharedMemorySize, MM_SMEM);
    cudaFuncSetAttribute(k_mm<1>, cudaFuncAttributeMaxDynamicSharedMemorySize, MM_SMEM);
    cudaFuncSetAttribute(k_mm<2>, cudaFuncAttributeMaxDynamicSharedMemorySize, MM_SMEM);
    cudaFuncSetAttribute(k_mm<3>, cudaFuncAttributeMaxDynamicSharedMemorySize, MM_SMEM);

    // ---- single fused pass over x, then the big GEMM as the 4th launch ----
    k_xpass   <<<dim3(NTIL, CTIL, BB), 256>>>(x, p_xth, p_xtl);             // 1
    k_redstats<<<(BB*CC + 255)/256, 256>>>();                               // 2
    k_prepW1  <<<CC, CC>>>(fc1_w, fc1_b, bn_g, bn_b);                       // 3
    dim3 gbig(CC/128, (NN + 127)/128, BB);   // m fast, n slow: B-tile L2 reuse
    k_mm<0><<<gbig, 128, MM_SMEM>>>(p_W1h, p_W1l, p_xth, p_h1, p_b1, CC, NN); // 4

    // remaining prep + salience branch
    k_scores_red<<<(BB*NN + 255)/256, 256>>>();
    k_prepW2  <<<CC, CC>>>(proj_w, fc2_w, fc2_b, proj_b);
    k_prep_w16<<<(3*CC*CC + 255)/256, 256>>>(qkv_w,  p_qw16, 3*CC*CC);
    k_prep_w16<<<(CC*CC   + 255)/256, 256>>>(proj_w, p_pw16, CC*CC);
    k_topk      <<<BB, 256>>>();
    k_gather_tok<<<dim3(TOPK, BB), 192>>>(p_xth, p_xtl);
    k_bgtok     <<<BB, CC>>>();
    k_mm<2><<<dim3((MTOK + 127)/128, (3*CC + 127)/128, 1), 128, MM_SMEM>>>(
        p_tokh, p_tokl, p_qw16, p_qkv, qkv_b, MTOK, 3*CC);
    k_attention <<<BB*NHEAD, 128>>>();
    k_split_rows<<<(MTOK*CC + 255)/256, 256>>>(p_attnout, p_aoh, p_aol, MTOK*CC);
    k_mm<3><<<dim3((MTOK + 127)/128, CC/128, 1), 128, MM_SMEM>>>(
        p_aoh, p_aol, p_pw16, p_ptok, (const float*)nullptr, MTOK, CC);

    // conv-mixer tail
    k_dwconv_t<<<dim3(NN/32, CC/32, BB), dim3(32, 8)>>>(dw_w, dw_b, p_xth);
    k_mm<1><<<gbig, 128, MM_SMEM>>>(p_W2h, p_W2l, p_xth, out, p_b2, CC, NN);

    // rank-99 correction at top-token positions
    k_scatter<<<BB*TOPK, CC>>>(out);
}

// round 15
// speedup vs baseline: 1.3108x; 1.0649x over previous
#include <cuda_runtime.h>
#include <cuda_fp16.h>
#include <math.h>
#include <float.h>
#include <stdint.h>

#define BB    32
#define CC    384
#define HH    56
#define WW    56
#define NN    3136
#define TOPK  98
#define NTOK  99
#define NHEAD 8
#define HDIM  48
#define EPSB  1e-5f
#define MTOK  (BB*NTOK)   // 3168 tokens
#define NTIL  (NN/64)     // 49
#define CTIL  (CC/64)     // 6
#define WSCALE   64.0f
#define INVWSC   0.015625f

// ===================== PTX helpers (sm_80-era, legal at compute_103) =====================
__device__ __forceinline__ uint32_t smem_to_u32(const void* smem_ptr) {
    uint32_t addr;
    asm("{ .reg .u64 tmp; cvta.to.shared.u64 tmp, %1; cvt.u32.u64 %0, tmp; }"
        : "=r"(addr) : "l"(smem_ptr));
    return addr;
}
#define CP_ASYNC16(dst, src, sz) \
    asm volatile("cp.async.cg.shared.global [%0], [%1], 16, %2;" \
        :: "r"((uint32_t)(dst)), "l"(src), "r"((uint32_t)(sz)) : "memory")
#define CP_ASYNC_COMMIT() asm volatile("cp.async.commit_group;" ::: "memory")
#define CP_ASYNC_WAIT(n)  asm volatile("cp.async.wait_group %0;" :: "n"(n) : "memory")

__device__ __forceinline__ void ldsm_x4(uint32_t (&r)[4], uint32_t addr){
    asm volatile("ldmatrix.sync.aligned.m8n8.x4.shared.b16 {%0,%1,%2,%3}, [%4];"
        : "=r"(r[0]),"=r"(r[1]),"=r"(r[2]),"=r"(r[3]) : "r"(addr));
}
__device__ __forceinline__ void mma16816h(float (&d)[4], const uint32_t (&a)[4],
                                          uint32_t b0, uint32_t b1){
    asm volatile("mma.sync.aligned.m16n8k16.row.col.f32.f16.f16.f32 "
        "{%0,%1,%2,%3}, {%4,%5,%6,%7}, {%8,%9}, {%0,%1,%2,%3};"
        : "+f"(d[0]),"+f"(d[1]),"+f"(d[2]),"+f"(d[3])
        : "r"(a[0]),"r"(a[1]),"r"(a[2]),"r"(a[3]), "r"(b0),"r"(b1));
}

// ===================== device scratch =====================
__device__ __half g_h1 [(size_t)BB*CC*NN];      // gelu(fc1(bn(x)))  [b][c][n] fp16
__device__ __half g_h2t[(size_t)BB*NN*CC];      // dwconv out, transposed [b][n][c] fp16
__device__ __half g_xth[(size_t)BB*NN*CC];      // [b][n][c] fp16 hi of x
__device__ __half g_xtl[(size_t)BB*NN*CC];      // [b][n][c] fp16 lo of x
__device__ float g_scores[BB*NN];
__device__ float g_scores_p[(size_t)BB*CTIL*NN];
__device__ float g_sumx_p [(size_t)BB*NTIL*CC];
__device__ float g_sumx2_p[(size_t)BB*NTIL*CC];
__device__ float g_sumx [BB*CC];
__device__ float g_sumx2[BB*CC];
__device__ int   g_topidx[BB*TOPK];
__device__ float g_qkv    [(size_t)MTOK*3*CC];
__device__ float g_attnout[MTOK*CC];
__device__ float g_ptok   [MTOK*CC];
__device__ __half g_W1h[CC*CC], g_W1l[CC*CC];   // fc1 (BN-folded), x64, fp16 hi/lo
__device__ __half g_W2h[CC*CC], g_W2l[CC*CC];   // proj@fc2, x64, fp16 hi/lo
__device__ __half g_tokh[MTOK*CC], g_tokl[MTOK*CC];
__device__ __half g_aoh [MTOK*CC], g_aol [MTOK*CC];
__device__ __half g_qw16[3*CC*CC];              // qkv_w x64 fp16
__device__ __half g_pw16[CC*CC];                // proj_w x64 fp16
__device__ float g_b1[CC];
__device__ float g_b2[CC];

__device__ __forceinline__ float gelu_exact(float v){
    return 0.5f * v * (1.0f + erff(v * 0.70710678118654752440f));
}
__device__ __forceinline__ void split_fp16(float v, __half& h, __half& l){
    h = __float2half_rn(v);
    l = __float2half_rn(v - __half2float(h));
}
__device__ __forceinline__ void split_pack2h(float v0, float v1, uint32_t& ph, uint32_t& pl){
    __half h0, l0, h1, l1;
    split_fp16(v0, h0, l0);
    split_fp16(v1, h1, l1);
    ph = (uint32_t)__half_as_ushort(h0) | ((uint32_t)__half_as_ushort(h1) << 16);
    pl = (uint32_t)__half_as_ushort(l0) | ((uint32_t)__half_as_ushort(l1) << 16);
}

// ======= fused pass over x: transpose + fp16 split AND partial stats =======
__global__ void k_xpass(const float* __restrict__ src,
                        __half* __restrict__ dh, __half* __restrict__ dl){
    __shared__ float sm[64][65];
    int b = blockIdx.z;
    int nx = blockIdx.x, cy = blockIdx.y;
    int n0 = nx * 64, c0 = cy * 64;
    const float* sp = src + (size_t)b * CC * NN;
    int t = threadIdx.x;
    #pragma unroll
    for (int p = 0; p < 4; p++){
        int row = (t >> 4) + p * 16;
        int col = (t & 15) * 4;
        float4 v = *(const float4*)&sp[(size_t)(c0 + row) * NN + n0 + col];
        sm[row][col+0] = v.x; sm[row][col+1] = v.y;
        sm[row][col+2] = v.z; sm[row][col+3] = v.w;
        float rs  = v.x + v.y + v.z + v.w;
        float rs2 = v.x*v.x + v.y*v.y + v.z*v.z + v.w*v.w;
        #pragma unroll
        for (int o = 8; o; o >>= 1){
            rs  += __shfl_down_sync(~0u, rs , o, 16);
            rs2 += __shfl_down_sync(~0u, rs2, o, 16);
        }
        if ((t & 15) == 0){
            size_t idx = ((size_t)b * NTIL + nx) * CC + c0 + row;
            g_sumx_p [idx] = rs;
            g_sumx2_p[idx] = rs2;
        }
    }
    __syncthreads();
    uint32_t* dh32 = (uint32_t*)(dh + (size_t)b * NN * CC);
    uint32_t* dl32 = (uint32_t*)(dl + (size_t)b * NN * CC);
    #pragma unroll
    for (int p = 0; p < 8; p++){
        int nr = (t >> 5) + p * 8;
        int cu = t & 31;
        float v0 = sm[2*cu][nr], v1 = sm[2*cu+1][nr];
        uint32_t ph, pl;
        split_pack2h(v0, v1, ph, pl);
        size_t o = ((size_t)(n0 + nr) * CC + c0) / 2 + cu;
        dh32[o] = ph; dl32[o] = pl;
        float sc = v0*v0 + v1*v1;
        #pragma unroll
        for (int of = 16; of; of >>= 1) sc += __shfl_down_sync(~0u, sc, of);
        if (cu == 0) g_scores_p[((size_t)b * CTIL + cy) * NN + n0 + nr] = sc;
    }
}

__global__ void k_redstats(){
    int i = blockIdx.x * 256 + threadIdx.x;
    if (i >= BB*CC) return;
    int b = i / CC, c = i % CC;
    float s = 0.f, s2 = 0.f;
    #pragma unroll 7
    for (int k = 0; k < NTIL; k++){
        size_t idx = ((size_t)b * NTIL + k) * CC + c;
        s += g_sumx_p[idx]; s2 += g_sumx2_p[idx];
    }
    g_sumx[i] = s; g_sumx2[i] = s2;
}
__global__ void k_scores_red(){
    int i = blockIdx.x * 256 + threadIdx.x;
    if (i >= BB*NN) return;
    int b = i / NN, n = i % NN;
    float s = 0.f;
    #pragma unroll
    for (int k = 0; k < CTIL; k++)
        s += g_scores_p[((size_t)b * CTIL + k) * NN + n];
    g_scores[i] = s;
}

// ===================== prep kernels =====================
__global__ void k_prepW1(const float* __restrict__ fc1_w, const float* __restrict__ fc1_b,
                         const float* __restrict__ bn_g, const float* __restrict__ bn_b){
    int o = blockIdx.x, c = threadIdx.x;
    float s = 0.f, s2 = 0.f;
    #pragma unroll 8
    for (int bb2 = 0; bb2 < BB; bb2++){ s += g_sumx[bb2*CC + c]; s2 += g_sumx2[bb2*CC + c]; }
    float inv = 1.f / ((float)BB * (float)NN);
    float mu  = s * inv;
    float var = s2 * inv - mu * mu;
    float a   = bn_g[c] * rsqrtf(var + EPSB);
    float bnC = bn_b[c] - mu * a;
    float w = fc1_w[o*CC + c];
    float w1 = w * a * WSCALE;
    __half h, l; split_fp16(w1, h, l);
    g_W1h[o*CC + c] = h; g_W1l[o*CC + c] = l;
    __shared__ float red[CC];
    red[c] = w * bnC;
    __syncthreads();
    for (int sft = 256; sft > 0; sft >>= 1){
        if (c < sft && c + sft < CC) red[c] += red[c + sft];
        __syncthreads();
    }
    if (c == 0) g_b1[o] = fc1_b[o] + red[0];
}

__global__ void k_prepW2(const float* __restrict__ proj_w, const float* __restrict__ fc2_w,
                         const float* __restrict__ fc2_b, const float* __restrict__ proj_b){
    int o = blockIdx.x, c = threadIdx.x;
    const float* pr = proj_w + o*CC;
    float acc = 0.f;
    for (int k = 0; k < CC; k++)
        acc = fmaf(pr[k], fc2_w[k*CC + c], acc);
    __half h, l; split_fp16(acc * WSCALE, h, l);
    g_W2h[o*CC + c] = h; g_W2l[o*CC + c] = l;
    __shared__ float red[CC];
    red[c] = pr[c] * fc2_b[c];
    __syncthreads();
    for (int s = 256; s > 0; s >>= 1){
        if (c < s && c + s < CC) red[c] += red[c + s];
        __syncthreads();
    }
    if (c == 0) g_b2[o] = proj_b[o] + red[0];
}

__global__ void k_prep_w16(const float* __restrict__ src, __half* __restrict__ dst, int n){
    int i = blockIdx.x * 256 + threadIdx.x;
    if (i < n) dst[i] = __float2half_rn(src[i] * WSCALE);
}

__global__ void k_split_rows(const float* __restrict__ src, __half* __restrict__ dh,
                             __half* __restrict__ dl, int n){
    int i = blockIdx.x * 256 + threadIdx.x;
    if (i < n){
        __half h, l; split_fp16(src[i], h, l);
        dh[i] = h; dl[i] = l;
    }
}

// ===================== radix-select topk (scores >= 0 -> bits monotonic) ===============
__global__ void k_topk(){
    int b = blockIdx.x, tid = threadIdx.x;
    const float* sc = g_scores + b*NN;
    __shared__ uint32_t hist[256];
    __shared__ uint32_t s_prefix, s_k;
    __shared__ int s_cnt, s_neq;
    __shared__ int eqidx[128];
    if (tid == 0){ s_prefix = 0u; s_k = TOPK; }
    __syncthreads();
    #pragma unroll 1
    for (int pass = 0; pass < 4; pass++){
        int shift = 24 - pass*8;
        uint32_t pmask = (pass == 0) ? 0u : (0xFFFFFFFFu << (shift + 8));
        for (int i = tid; i < 256; i += 256) hist[i] = 0;
        __syncthreads();
        uint32_t pref = s_prefix;
        for (int n = tid; n < NN; n += 256){
            uint32_t v = __float_as_uint(sc[n]);
            if ((v & pmask) == pref) atomicAdd(&hist[(v >> shift) & 255], 1);
        }
        __syncthreads();
        if (tid == 0){
            uint32_t k = s_k, cum = 0; int Bn = 0;
            for (int bn = 255; bn >= 0; bn--){
                if (cum + hist[bn] >= k){ Bn = bn; break; }
                cum += hist[bn];
            }
            s_k = k - cum;
            s_prefix = pref | ((uint32_t)Bn << shift);
        }
        __syncthreads();
    }
    if (tid == 0){ s_cnt = 0; s_neq = 0; }
    __syncthreads();
    float thrf = __uint_as_float(s_prefix);
    for (int n = tid; n < NN; n += 256){
        float v = sc[n];
        if (v > thrf){
            int p = atomicAdd(&s_cnt, 1);
            g_topidx[b*TOPK + p] = n;
        } else if (v == thrf){
            int p = atomicAdd(&s_neq, 1);
            if (p < 128) eqidx[p] = n;
        }
    }
    __syncthreads();
    if (tid == 0){
        int have = s_cnt;
        int need = TOPK - have;
        int ne = s_neq < 128 ? s_neq : 128;
        for (int t = 0; t < need; t++){
            int best = 1 << 30, bi = 0;
            for (int i = 0; i < ne; i++)
                if (eqidx[i] < best){ best = eqidx[i]; bi = i; }
            g_topidx[b*TOPK + have + t] = best;
            eqidx[bi] = 1 << 30;
        }
    }
}

// coalesced token gather from the transposed split planes
__global__ void k_gather_tok(const __half* __restrict__ xth,
                             const __half* __restrict__ xtl){
    int j = blockIdx.x, b = blockIdx.y;
    int t = threadIdx.x;                     // 192 threads, 1 uint32 each
    int idx = g_topidx[b*TOPK + j];
    const uint32_t* sh = (const uint32_t*)(xth + ((size_t)b*NN + idx)*CC);
    const uint32_t* sl = (const uint32_t*)(xtl + ((size_t)b*NN + idx)*CC);
    uint32_t* dh = (uint32_t*)(g_tokh + ((size_t)b*NTOK + j)*CC);
    uint32_t* dl = (uint32_t*)(g_tokl + ((size_t)b*NTOK + j)*CC);
    dh[t] = sh[t];
    dl[t] = sl[t];
}

// bg token
__global__ void k_bgtok(){
    int b = blockIdx.x, c = threadIdx.x;
    const __half* th = g_tokh + (size_t)b*NTOK*CC + c;
    const __half* tl = g_tokl + (size_t)b*NTOK*CC + c;
    float s = 0.f;
    #pragma unroll 7
    for (int j = 0; j < TOPK; j++)
        s += __half2float(th[(size_t)j*CC]) + __half2float(tl[(size_t)j*CC]);
    float bg = (g_sumx[b*CC + c] - s) * (1.f / (float)(NN - TOPK));
    __half h, l; split_fp16(bg, h, l);
    g_tokh[((size_t)b*NTOK + TOPK)*CC + c] = h;
    g_tokl[((size_t)b*NTOK + TOPK)*CC + c] = l;
}

// ===================== attention over 99 tokens =====================
__global__ void k_attention(){
    int b = blockIdx.x / NHEAD, h = blockIdx.x % NHEAD;
    __shared__ float Ks[NTOK][HDIM];
    __shared__ float Vs[NTOK][HDIM];
    __shared__ float Qs[4][HDIM];
    __shared__ float Ps[4][NTOK];
    int tid = threadIdx.x;
    const float* qkvb = g_qkv + (size_t)b * NTOK * 3 * CC;
    for (int i = tid; i < NTOK*HDIM; i += blockDim.x){
        int t = i / HDIM, d = i % HDIM;
        Ks[t][d] = qkvb[(size_t)t*3*CC +   CC + h*HDIM + d];
        Vs[t][d] = qkvb[(size_t)t*3*CC + 2*CC + h*HDIM + d];
    }
    __syncthreads();
    int w = tid >> 5, lane = tid & 31;
    const float scale = rsqrtf((float)HDIM);
    for (int t = w; t < NTOK; t += 4){
        const float* qp = qkvb + (size_t)t*3*CC + h*HDIM;
        Qs[w][lane] = qp[lane];
        if (lane < HDIM - 32) Qs[w][lane + 32] = qp[lane + 32];
        __syncwarp();
        float sc[4]; float mx = -FLT_MAX;
        #pragma unroll
        for (int r = 0; r < 4; r++){
            int m = lane + r*32;
            float s = -FLT_MAX;
            if (m < NTOK){
                s = 0.f;
                #pragma unroll
                for (int d = 0; d < HDIM; d++) s = fmaf(Qs[w][d], Ks[m][d], s);
                s *= scale;
            }
            sc[r] = s; mx = fmaxf(mx, s);
        }
        for (int o = 16; o; o >>= 1) mx = fmaxf(mx, __shfl_xor_sync(~0u, mx, o));
        float sum = 0.f;
        #pragma unroll
        for (int r = 0; r < 4; r++){
            int m = lane + r*32;
            float e = (m < NTOK) ? expf(sc[r] - mx) : 0.f;
            sc[r] = e; sum += e;
        }
        for (int o = 16; o; o >>= 1) sum += __shfl_xor_sync(~0u, sum, o);
        float inv = 1.f / sum;
        #pragma unroll
        for (int r = 0; r < 4; r++){
            int m = lane + r*32;
            if (m < NTOK) Ps[w][m] = sc[r] * inv;
        }
        __syncwarp();
        for (int d = lane; d < HDIM; d += 32){
            float o = 0.f;
            for (int m = 0; m < NTOK; m++) o = fmaf(Ps[w][m], Vs[m][d], o);
            g_attnout[((size_t)b*NTOK + t)*CC + h*HDIM + d] = o;
        }
        __syncwarp();
    }
}

// ===================== depthwise 3x3 (fp16 in) + transpose + fp16 store ==========
__global__ void k_dwconv_t(const float* __restrict__ dw_w, const float* __restrict__ dw_b,
                           __half* __restrict__ dh){
    __shared__ float t[32][33];
    int b = blockIdx.z, c0 = blockIdx.y * 32, n0 = blockIdx.x * 32;
    int tid = threadIdx.y * 32 + threadIdx.x;
    for (int r = threadIdx.y; r < 32; r += 8){
        int c = c0 + r;
        int n = n0 + threadIdx.x;
        const __half* src = g_h1 + ((size_t)b * CC + c) * NN;
        int y = n / WW, xp = n % WW;
        const float* w = dw_w + c * 9;
        float acc = dw_b[c];
        #pragma unroll
        for (int dy = -1; dy <= 1; dy++){
            int yy = y + dy;
            if (yy < 0 || yy >= HH) continue;
            #pragma unroll
            for (int dx = -1; dx <= 1; dx++){
                int xw = xp + dx;
                if (xw < 0 || xw >= WW) continue;
                acc = fmaf(__half2float(src[yy*WW + xw]), w[(dy+1)*3 + (dx+1)], acc);
            }
        }
        t[r][threadIdx.x] = acc;
    }
    __syncthreads();
    uint32_t* dh32 = (uint32_t*)(dh + (size_t)b * NN * CC);
    for (int idx = tid; idx < 32 * 16; idx += 256){
        int nr = idx >> 4, cu = idx & 15;
        uint32_t ph = (uint32_t)__half_as_ushort(__float2half_rn(t[2*cu][nr]))
                    | ((uint32_t)__half_as_ushort(__float2half_rn(t[2*cu+1][nr])) << 16);
        size_t o = ((size_t)(n0 + nr) * CC + c0) / 2 + cu;
        dh32[o] = ph;
    }
}

// ====== warp-mma fp16 2-product GEMM (128x128 tile, 128 threads, 4 warps 2x2) ====
// D = (Ah+Al) * Bh^T, fp32 accum. A pre-scaled by 64; epilogue /64.
// MODE 0: h1(fp16) = gelu(acc/64 + b1[m]);  MODE 1: out(fp32) = acc/64 + b2[m] + ptok_bg
// MODE 2: qkv = acc/64 + qkv_b[n];          MODE 3: ptok = acc/64
#define LDS_B 80
#define STG   (384*LDS_B)            // 30720 B per stage
#define EPITCH 132
#define MM_SMEM (128*EPITCH*4)       // 67584 B >= 2*STG; epilogue staging bound
#define JSTRIDE (32*CC*2)

template<int MODE>
__global__ void __launch_bounds__(128)
k_mm(const __half* __restrict__ Aph, const __half* __restrict__ Apl,
     const __half* __restrict__ Bh_,
     float* __restrict__ Out, const float* __restrict__ bias,
     int Mrows, int Nrows){
    extern __shared__ char smem[];
    uint32_t sb = smem_to_u32(smem);
    int tid = threadIdx.x, wid = tid >> 5, lane = tid & 31;
    int m0 = blockIdx.x * 128, n0 = blockIdx.y * 128;
    int b = blockIdx.z;
    const __half* Bph = Bh_;
    if (MODE <= 1) Bph += (size_t)b * NN * CC;

    int r0 = tid >> 2, cu4 = tid & 3;
    const char* fAh = (const char*)Aph + ((size_t)(m0 + r0) * CC) * 2 + cu4 * 16;
    const char* fAl = (const char*)Apl + ((size_t)(m0 + r0) * CC) * 2 + cu4 * 16;
    const char* fBh = (const char*)Bph + ((size_t)(n0 + r0) * CC) * 2 + cu4 * 16;
    uint32_t d0 = (uint32_t)(r0 * LDS_B + cu4 * 16);
    bool fast = (m0 + 128 <= Mrows) && (n0 + 128 <= Nrows);

    #define LOADC_F(ch, st) do {                                                  \
        uint32_t s0w = sb + (st) * STG;                                           \
        int kb = (ch) * 64;                                                       \
        _Pragma("unroll")                                                         \
        for (int q = 0; q < 4; q++){                                              \
            CP_ASYNC16(s0w + d0 + q*(32*LDS_B),               fAh + kb + q*JSTRIDE, 16); \
            CP_ASYNC16(s0w + d0 + q*(32*LDS_B) + 128*LDS_B,   fAl + kb + q*JSTRIDE, 16); \
            CP_ASYNC16(s0w + d0 + q*(32*LDS_B) + 256*LDS_B,   fBh + kb + q*JSTRIDE, 16); \
        }                                                                         \
        CP_ASYNC_COMMIT();                                                        \
    } while(0)

    #define LOADC_S(ch, st) do {                                                  \
        int k0 = (ch) * 32;                                                       \
        uint32_t s0w = sb + (st) * STG;                                           \
        _Pragma("unroll")                                                         \
        for (int i = tid; i < 1536; i += 128){                                    \
            int r = i >> 2, cu = i & 3;                                           \
            uint32_t dst = s0w + (uint32_t)(r * LDS_B + cu * 16);                 \
            const char* src; uint32_t sz;                                         \
            if (r < 256){                                                         \
                int rr = r & 127;                                                 \
                int gm = m0 + rr;                                                 \
                sz = (gm < Mrows) ? 16u : 0u;                                     \
                int gmc = (gm < Mrows) ? gm : 0;                                  \
                const __half* base = (r < 128) ? Aph : Apl;                       \
                src = (const char*)(base + (size_t)gmc*CC + k0) + cu*16;          \
            } else {                                                              \
                int rr = r & 127;                                                 \
                int gn = n0 + rr;                                                 \
                sz = (gn < Nrows) ? 16u : 0u;                                     \
                int gnc = (gn < Nrows) ? gn : 0;                                  \
                src = (const char*)(Bph + (size_t)gnc*CC + k0) + cu*16;           \
            }                                                                     \
            CP_ASYNC16(dst, src, sz);                                             \
        }                                                                         \
        CP_ASYNC_COMMIT();                                                        \
    } while(0)

    float acc[4][8][4] = {};
    if (fast){ LOADC_F(0, 0); LOADC_F(1, 1); }
    else     { LOADC_S(0, 0); LOADC_S(1, 1); }

    int wm = (wid >> 1) * 64, wn = (wid & 1) * 64;
    uint32_t a_off = (uint32_t)(wm + (lane & 15)) * LDS_B + ((lane >> 4) & 1) * 16;
    uint32_t b_off = (uint32_t)(wn + (lane & 7) + ((lane >> 4) & 1) * 8) * LDS_B
                   + ((lane >> 3) & 1) * 16;

    #pragma unroll 1
    for (int c = 0; c < 12; c++){
        CP_ASYNC_WAIT(1);
        __syncthreads();
        uint32_t s0 = sb + (c & 1) * STG;
        #pragma unroll
        for (int kk = 0; kk < 2; kk++){
            uint32_t ah[4][4], al[4][4];
            #pragma unroll
            for (int i = 0; i < 4; i++){
                uint32_t ra = s0 + a_off + (uint32_t)(i * 16 * LDS_B) + kk * 32;
                ldsm_x4(ah[i], ra);
                ldsm_x4(al[i], ra + 128 * LDS_B);
            }
            #pragma unroll
            for (int j = 0; j < 4; j++){
                uint32_t bh[4];
                uint32_t rb = s0 + 256 * LDS_B + b_off + (uint32_t)(j * 16 * LDS_B) + kk * 32;
                ldsm_x4(bh, rb);
                #pragma unroll
                for (int i = 0; i < 4; i++) mma16816h(acc[i][j*2+0], ah[i], bh[0], bh[1]);
                #pragma unroll
                for (int i = 0; i < 4; i++) mma16816h(acc[i][j*2+1], ah[i], bh[2], bh[3]);
                #pragma unroll
                for (int i = 0; i < 4; i++) mma16816h(acc[i][j*2+0], al[i], bh[0], bh[1]);
                #pragma unroll
                for (int i = 0; i < 4; i++) mma16816h(acc[i][j*2+1], al[i], bh[2], bh[3]);
            }
        }
        __syncthreads();
        if (c + 2 < 12){
            if (fast) LOADC_F(c + 2, c & 1);
            else      LOADC_S(c + 2, c & 1);
        } else CP_ASYNC_COMMIT();
    }
    CP_ASYNC_WAIT(0);
    __syncthreads();

    // ---- stage accumulators in smem, then coalesced stores ----
    float* eps = (float*)smem;
    int rbase = wm + (lane >> 2);
    int cbase = wn + (lane & 3) * 2;
    #pragma unroll
    for (int i = 0; i < 4; i++)
        #pragma unroll
        for (int half = 0; half < 2; half++){
            int ml = rbase + i * 16 + half * 8;
            #pragma unroll
            for (int j = 0; j < 8; j++){
                int nl = cbase + j * 8;
                eps[ml * EPITCH + nl    ] = acc[i][j][half*2+0];
                eps[ml * EPITCH + nl + 1] = acc[i][j][half*2+1];
            }
        }
    __syncthreads();
    for (int idx = tid; idx < 128 * 32; idx += 128){
        int ml = idx >> 5, nl = (idx & 31) * 4;
        float4 v = *(const float4*)&eps[ml * EPITCH + nl];
        int m = m0 + ml, n = n0 + nl;
        v.x *= INVWSC; v.y *= INVWSC; v.z *= INVWSC; v.w *= INVWSC;
        if (MODE == 0){
            if (n >= Nrows) continue;
            float bs = bias[m];
            v.x = gelu_exact(v.x + bs); v.y = gelu_exact(v.y + bs);
            v.z = gelu_exact(v.z + bs); v.w = gelu_exact(v.w + bs);
            __half* hp = (__half*)Out + ((size_t)b*CC + m)*NN + n;
            *(__half2*)(hp    ) = __floats2half2_rn(v.x, v.y);
            *(__half2*)(hp + 2) = __floats2half2_rn(v.z, v.w);
        } else if (MODE == 1){
            if (n >= Nrows) continue;
            float bs = bias[m] + g_ptok[((size_t)b*NTOK + TOPK)*CC + m];
            v.x += bs; v.y += bs; v.z += bs; v.w += bs;
            *(float4*)&Out[((size_t)b*CC + m)*NN + n] = v;
        } else {
            if (m >= Mrows || n >= Nrows) continue;
            if (MODE == 2){
                v.x += bias[n]; v.y += bias[n+1]; v.z += bias[n+2]; v.w += bias[n+3];
            }
            *(float4*)&Out[(size_t)m * (MODE == 2 ? 3*CC : CC) + n] = v;
        }
    }
    #undef LOADC_F
    #undef LOADC_S
}

// ===================== scatter projected top tokens =====================
__global__ void k_scatter(float* __restrict__ out){
    int b = blockIdx.x / TOPK, j = blockIdx.x % TOPK;
    int o = threadIdx.x;
    int n = g_topidx[b*TOPK + j];
    float d = g_ptok[((size_t)b*NTOK + j   )*CC + o]
            - g_ptok[((size_t)b*NTOK + TOPK)*CC + o];
    out[((size_t)b*CC + o)*NN + n] += d;
}

// ===================== host launch =====================
extern "C" void kernel_launch(void* const* d_in, const int* in_sizes, int n_in,
                              void* d_out, int out_size){
    const float* x      = (const float*)d_in[0];
    const float* qkv_w  = (const float*)d_in[1];
    const float* qkv_b  = (const float*)d_in[2];
    const float* proj_w = (const float*)d_in[3];
    const float* proj_b = (const float*)d_in[4];
    const float* bn_g   = (const float*)d_in[5];
    const float* bn_b   = (const float*)d_in[6];
    const float* fc1_w  = (const float*)d_in[7];
    const float* fc1_b  = (const float*)d_in[8];
    const float* fc2_w  = (const float*)d_in[9];
    const float* fc2_b  = (const float*)d_in[10];
    const float* dw_w   = (const float*)d_in[11];
    const float* dw_b   = (const float*)d_in[12];
    float* out = (float*)d_out;

    float *p_qkv, *p_attnout, *p_ptok, *p_b1, *p_b2;
    __half *p_h1, *p_h2t, *p_W1h, *p_W1l, *p_W2h, *p_W2l, *p_xth, *p_xtl;
    __half *p_tokh, *p_tokl, *p_aoh, *p_aol, *p_qw16, *p_pw16;
    cudaGetSymbolAddress((void**)&p_qkv    , g_qkv);
    cudaGetSymbolAddress((void**)&p_attnout, g_attnout);
    cudaGetSymbolAddress((void**)&p_ptok   , g_ptok);
    cudaGetSymbolAddress((void**)&p_b1     , g_b1);
    cudaGetSymbolAddress((void**)&p_b2     , g_b2);
    cudaGetSymbolAddress((void**)&p_h1     , g_h1);
    cudaGetSymbolAddress((void**)&p_h2t    , g_h2t);
    cudaGetSymbolAddress((void**)&p_W1h    , g_W1h);
    cudaGetSymbolAddress((void**)&p_W1l    , g_W1l);
    cudaGetSymbolAddress((void**)&p_W2h    , g_W2h);
    cudaGetSymbolAddress((void**)&p_W2l    , g_W2l);
    cudaGetSymbolAddress((void**)&p_xth    , g_xth);
    cudaGetSymbolAddress((void**)&p_xtl    , g_xtl);
    cudaGetSymbolAddress((void**)&p_tokh   , g_tokh);
    cudaGetSymbolAddress((void**)&p_tokl   , g_tokl);
    cudaGetSymbolAddress((void**)&p_aoh    , g_aoh);
    cudaGetSymbolAddress((void**)&p_aol    , g_aol);
    cudaGetSymbolAddress((void**)&p_qw16   , g_qw16);
    cudaGetSymbolAddress((void**)&p_pw16   , g_pw16);

    cudaFuncSetAttribute(k_mm<0>, cudaFuncAttributeMaxDynamicSharedMemorySize, MM_SMEM);
    cudaFuncSetAttribute(k_mm<1>, cudaFuncAttributeMaxDynamicSharedMemorySize, MM_SMEM);
    cudaFuncSetAttribute(k_mm<2>, cudaFuncAttributeMaxDynamicSharedMemorySize, MM_SMEM);
    cudaFuncSetAttribute(k_mm<3>, cudaFuncAttributeMaxDynamicSharedMemorySize, MM_SMEM);

    // fork/join resources (created per call; host-side objects, no device alloc)
    cudaStream_t s2;
    cudaStreamCreateWithFlags(&s2, cudaStreamNonBlocking);
    cudaEvent_t evF, evJ;
    cudaEventCreateWithFlags(&evF, cudaEventDisableTiming);
    cudaEventCreateWithFlags(&evJ, cudaEventDisableTiming);

    // ---- stream 0: conv-mixer chain ----
    k_xpass   <<<dim3(NTIL, CTIL, BB), 256>>>(x, p_xth, p_xtl);
    k_redstats<<<(BB*CC + 255)/256, 256>>>();
    cudaEventRecord(evF, 0);
    cudaStreamWaitEvent(s2, evF, 0);
    k_prepW1  <<<CC, CC>>>(fc1_w, fc1_b, bn_g, bn_b);
    dim3 gbig(CC/128, (NN + 127)/128, BB);
    k_mm<0><<<gbig, 128, MM_SMEM>>>(p_W1h, p_W1l, p_xth, (float*)p_h1, p_b1, CC, NN);
    k_dwconv_t<<<dim3(NN/32, CC/32, BB), dim3(32, 8)>>>(dw_w, dw_b, p_h2t);

    // ---- stream s2: salience branch (overlaps with k_mm<0> + dwconv) ----
    k_scores_red<<<(BB*NN + 255)/256, 256, 0, s2>>>();
    k_prepW2  <<<CC, CC, 0, s2>>>(proj_w, fc2_w, fc2_b, proj_b);
    k_prep_w16<<<(3*CC*CC + 255)/256, 256, 0, s2>>>(qkv_w,  p_qw16, 3*CC*CC);
    k_prep_w16<<<(CC*CC   + 255)/256, 256, 0, s2>>>(proj_w, p_pw16, CC*CC);
    k_topk      <<<BB, 256, 0, s2>>>();
    k_gather_tok<<<dim3(TOPK, BB), 192, 0, s2>>>(p_xth, p_xtl);
    k_bgtok     <<<BB, CC, 0, s2>>>();
    k_mm<2><<<dim3((MTOK + 127)/128, (3*CC + 127)/128, 1), 128, MM_SMEM, s2>>>(
        p_tokh, p_tokl, p_qw16, p_qkv, qkv_b, MTOK, 3*CC);
    k_attention <<<BB*NHEAD, 128, 0, s2>>>();
    k_split_rows<<<(MTOK*CC + 255)/256, 256, 0, s2>>>(p_attnout, p_aoh, p_aol, MTOK*CC);
    k_mm<3><<<dim3((MTOK + 127)/128, CC/128, 1), 128, MM_SMEM, s2>>>(
        p_aoh, p_aol, p_pw16, p_ptok, (const float*)nullptr, MTOK, CC);
    cudaEventRecord(evJ, s2);
    cudaStreamWaitEvent(0, evJ, 0);

    // ---- stream 0: final GEMM + scatter (needs ptok + W2 from s2, h2t from dwconv) ----
    k_mm<1><<<gbig, 128, MM_SMEM>>>(p_W2h, p_W2l, p_h2t, out, p_b2, CC, NN);
    k_scatter<<<BB*TOPK, CC>>>(out);
}

// round 16
// speedup vs baseline: 1.5443x; 1.1781x over previous
#include <cuda_runtime.h>
#include <cuda_fp16.h>
#include <math.h>
#include <float.h>
#include <stdint.h>

#define BB    32
#define CC    384
#define HH    56
#define WW    56
#define NN    3136
#define TOPK  98
#define NTOK  99
#define NHEAD 8
#define HDIM  48
#define EPSB  1e-5f
#define MTOK  (BB*NTOK)   // 3168 tokens
#define NTIL  (NN/64)     // 49
#define CTIL  (CC/64)     // 6
#define WSCALE   64.0f
#define INVWSC   0.015625f

// ===================== PTX helpers (sm_80-era, legal at compute_103) =====================
__device__ __forceinline__ uint32_t smem_to_u32(const void* smem_ptr) {
    uint32_t addr;
    asm("{ .reg .u64 tmp; cvta.to.shared.u64 tmp, %1; cvt.u32.u64 %0, tmp; }"
        : "=r"(addr) : "l"(smem_ptr));
    return addr;
}
#define CP_ASYNC16(dst, src, sz) \
    asm volatile("cp.async.cg.shared.global [%0], [%1], 16, %2;" \
        :: "r"((uint32_t)(dst)), "l"(src), "r"((uint32_t)(sz)) : "memory")
#define CP_ASYNC_COMMIT() asm volatile("cp.async.commit_group;" ::: "memory")
#define CP_ASYNC_WAIT(n)  asm volatile("cp.async.wait_group %0;" :: "n"(n) : "memory")

__device__ __forceinline__ void ldsm_x4(uint32_t (&r)[4], uint32_t addr){
    asm volatile("ldmatrix.sync.aligned.m8n8.x4.shared.b16 {%0,%1,%2,%3}, [%4];"
        : "=r"(r[0]),"=r"(r[1]),"=r"(r[2]),"=r"(r[3]) : "r"(addr));
}
__device__ __forceinline__ void mma16816h(float (&d)[4], const uint32_t (&a)[4],
                                          uint32_t b0, uint32_t b1){
    asm volatile("mma.sync.aligned.m16n8k16.row.col.f32.f16.f16.f32 "
        "{%0,%1,%2,%3}, {%4,%5,%6,%7}, {%8,%9}, {%0,%1,%2,%3};"
        : "+f"(d[0]),"+f"(d[1]),"+f"(d[2]),"+f"(d[3])
        : "r"(a[0]),"r"(a[1]),"r"(a[2]),"r"(a[3]), "r"(b0),"r"(b1));
}

// ===================== device scratch =====================
__device__ __half g_h1 [(size_t)BB*CC*NN];      // gelu(fc1(bn(x)))  [b][c][n] fp16
__device__ __half g_h2t[(size_t)BB*NN*CC];      // dwconv out, transposed [b][n][c] fp16
__device__ __half g_xth[(size_t)BB*NN*CC];      // [b][n][c] fp16 hi of x
__device__ __half g_xtl[(size_t)BB*NN*CC];      // [b][n][c] fp16 lo of x
__device__ float g_scores[BB*NN];
__device__ float g_scores_p[(size_t)BB*CTIL*NN];
__device__ float g_sumx_p [(size_t)BB*NTIL*CC];
__device__ float g_sumx2_p[(size_t)BB*NTIL*CC];
__device__ float g_sumx [BB*CC];
__device__ float g_sumx2[BB*CC];
__device__ int   g_topidx[BB*TOPK];
__device__ float g_qkv    [(size_t)MTOK*3*CC];
__device__ float g_attnout[MTOK*CC];
__device__ float g_ptok   [MTOK*CC];
__device__ __half g_W1h[CC*CC];                 // fc1 (BN-folded), x64, fp16
__device__ __half g_W2h[CC*CC];                 // proj@fc2, x64, fp16
__device__ __half g_tokh[MTOK*CC], g_tokl[MTOK*CC];
__device__ __half g_aoh [MTOK*CC], g_aol [MTOK*CC];
__device__ __half g_qw16[3*CC*CC];              // qkv_w x64 fp16
__device__ __half g_pw16[CC*CC];                // proj_w x64 fp16
__device__ float g_b1[CC];
__device__ float g_b2[CC];

__device__ __forceinline__ float gelu_exact(float v){
    return 0.5f * v * (1.0f + erff(v * 0.70710678118654752440f));
}
__device__ __forceinline__ void split_fp16(float v, __half& h, __half& l){
    h = __float2half_rn(v);
    l = __float2half_rn(v - __half2float(h));
}
__device__ __forceinline__ void split_pack2h(float v0, float v1, uint32_t& ph, uint32_t& pl){
    __half h0, l0, h1, l1;
    split_fp16(v0, h0, l0);
    split_fp16(v1, h1, l1);
    ph = (uint32_t)__half_as_ushort(h0) | ((uint32_t)__half_as_ushort(h1) << 16);
    pl = (uint32_t)__half_as_ushort(l0) | ((uint32_t)__half_as_ushort(l1) << 16);
}

// ======= fused pass over x: transpose + fp16 split AND partial stats =======
__global__ void k_xpass(const float* __restrict__ src,
                        __half* __restrict__ dh, __half* __restrict__ dl){
    __shared__ float sm[64][65];
    int b = blockIdx.z;
    int nx = blockIdx.x, cy = blockIdx.y;
    int n0 = nx * 64, c0 = cy * 64;
    const float* sp = src + (size_t)b * CC * NN;
    int t = threadIdx.x;
    #pragma unroll
    for (int p = 0; p < 4; p++){
        int row = (t >> 4) + p * 16;
        int col = (t & 15) * 4;
        float4 v = *(const float4*)&sp[(size_t)(c0 + row) * NN + n0 + col];
        sm[row][col+0] = v.x; sm[row][col+1] = v.y;
        sm[row][col+2] = v.z; sm[row][col+3] = v.w;
        float rs  = v.x + v.y + v.z + v.w;
        float rs2 = v.x*v.x + v.y*v.y + v.z*v.z + v.w*v.w;
        #pragma unroll
        for (int o = 8; o; o >>= 1){
            rs  += __shfl_down_sync(~0u, rs , o, 16);
            rs2 += __shfl_down_sync(~0u, rs2, o, 16);
        }
        if ((t & 15) == 0){
            size_t idx = ((size_t)b * NTIL + nx) * CC + c0 + row;
            g_sumx_p [idx] = rs;
            g_sumx2_p[idx] = rs2;
        }
    }
    __syncthreads();
    uint32_t* dh32 = (uint32_t*)(dh + (size_t)b * NN * CC);
    uint32_t* dl32 = (uint32_t*)(dl + (size_t)b * NN * CC);
    #pragma unroll
    for (int p = 0; p < 8; p++){
        int nr = (t >> 5) + p * 8;
        int cu = t & 31;
        float v0 = sm[2*cu][nr], v1 = sm[2*cu+1][nr];
        uint32_t ph, pl;
        split_pack2h(v0, v1, ph, pl);
        size_t o = ((size_t)(n0 + nr) * CC + c0) / 2 + cu;
        dh32[o] = ph; dl32[o] = pl;
        float sc = v0*v0 + v1*v1;
        #pragma unroll
        for (int of = 16; of; of >>= 1) sc += __shfl_down_sync(~0u, sc, of);
        if (cu == 0) g_scores_p[((size_t)b * CTIL + cy) * NN + n0 + nr] = sc;
    }
}

__global__ void k_redstats(){
    int i = blockIdx.x * 256 + threadIdx.x;
    if (i >= BB*CC) return;
    int b = i / CC, c = i % CC;
    float s = 0.f, s2 = 0.f;
    #pragma unroll 7
    for (int k = 0; k < NTIL; k++){
        size_t idx = ((size_t)b * NTIL + k) * CC + c;
        s += g_sumx_p[idx]; s2 += g_sumx2_p[idx];
    }
    g_sumx[i] = s; g_sumx2[i] = s2;
}
__global__ void k_scores_red(){
    int i = blockIdx.x * 256 + threadIdx.x;
    if (i >= BB*NN) return;
    int b = i / NN, n = i % NN;
    float s = 0.f;
    #pragma unroll
    for (int k = 0; k < CTIL; k++)
        s += g_scores_p[((size_t)b * CTIL + k) * NN + n];
    g_scores[i] = s;
}

// ===================== prep kernels =====================
__global__ void k_prepW1(const float* __restrict__ fc1_w, const float* __restrict__ fc1_b,
                         const float* __restrict__ bn_g, const float* __restrict__ bn_b){
    int o = blockIdx.x, c = threadIdx.x;
    float s = 0.f, s2 = 0.f;
    #pragma unroll 8
    for (int bb2 = 0; bb2 < BB; bb2++){ s += g_sumx[bb2*CC + c]; s2 += g_sumx2[bb2*CC + c]; }
    float inv = 1.f / ((float)BB * (float)NN);
    float mu  = s * inv;
    float var = s2 * inv - mu * mu;
    float a   = bn_g[c] * rsqrtf(var + EPSB);
    float bnC = bn_b[c] - mu * a;
    float w = fc1_w[o*CC + c];
    g_W1h[o*CC + c] = __float2half_rn(w * a * WSCALE);
    __shared__ float red[CC];
    red[c] = w * bnC;
    __syncthreads();
    for (int sft = 256; sft > 0; sft >>= 1){
        if (c < sft && c + sft < CC) red[c] += red[c + sft];
        __syncthreads();
    }
    if (c == 0) g_b1[o] = fc1_b[o] + red[0];
}

__global__ void k_prepW2(const float* __restrict__ proj_w, const float* __restrict__ fc2_w,
                         const float* __restrict__ fc2_b, const float* __restrict__ proj_b){
    int o = blockIdx.x, c = threadIdx.x;
    const float* pr = proj_w + o*CC;
    float acc = 0.f;
    for (int k = 0; k < CC; k++)
        acc = fmaf(pr[k], fc2_w[k*CC + c], acc);
    g_W2h[o*CC + c] = __float2half_rn(acc * WSCALE);
    __shared__ float red[CC];
    red[c] = pr[c] * fc2_b[c];
    __syncthreads();
    for (int s = 256; s > 0; s >>= 1){
        if (c < s && c + s < CC) red[c] += red[c + s];
        __syncthreads();
    }
    if (c == 0) g_b2[o] = proj_b[o] + red[0];
}

__global__ void k_prep_w16(const float* __restrict__ src, __half* __restrict__ dst, int n){
    int i = blockIdx.x * 256 + threadIdx.x;
    if (i < n) dst[i] = __float2half_rn(src[i] * WSCALE);
}

__global__ void k_split_rows(const float* __restrict__ src, __half* __restrict__ dh,
                             __half* __restrict__ dl, int n){
    int i = blockIdx.x * 256 + threadIdx.x;
    if (i < n){
        __half h, l; split_fp16(src[i], h, l);
        dh[i] = h; dl[i] = l;
    }
}

// ===================== radix-select topk (scores >= 0 -> bits monotonic) ===============
__global__ void k_topk(){
    int b = blockIdx.x, tid = threadIdx.x;
    const float* sc = g_scores + b*NN;
    __shared__ uint32_t hist[256];
    __shared__ uint32_t s_prefix, s_k;
    __shared__ int s_cnt, s_neq;
    __shared__ int eqidx[128];
    if (tid == 0){ s_prefix = 0u; s_k = TOPK; }
    __syncthreads();
    #pragma unroll 1
    for (int pass = 0; pass < 4; pass++){
        int shift = 24 - pass*8;
        uint32_t pmask = (pass == 0) ? 0u : (0xFFFFFFFFu << (shift + 8));
        for (int i = tid; i < 256; i += 256) hist[i] = 0;
        __syncthreads();
        uint32_t pref = s_prefix;
        for (int n = tid; n < NN; n += 256){
            uint32_t v = __float_as_uint(sc[n]);
            if ((v & pmask) == pref) atomicAdd(&hist[(v >> shift) & 255], 1);
        }
        __syncthreads();
        if (tid == 0){
            uint32_t k = s_k, cum = 0; int Bn = 0;
            for (int bn = 255; bn >= 0; bn--){
                if (cum + hist[bn] >= k){ Bn = bn; break; }
                cum += hist[bn];
            }
            s_k = k - cum;
            s_prefix = pref | ((uint32_t)Bn << shift);
        }
        __syncthreads();
    }
    if (tid == 0){ s_cnt = 0; s_neq = 0; }
    __syncthreads();
    float thrf = __uint_as_float(s_prefix);
    for (int n = tid; n < NN; n += 256){
        float v = sc[n];
        if (v > thrf){
            int p = atomicAdd(&s_cnt, 1);
            g_topidx[b*TOPK + p] = n;
        } else if (v == thrf){
            int p = atomicAdd(&s_neq, 1);
            if (p < 128) eqidx[p] = n;
        }
    }
    __syncthreads();
    if (tid == 0){
        int have = s_cnt;
        int need = TOPK - have;
        int ne = s_neq < 128 ? s_neq : 128;
        for (int t = 0; t < need; t++){
            int best = 1 << 30, bi = 0;
            for (int i = 0; i < ne; i++)
                if (eqidx[i] < best){ best = eqidx[i]; bi = i; }
            g_topidx[b*TOPK + have + t] = best;
            eqidx[bi] = 1 << 30;
        }
    }
}

// coalesced token gather from the transposed split planes
__global__ void k_gather_tok(const __half* __restrict__ xth,
                             const __half* __restrict__ xtl){
    int j = blockIdx.x, b = blockIdx.y;
    int t = threadIdx.x;                     // 192 threads, 1 uint32 each
    int idx = g_topidx[b*TOPK + j];
    const uint32_t* sh = (const uint32_t*)(xth + ((size_t)b*NN + idx)*CC);
    const uint32_t* sl = (const uint32_t*)(xtl + ((size_t)b*NN + idx)*CC);
    uint32_t* dh = (uint32_t*)(g_tokh + ((size_t)b*NTOK + j)*CC);
    uint32_t* dl = (uint32_t*)(g_tokl + ((size_t)b*NTOK + j)*CC);
    dh[t] = sh[t];
    dl[t] = sl[t];
}

// bg token
__global__ void k_bgtok(){
    int b = blockIdx.x, c = threadIdx.x;
    const __half* th = g_tokh + (size_t)b*NTOK*CC + c;
    const __half* tl = g_tokl + (size_t)b*NTOK*CC + c;
    float s = 0.f;
    #pragma unroll 7
    for (int j = 0; j < TOPK; j++)
        s += __half2float(th[(size_t)j*CC]) + __half2float(tl[(size_t)j*CC]);
    float bg = (g_sumx[b*CC + c] - s) * (1.f / (float)(NN - TOPK));
    __half h, l; split_fp16(bg, h, l);
    g_tokh[((size_t)b*NTOK + TOPK)*CC + c] = h;
    g_tokl[((size_t)b*NTOK + TOPK)*CC + c] = l;
}

// ===================== attention over 99 tokens =====================
__global__ void k_attention(){
    int b = blockIdx.x / NHEAD, h = blockIdx.x % NHEAD;
    __shared__ float Ks[NTOK][HDIM];
    __shared__ float Vs[NTOK][HDIM];
    __shared__ float Qs[4][HDIM];
    __shared__ float Ps[4][NTOK];
    int tid = threadIdx.x;
    const float* qkvb = g_qkv + (size_t)b * NTOK * 3 * CC;
    for (int i = tid; i < NTOK*HDIM; i += blockDim.x){
        int t = i / HDIM, d = i % HDIM;
        Ks[t][d] = qkvb[(size_t)t*3*CC +   CC + h*HDIM + d];
        Vs[t][d] = qkvb[(size_t)t*3*CC + 2*CC + h*HDIM + d];
    }
    __syncthreads();
    int w = tid >> 5, lane = tid & 31;
    const float scale = rsqrtf((float)HDIM);
    for (int t = w; t < NTOK; t += 4){
        const float* qp = qkvb + (size_t)t*3*CC + h*HDIM;
        Qs[w][lane] = qp[lane];
        if (lane < HDIM - 32) Qs[w][lane + 32] = qp[lane + 32];
        __syncwarp();
        float sc[4]; float mx = -FLT_MAX;
        #pragma unroll
        for (int r = 0; r < 4; r++){
            int m = lane + r*32;
            float s = -FLT_MAX;
            if (m < NTOK){
                s = 0.f;
                #pragma unroll
                for (int d = 0; d < HDIM; d++) s = fmaf(Qs[w][d], Ks[m][d], s);
                s *= scale;
            }
            sc[r] = s; mx = fmaxf(mx, s);
        }
        for (int o = 16; o; o >>= 1) mx = fmaxf(mx, __shfl_xor_sync(~0u, mx, o));
        float sum = 0.f;
        #pragma unroll
        for (int r = 0; r < 4; r++){
            int m = lane + r*32;
            float e = (m < NTOK) ? expf(sc[r] - mx) : 0.f;
            sc[r] = e; sum += e;
        }
        for (int o = 16; o; o >>= 1) sum += __shfl_xor_sync(~0u, sum, o);
        float inv = 1.f / sum;
        #pragma unroll
        for (int r = 0; r < 4; r++){
            int m = lane + r*32;
            if (m < NTOK) Ps[w][m] = sc[r] * inv;
        }
        __syncwarp();
        for (int d = lane; d < HDIM; d += 32){
            float o = 0.f;
            for (int m = 0; m < NTOK; m++) o = fmaf(Ps[w][m], Vs[m][d], o);
            g_attnout[((size_t)b*NTOK + t)*CC + h*HDIM + d] = o;
        }
        __syncwarp();
    }
}

// ===================== depthwise 3x3 (fp16 in) + transpose + fp16 store ==========
__global__ void k_dwconv_t(const float* __restrict__ dw_w, const float* __restrict__ dw_b,
                           __half* __restrict__ dh){
    __shared__ float t[32][33];
    int b = blockIdx.z, c0 = blockIdx.y * 32, n0 = blockIdx.x * 32;
    int tid = threadIdx.y * 32 + threadIdx.x;
    for (int r = threadIdx.y; r < 32; r += 8){
        int c = c0 + r;
        int n = n0 + threadIdx.x;
        const __half* src = g_h1 + ((size_t)b * CC + c) * NN;
        int y = n / WW, xp = n % WW;
        const float* w = dw_w + c * 9;
        float acc = dw_b[c];
        #pragma unroll
        for (int dy = -1; dy <= 1; dy++){
            int yy = y + dy;
            if (yy < 0 || yy >= HH) continue;
            #pragma unroll
            for (int dx = -1; dx <= 1; dx++){
                int xw = xp + dx;
                if (xw < 0 || xw >= WW) continue;
                acc = fmaf(__half2float(src[yy*WW + xw]), w[(dy+1)*3 + (dx+1)], acc);
            }
        }
        t[r][threadIdx.x] = acc;
    }
    __syncthreads();
    uint32_t* dh32 = (uint32_t*)(dh + (size_t)b * NN * CC);
    for (int idx = tid; idx < 32 * 16; idx += 256){
        int nr = idx >> 4, cu = idx & 15;
        uint32_t ph = (uint32_t)__half_as_ushort(__float2half_rn(t[2*cu][nr]))
                    | ((uint32_t)__half_as_ushort(__float2half_rn(t[2*cu+1][nr])) << 16);
        size_t o = ((size_t)(n0 + nr) * CC + c0) / 2 + cu;
        dh32[o] = ph;
    }
}

// ====== warp-mma fp16 GEMM (128x128 tile, 128 threads, 4 warps 2x2) ====
// NPROD=1: D = Ah*Bh^T.  NPROD=2: D = (Ah+Al)*Bh^T.  fp32 accum, one operand x64.
// MODE 0: h1(fp16) = gelu(acc/64 + b1[m]);  MODE 1: out(fp32) = acc/64 + b2[m] + ptok_bg
// MODE 2: qkv = acc/64 + qkv_b[n];          MODE 3: ptok = acc/64
#define LDS_B 80
#define EPITCH 132
#define MM_SMEM (128*EPITCH*4)       // 67584 B; covers 2 stages of both variants
#define JSTRIDE (32*CC*2)

template<int MODE, int NPROD>
__global__ void __launch_bounds__(128)
k_mm(const __half* __restrict__ Aph, const __half* __restrict__ Apl,
     const __half* __restrict__ Bh_,
     float* __restrict__ Out, const float* __restrict__ bias,
     int Mrows, int Nrows){
    constexpr int AR   = 128 * NPROD;          // A rows per stage
    constexpr int STGB = (AR + 128) * LDS_B;   // stage bytes
    extern __shared__ char smem[];
    uint32_t sb = smem_to_u32(smem);
    int tid = threadIdx.x, wid = tid >> 5, lane = tid & 31;
    int m0 = blockIdx.x * 128, n0 = blockIdx.y * 128;
    int b = blockIdx.z;
    const __half* Bph = Bh_;
    if (MODE <= 1) Bph += (size_t)b * NN * CC;

    int r0 = tid >> 2, cu4 = tid & 3;
    const char* fAh = (const char*)Aph + ((size_t)(m0 + r0) * CC) * 2 + cu4 * 16;
    const char* fAl = (NPROD == 2)
        ? (const char*)Apl + ((size_t)(m0 + r0) * CC) * 2 + cu4 * 16 : (const char*)0;
    const char* fBh = (const char*)Bph + ((size_t)(n0 + r0) * CC) * 2 + cu4 * 16;
    uint32_t d0 = (uint32_t)(r0 * LDS_B + cu4 * 16);
    bool fast = (m0 + 128 <= Mrows) && (n0 + 128 <= Nrows);

    #define LOADC_F(ch, st) do {                                                  \
        uint32_t s0w = sb + (st) * STGB;                                          \
        int kb = (ch) * 64;                                                       \
        _Pragma("unroll")                                                         \
        for (int q = 0; q < 4; q++){                                              \
            CP_ASYNC16(s0w + d0 + q*(32*LDS_B),            fAh + kb + q*JSTRIDE, 16); \
            if (NPROD == 2)                                                       \
                CP_ASYNC16(s0w + d0 + q*(32*LDS_B) + 128*LDS_B, fAl + kb + q*JSTRIDE, 16); \
            CP_ASYNC16(s0w + d0 + q*(32*LDS_B) + AR*LDS_B, fBh + kb + q*JSTRIDE, 16); \
        }                                                                         \
        CP_ASYNC_COMMIT();                                                        \
    } while(0)

    #define LOADC_S(ch, st) do {                                                  \
        int k0 = (ch) * 32;                                                       \
        uint32_t s0w = sb + (st) * STGB;                                          \
        _Pragma("unroll")                                                         \
        for (int i = tid; i < (AR + 128) * 4; i += 128){                          \
            int r = i >> 2, cu = i & 3;                                           \
            uint32_t dst = s0w + (uint32_t)(r * LDS_B + cu * 16);                 \
            const char* src; uint32_t sz;                                         \
            if (r < AR){                                                          \
                int rr = r & 127;                                                 \
                int gm = m0 + rr;                                                 \
                sz = (gm < Mrows) ? 16u : 0u;                                     \
                int gmc = (gm < Mrows) ? gm : 0;                                  \
                const __half* base = (r < 128) ? Aph : Apl;                       \
                src = (const char*)(base + (size_t)gmc*CC + k0) + cu*16;          \
            } else {                                                              \
                int rr = (r - AR) & 127;                                          \
                int gn = n0 + rr;                                                 \
                sz = (gn < Nrows) ? 16u : 0u;                                     \
                int gnc = (gn < Nrows) ? gn : 0;                                  \
                src = (const char*)(Bph + (size_t)gnc*CC + k0) + cu*16;           \
            }                                                                     \
            CP_ASYNC16(dst, src, sz);                                             \
        }                                                                         \
        CP_ASYNC_COMMIT();                                                        \
    } while(0)

    float acc[4][8][4] = {};
    if (fast){ LOADC_F(0, 0); LOADC_F(1, 1); }
    else     { LOADC_S(0, 0); LOADC_S(1, 1); }

    int wm = (wid >> 1) * 64, wn = (wid & 1) * 64;
    uint32_t a_off = (uint32_t)(wm + (lane & 15)) * LDS_B + ((lane >> 4) & 1) * 16;
    uint32_t b_off = (uint32_t)(wn + (lane & 7) + ((lane >> 4) & 1) * 8) * LDS_B
                   + ((lane >> 3) & 1) * 16;

    #pragma unroll 1
    for (int c = 0; c < 12; c++){
        CP_ASYNC_WAIT(1);
        __syncthreads();
        uint32_t s0 = sb + (c & 1) * STGB;
        #pragma unroll
        for (int kk = 0; kk < 2; kk++){
            uint32_t ah[4][4], al[4][4];
            #pragma unroll
            for (int i = 0; i < 4; i++){
                uint32_t ra = s0 + a_off + (uint32_t)(i * 16 * LDS_B) + kk * 32;
                ldsm_x4(ah[i], ra);
                if (NPROD == 2) ldsm_x4(al[i], ra + 128 * LDS_B);
            }
            #pragma unroll
            for (int j = 0; j < 4; j++){
                uint32_t bh[4];
                uint32_t rb = s0 + AR * LDS_B + b_off + (uint32_t)(j * 16 * LDS_B) + kk * 32;
                ldsm_x4(bh, rb);
                #pragma unroll
                for (int i = 0; i < 4; i++) mma16816h(acc[i][j*2+0], ah[i], bh[0], bh[1]);
                #pragma unroll
                for (int i = 0; i < 4; i++) mma16816h(acc[i][j*2+1], ah[i], bh[2], bh[3]);
                if (NPROD == 2){
                    #pragma unroll
                    for (int i = 0; i < 4; i++) mma16816h(acc[i][j*2+0], al[i], bh[0], bh[1]);
                    #pragma unroll
                    for (int i = 0; i < 4; i++) mma16816h(acc[i][j*2+1], al[i], bh[2], bh[3]);
                }
            }
        }
        __syncthreads();
        if (c + 2 < 12){
            if (fast) LOADC_F(c + 2, c & 1);
            else      LOADC_S(c + 2, c & 1);
        } else CP_ASYNC_COMMIT();
    }
    CP_ASYNC_WAIT(0);
    __syncthreads();

    // ---- stage accumulators in smem, then coalesced stores ----
    float* eps = (float*)smem;
    int rbase = wm + (lane >> 2);
    int cbase = wn + (lane & 3) * 2;
    #pragma unroll
    for (int i = 0; i < 4; i++)
        #pragma unroll
        for (int half = 0; half < 2; half++){
            int ml = rbase + i * 16 + half * 8;
            #pragma unroll
            for (int j = 0; j < 8; j++){
                int nl = cbase + j * 8;
                eps[ml * EPITCH + nl    ] = acc[i][j][half*2+0];
                eps[ml * EPITCH + nl + 1] = acc[i][j][half*2+1];
            }
        }
    __syncthreads();
    for (int idx = tid; idx < 128 * 32; idx += 128){
        int ml = idx >> 5, nl = (idx & 31) * 4;
        float4 v = *(const float4*)&eps[ml * EPITCH + nl];
        int m = m0 + ml, n = n0 + nl;
        v.x *= INVWSC; v.y *= INVWSC; v.z *= INVWSC; v.w *= INVWSC;
        if (MODE == 0){
            if (n >= Nrows) continue;
            float bs = bias[m];
            v.x = gelu_exact(v.x + bs); v.y = gelu_exact(v.y + bs);
            v.z = gelu_exact(v.z + bs); v.w = gelu_exact(v.w + bs);
            __half* hp = (__half*)Out + ((size_t)b*CC + m)*NN + n;
            *(__half2*)(hp    ) = __floats2half2_rn(v.x, v.y);
            *(__half2*)(hp + 2) = __floats2half2_rn(v.z, v.w);
        } else if (MODE == 1){
            if (n >= Nrows) continue;
            float bs = bias[m] + g_ptok[((size_t)b*NTOK + TOPK)*CC + m];
            v.x += bs; v.y += bs; v.z += bs; v.w += bs;
            *(float4*)&Out[((size_t)b*CC + m)*NN + n] = v;
        } else {
            if (m >= Mrows || n >= Nrows) continue;
            if (MODE == 2){
                v.x += bias[n]; v.y += bias[n+1]; v.z += bias[n+2]; v.w += bias[n+3];
            }
            *(float4*)&Out[(size_t)m * (MODE == 2 ? 3*CC : CC) + n] = v;
        }
    }
    #undef LOADC_F
    #undef LOADC_S
}

// ===================== scatter projected top tokens =====================
__global__ void k_scatter(float* __restrict__ out){
    int b = blockIdx.x / TOPK, j = blockIdx.x % TOPK;
    int o = threadIdx.x;
    int n = g_topidx[b*TOPK + j];
    float d = g_ptok[((size_t)b*NTOK + j   )*CC + o]
            - g_ptok[((size_t)b*NTOK + TOPK)*CC + o];
    out[((size_t)b*CC + o)*NN + n] += d;
}

// ===================== host launch =====================
extern "C" void kernel_launch(void* const* d_in, const int* in_sizes, int n_in,
                              void* d_out, int out_size){
    const float* x      = (const float*)d_in[0];
    const float* qkv_w  = (const float*)d_in[1];
    const float* qkv_b  = (const float*)d_in[2];
    const float* proj_w = (const float*)d_in[3];
    const float* proj_b = (const float*)d_in[4];
    const float* bn_g   = (const float*)d_in[5];
    const float* bn_b   = (const float*)d_in[6];
    const float* fc1_w  = (const float*)d_in[7];
    const float* fc1_b  = (const float*)d_in[8];
    const float* fc2_w  = (const float*)d_in[9];
    const float* fc2_b  = (const float*)d_in[10];
    const float* dw_w   = (const float*)d_in[11];
    const float* dw_b   = (const float*)d_in[12];
    float* out = (float*)d_out;

    float *p_qkv, *p_attnout, *p_ptok, *p_b1, *p_b2;
    __half *p_h1, *p_h2t, *p_W1h, *p_W2h, *p_xth, *p_xtl;
    __half *p_tokh, *p_tokl, *p_aoh, *p_aol, *p_qw16, *p_pw16;
    cudaGetSymbolAddress((void**)&p_qkv    , g_qkv);
    cudaGetSymbolAddress((void**)&p_attnout, g_attnout);
    cudaGetSymbolAddress((void**)&p_ptok   , g_ptok);
    cudaGetSymbolAddress((void**)&p_b1     , g_b1);
    cudaGetSymbolAddress((void**)&p_b2     , g_b2);
    cudaGetSymbolAddress((void**)&p_h1     , g_h1);
    cudaGetSymbolAddress((void**)&p_h2t    , g_h2t);
    cudaGetSymbolAddress((void**)&p_W1h    , g_W1h);
    cudaGetSymbolAddress((void**)&p_W2h    , g_W2h);
    cudaGetSymbolAddress((void**)&p_xth    , g_xth);
    cudaGetSymbolAddress((void**)&p_xtl    , g_xtl);
    cudaGetSymbolAddress((void**)&p_tokh   , g_tokh);
    cudaGetSymbolAddress((void**)&p_tokl   , g_tokl);
    cudaGetSymbolAddress((void**)&p_aoh    , g_aoh);
    cudaGetSymbolAddress((void**)&p_aol    , g_aol);
    cudaGetSymbolAddress((void**)&p_qw16   , g_qw16);
    cudaGetSymbolAddress((void**)&p_pw16   , g_pw16);

    cudaFuncSetAttribute((const void*)k_mm<0,1>, cudaFuncAttributeMaxDynamicSharedMemorySize, MM_SMEM);
    cudaFuncSetAttribute((const void*)k_mm<1,1>, cudaFuncAttributeMaxDynamicSharedMemorySize, MM_SMEM);
    cudaFuncSetAttribute((const void*)k_mm<2,2>, cudaFuncAttributeMaxDynamicSharedMemorySize, MM_SMEM);
    cudaFuncSetAttribute((const void*)k_mm<3,2>, cudaFuncAttributeMaxDynamicSharedMemorySize, MM_SMEM);

    cudaStream_t s2;
    cudaStreamCreateWithFlags(&s2, cudaStreamNonBlocking);
    cudaEvent_t evF, evJ;
    cudaEventCreateWithFlags(&evF, cudaEventDisableTiming);
    cudaEventCreateWithFlags(&evJ, cudaEventDisableTiming);

    // ---- stream 0: conv-mixer chain ----
    k_xpass   <<<dim3(NTIL, CTIL, BB), 256>>>(x, p_xth, p_xtl);
    k_redstats<<<(BB*CC + 255)/256, 256>>>();
    cudaEventRecord(evF, 0);
    cudaStreamWaitEvent(s2, evF, 0);
    k_prepW1  <<<CC, CC>>>(fc1_w, fc1_b, bn_g, bn_b);
    dim3 gbig(CC/128, (NN + 127)/128, BB);
    k_mm<0,1><<<gbig, 128, MM_SMEM>>>(p_W1h, (const __half*)nullptr, p_xth,
                                      (float*)p_h1, p_b1, CC, NN);
    k_dwconv_t<<<dim3(NN/32, CC/32, BB), dim3(32, 8)>>>(dw_w, dw_b, p_h2t);

    // ---- stream s2: salience branch (overlaps with k_mm<0> + dwconv) ----
    k_scores_red<<<(BB*NN + 255)/256, 256, 0, s2>>>();
    k_prepW2  <<<CC, CC, 0, s2>>>(proj_w, fc2_w, fc2_b, proj_b);
    k_prep_w16<<<(3*CC*CC + 255)/256, 256, 0, s2>>>(qkv_w,  p_qw16, 3*CC*CC);
    k_prep_w16<<<(CC*CC   + 255)/256, 256, 0, s2>>>(proj_w, p_pw16, CC*CC);
    k_topk      <<<BB, 256, 0, s2>>>();
    k_gather_tok<<<dim3(TOPK, BB), 192, 0, s2>>>(p_xth, p_xtl);
    k_bgtok     <<<BB, CC, 0, s2>>>();
    k_mm<2,2><<<dim3((MTOK + 127)/128, (3*CC + 127)/128, 1), 128, MM_SMEM, s2>>>(
        p_tokh, p_tokl, p_qw16, p_qkv, qkv_b, MTOK, 3*CC);
    k_attention <<<BB*NHEAD, 128, 0, s2>>>();
    k_split_rows<<<(MTOK*CC + 255)/256, 256, 0, s2>>>(p_attnout, p_aoh, p_aol, MTOK*CC);
    k_mm<3,2><<<dim3((MTOK + 127)/128, CC/128, 1), 128, MM_SMEM, s2>>>(
        p_aoh, p_aol, p_pw16, p_ptok, (const float*)nullptr, MTOK, CC);
    cudaEventRecord(evJ, s2);
    cudaStreamWaitEvent(0, evJ, 0);

    // ---- stream 0: final GEMM + scatter ----
    k_mm<1,1><<<gbig, 128, MM_SMEM>>>(p_W2h, (const __half*)nullptr, p_h2t, out, p_b2, CC, NN);
    k_scatter<<<BB*TOPK, CC>>>(out);
}

// round 17
// speedup vs baseline: 1.5809x; 1.0237x over previous
#include <cuda_runtime.h>
#include <cuda_fp16.h>
#include <math.h>
#include <float.h>
#include <stdint.h>

#define BB    32
#define CC    384
#define HH    56
#define WW    56
#define NN    3136
#define TOPK  98
#define NTOK  99
#define NHEAD 8
#define HDIM  48
#define EPSB  1e-5f
#define MTOK  (BB*NTOK)   // 3168 tokens
#define NTIL  (NN/64)     // 49
#define CTIL  (CC/64)     // 6
#define WSCALE   64.0f
#define INVWSC   0.015625f

// ===================== PTX helpers (sm_80-era, legal at compute_103) =====================
__device__ __forceinline__ uint32_t smem_to_u32(const void* smem_ptr) {
    uint32_t addr;
    asm("{ .reg .u64 tmp; cvta.to.shared.u64 tmp, %1; cvt.u32.u64 %0, tmp; }"
        : "=r"(addr) : "l"(smem_ptr));
    return addr;
}
#define CP_ASYNC16(dst, src, sz) \
    asm volatile("cp.async.cg.shared.global [%0], [%1], 16, %2;" \
        :: "r"((uint32_t)(dst)), "l"(src), "r"((uint32_t)(sz)) : "memory")
#define CP_ASYNC_COMMIT() asm volatile("cp.async.commit_group;" ::: "memory")
#define CP_ASYNC_WAIT(n)  asm volatile("cp.async.wait_group %0;" :: "n"(n) : "memory")

__device__ __forceinline__ void ldsm_x4(uint32_t (&r)[4], uint32_t addr){
    asm volatile("ldmatrix.sync.aligned.m8n8.x4.shared.b16 {%0,%1,%2,%3}, [%4];"
        : "=r"(r[0]),"=r"(r[1]),"=r"(r[2]),"=r"(r[3]) : "r"(addr));
}
__device__ __forceinline__ void mma16816h(float (&d)[4], const uint32_t (&a)[4],
                                          uint32_t b0, uint32_t b1){
    asm volatile("mma.sync.aligned.m16n8k16.row.col.f32.f16.f16.f32 "
        "{%0,%1,%2,%3}, {%4,%5,%6,%7}, {%8,%9}, {%0,%1,%2,%3};"
        : "+f"(d[0]),"+f"(d[1]),"+f"(d[2]),"+f"(d[3])
        : "r"(a[0]),"r"(a[1]),"r"(a[2]),"r"(a[3]), "r"(b0),"r"(b1));
}

// ===================== device scratch =====================
__device__ __half g_h1 [(size_t)BB*CC*NN];      // gelu(fc1(bn(x)))  [b][c][n] fp16
__device__ __half g_h2t[(size_t)BB*NN*CC];      // dwconv out, transposed [b][n][c] fp16
__device__ __half g_xth[(size_t)BB*NN*CC];      // [b][n][c] fp16 of x
__device__ float g_scores[BB*NN];
__device__ float g_scores_p[(size_t)BB*CTIL*NN];
__device__ float g_sumx_p [(size_t)BB*NTIL*CC];
__device__ float g_sumx2_p[(size_t)BB*NTIL*CC];
__device__ float g_sumx [BB*CC];
__device__ float g_sumx2[BB*CC];
__device__ int   g_topidx[BB*TOPK];
__device__ float g_qkv    [(size_t)MTOK*3*CC];
__device__ float g_attnout[MTOK*CC];
__device__ float g_ptok   [MTOK*CC];
__device__ __half g_W1h[CC*CC];                 // fc1 (BN-folded), x64, fp16
__device__ __half g_W2h[CC*CC];                 // proj@fc2, x64, fp16
__device__ __half g_tokh[MTOK*CC];
__device__ __half g_aoh [MTOK*CC], g_aol [MTOK*CC];
__device__ __half g_qw16[3*CC*CC];              // qkv_w x64 fp16
__device__ __half g_pw16[CC*CC];                // proj_w x64 fp16
__device__ float g_b1[CC];
__device__ float g_b2[CC];

__device__ __forceinline__ float gelu_exact(float v){
    return 0.5f * v * (1.0f + erff(v * 0.70710678118654752440f));
}
__device__ __forceinline__ void split_fp16(float v, __half& h, __half& l){
    h = __float2half_rn(v);
    l = __float2half_rn(v - __half2float(h));
}

// ======= fused pass over x: transpose + fp16 AND partial stats =======
__global__ void k_xpass(const float* __restrict__ src, __half* __restrict__ dh){
    __shared__ float sm[64][65];
    int b = blockIdx.z;
    int nx = blockIdx.x, cy = blockIdx.y;
    int n0 = nx * 64, c0 = cy * 64;
    const float* sp = src + (size_t)b * CC * NN;
    int t = threadIdx.x;
    #pragma unroll
    for (int p = 0; p < 4; p++){
        int row = (t >> 4) + p * 16;
        int col = (t & 15) * 4;
        float4 v = *(const float4*)&sp[(size_t)(c0 + row) * NN + n0 + col];
        sm[row][col+0] = v.x; sm[row][col+1] = v.y;
        sm[row][col+2] = v.z; sm[row][col+3] = v.w;
        float rs  = v.x + v.y + v.z + v.w;
        float rs2 = v.x*v.x + v.y*v.y + v.z*v.z + v.w*v.w;
        #pragma unroll
        for (int o = 8; o; o >>= 1){
            rs  += __shfl_down_sync(~0u, rs , o, 16);
            rs2 += __shfl_down_sync(~0u, rs2, o, 16);
        }
        if ((t & 15) == 0){
            size_t idx = ((size_t)b * NTIL + nx) * CC + c0 + row;
            g_sumx_p [idx] = rs;
            g_sumx2_p[idx] = rs2;
        }
    }
    __syncthreads();
    uint32_t* dh32 = (uint32_t*)(dh + (size_t)b * NN * CC);
    #pragma unroll
    for (int p = 0; p < 8; p++){
        int nr = (t >> 5) + p * 8;
        int cu = t & 31;
        float v0 = sm[2*cu][nr], v1 = sm[2*cu+1][nr];
        uint32_t ph = (uint32_t)__half_as_ushort(__float2half_rn(v0))
                    | ((uint32_t)__half_as_ushort(__float2half_rn(v1)) << 16);
        size_t o = ((size_t)(n0 + nr) * CC + c0) / 2 + cu;
        dh32[o] = ph;
        float sc = v0*v0 + v1*v1;
        #pragma unroll
        for (int of = 16; of; of >>= 1) sc += __shfl_down_sync(~0u, sc, of);
        if (cu == 0) g_scores_p[((size_t)b * CTIL + cy) * NN + n0 + nr] = sc;
    }
}

__global__ void k_redstats(){
    int i = blockIdx.x * 256 + threadIdx.x;
    if (i >= BB*CC) return;
    int b = i / CC, c = i % CC;
    float s = 0.f, s2 = 0.f;
    #pragma unroll 7
    for (int k = 0; k < NTIL; k++){
        size_t idx = ((size_t)b * NTIL + k) * CC + c;
        s += g_sumx_p[idx]; s2 += g_sumx2_p[idx];
    }
    g_sumx[i] = s; g_sumx2[i] = s2;
}
__global__ void k_scores_red(){
    int i = blockIdx.x * 256 + threadIdx.x;
    if (i >= BB*NN) return;
    int b = i / NN, n = i % NN;
    float s = 0.f;
    #pragma unroll
    for (int k = 0; k < CTIL; k++)
        s += g_scores_p[((size_t)b * CTIL + k) * NN + n];
    g_scores[i] = s;
}

// ===================== prep kernels =====================
__global__ void k_prepW1(const float* __restrict__ fc1_w, const float* __restrict__ fc1_b,
                         const float* __restrict__ bn_g, const float* __restrict__ bn_b){
    int o = blockIdx.x, c = threadIdx.x;
    float s = 0.f, s2 = 0.f;
    #pragma unroll 8
    for (int bb2 = 0; bb2 < BB; bb2++){ s += g_sumx[bb2*CC + c]; s2 += g_sumx2[bb2*CC + c]; }
    float inv = 1.f / ((float)BB * (float)NN);
    float mu  = s * inv;
    float var = s2 * inv - mu * mu;
    float a   = bn_g[c] * rsqrtf(var + EPSB);
    float bnC = bn_b[c] - mu * a;
    float w = fc1_w[o*CC + c];
    g_W1h[o*CC + c] = __float2half_rn(w * a * WSCALE);
    __shared__ float red[CC];
    red[c] = w * bnC;
    __syncthreads();
    for (int sft = 256; sft > 0; sft >>= 1){
        if (c < sft && c + sft < CC) red[c] += red[c + sft];
        __syncthreads();
    }
    if (c == 0) g_b1[o] = fc1_b[o] + red[0];
}

__global__ void k_prepW2(const float* __restrict__ proj_w, const float* __restrict__ fc2_w,
                         const float* __restrict__ fc2_b, const float* __restrict__ proj_b){
    int o = blockIdx.x, c = threadIdx.x;
    const float* pr = proj_w + o*CC;
    float acc = 0.f;
    for (int k = 0; k < CC; k++)
        acc = fmaf(pr[k], fc2_w[k*CC + c], acc);
    g_W2h[o*CC + c] = __float2half_rn(acc * WSCALE);
    __shared__ float red[CC];
    red[c] = pr[c] * fc2_b[c];
    __syncthreads();
    for (int s = 256; s > 0; s >>= 1){
        if (c < s && c + s < CC) red[c] += red[c + s];
        __syncthreads();
    }
    if (c == 0) g_b2[o] = proj_b[o] + red[0];
}

__global__ void k_prep_w16(const float* __restrict__ src, __half* __restrict__ dst, int n){
    int i = blockIdx.x * 256 + threadIdx.x;
    if (i < n) dst[i] = __float2half_rn(src[i] * WSCALE);
}

__global__ void k_split_rows(const float* __restrict__ src, __half* __restrict__ dh,
                             __half* __restrict__ dl, int n){
    int i = blockIdx.x * 256 + threadIdx.x;
    if (i < n){
        __half h, l; split_fp16(src[i], h, l);
        dh[i] = h; dl[i] = l;
    }
}

// ===================== radix-select topk (scores >= 0 -> bits monotonic) ===============
__global__ void k_topk(){
    int b = blockIdx.x, tid = threadIdx.x;
    const float* sc = g_scores + b*NN;
    __shared__ uint32_t hist[256];
    __shared__ uint32_t s_prefix, s_k;
    __shared__ int s_cnt, s_neq;
    __shared__ int eqidx[128];
    if (tid == 0){ s_prefix = 0u; s_k = TOPK; }
    __syncthreads();
    #pragma unroll 1
    for (int pass = 0; pass < 4; pass++){
        int shift = 24 - pass*8;
        uint32_t pmask = (pass == 0) ? 0u : (0xFFFFFFFFu << (shift + 8));
        for (int i = tid; i < 256; i += 256) hist[i] = 0;
        __syncthreads();
        uint32_t pref = s_prefix;
        for (int n = tid; n < NN; n += 256){
            uint32_t v = __float_as_uint(sc[n]);
            if ((v & pmask) == pref) atomicAdd(&hist[(v >> shift) & 255], 1);
        }
        __syncthreads();
        if (tid == 0){
            uint32_t k = s_k, cum = 0; int Bn = 0;
            for (int bn = 255; bn >= 0; bn--){
                if (cum + hist[bn] >= k){ Bn = bn; break; }
                cum += hist[bn];
            }
            s_k = k - cum;
            s_prefix = pref | ((uint32_t)Bn << shift);
        }
        __syncthreads();
    }
    if (tid == 0){ s_cnt = 0; s_neq = 0; }
    __syncthreads();
    float thrf = __uint_as_float(s_prefix);
    for (int n = tid; n < NN; n += 256){
        float v = sc[n];
        if (v > thrf){
            int p = atomicAdd(&s_cnt, 1);
            g_topidx[b*TOPK + p] = n;
        } else if (v == thrf){
            int p = atomicAdd(&s_neq, 1);
            if (p < 128) eqidx[p] = n;
        }
    }
    __syncthreads();
    if (tid == 0){
        int have = s_cnt;
        int need = TOPK - have;
        int ne = s_neq < 128 ? s_neq : 128;
        for (int t = 0; t < need; t++){
            int best = 1 << 30, bi = 0;
            for (int i = 0; i < ne; i++)
                if (eqidx[i] < best){ best = eqidx[i]; bi = i; }
            g_topidx[b*TOPK + have + t] = best;
            eqidx[bi] = 1 << 30;
        }
    }
}

// coalesced token gather from the transposed fp16 plane
__global__ void k_gather_tok(const __half* __restrict__ xth){
    int j = blockIdx.x, b = blockIdx.y;
    int t = threadIdx.x;                     // 192 threads, 1 uint32 each
    int idx = g_topidx[b*TOPK + j];
    const uint32_t* sh = (const uint32_t*)(xth + ((size_t)b*NN + idx)*CC);
    uint32_t* dh = (uint32_t*)(g_tokh + ((size_t)b*NTOK + j)*CC);
    dh[t] = sh[t];
}

// bg token
__global__ void k_bgtok(){
    int b = blockIdx.x, c = threadIdx.x;
    const __half* th = g_tokh + (size_t)b*NTOK*CC + c;
    float s = 0.f;
    #pragma unroll 7
    for (int j = 0; j < TOPK; j++)
        s += __half2float(th[(size_t)j*CC]);
    float bg = (g_sumx[b*CC + c] - s) * (1.f / (float)(NN - TOPK));
    g_tokh[((size_t)b*NTOK + TOPK)*CC + c] = __float2half_rn(bg);
}

// ===================== attention over 99 tokens =====================
__global__ void k_attention(){
    int b = blockIdx.x / NHEAD, h = blockIdx.x % NHEAD;
    __shared__ float Ks[NTOK][HDIM];
    __shared__ float Vs[NTOK][HDIM];
    __shared__ float Qs[4][HDIM];
    __shared__ float Ps[4][NTOK];
    int tid = threadIdx.x;
    const float* qkvb = g_qkv + (size_t)b * NTOK * 3 * CC;
    for (int i = tid; i < NTOK*HDIM; i += blockDim.x){
        int t = i / HDIM, d = i % HDIM;
        Ks[t][d] = qkvb[(size_t)t*3*CC +   CC + h*HDIM + d];
        Vs[t][d] = qkvb[(size_t)t*3*CC + 2*CC + h*HDIM + d];
    }
    __syncthreads();
    int w = tid >> 5, lane = tid & 31;
    const float scale = rsqrtf((float)HDIM);
    for (int t = w; t < NTOK; t += 4){
        const float* qp = qkvb + (size_t)t*3*CC + h*HDIM;
        Qs[w][lane] = qp[lane];
        if (lane < HDIM - 32) Qs[w][lane + 32] = qp[lane + 32];
        __syncwarp();
        float sc[4]; float mx = -FLT_MAX;
        #pragma unroll
        for (int r = 0; r < 4; r++){
            int m = lane + r*32;
            float s = -FLT_MAX;
            if (m < NTOK){
                s = 0.f;
                #pragma unroll
                for (int d = 0; d < HDIM; d++) s = fmaf(Qs[w][d], Ks[m][d], s);
                s *= scale;
            }
            sc[r] = s; mx = fmaxf(mx, s);
        }
        for (int o = 16; o; o >>= 1) mx = fmaxf(mx, __shfl_xor_sync(~0u, mx, o));
        float sum = 0.f;
        #pragma unroll
        for (int r = 0; r < 4; r++){
            int m = lane + r*32;
            float e = (m < NTOK) ? expf(sc[r] - mx) : 0.f;
            sc[r] = e; sum += e;
        }
        for (int o = 16; o; o >>= 1) sum += __shfl_xor_sync(~0u, sum, o);
        float inv = 1.f / sum;
        #pragma unroll
        for (int r = 0; r < 4; r++){
            int m = lane + r*32;
            if (m < NTOK) Ps[w][m] = sc[r] * inv;
        }
        __syncwarp();
        for (int d = lane; d < HDIM; d += 32){
            float o = 0.f;
            for (int m = 0; m < NTOK; m++) o = fmaf(Ps[w][m], Vs[m][d], o);
            g_attnout[((size_t)b*NTOK + t)*CC + h*HDIM + d] = o;
        }
        __syncwarp();
    }
}

// ===================== depthwise 3x3 (fp16 in) + transpose + fp16 store ==========
__global__ void k_dwconv_t(const float* __restrict__ dw_w, const float* __restrict__ dw_b,
                           __half* __restrict__ dh){
    __shared__ float t[32][33];
    int b = blockIdx.z, c0 = blockIdx.y * 32, n0 = blockIdx.x * 32;
    int tid = threadIdx.y * 32 + threadIdx.x;
    for (int r = threadIdx.y; r < 32; r += 8){
        int c = c0 + r;
        int n = n0 + threadIdx.x;
        const __half* src = g_h1 + ((size_t)b * CC + c) * NN;
        int y = n / WW, xp = n % WW;
        const float* w = dw_w + c * 9;
        float acc = dw_b[c];
        #pragma unroll
        for (int dy = -1; dy <= 1; dy++){
            int yy = y + dy;
            if (yy < 0 || yy >= HH) continue;
            #pragma unroll
            for (int dx = -1; dx <= 1; dx++){
                int xw = xp + dx;
                if (xw < 0 || xw >= WW) continue;
                acc = fmaf(__half2float(src[yy*WW + xw]), w[(dy+1)*3 + (dx+1)], acc);
            }
        }
        t[r][threadIdx.x] = acc;
    }
    __syncthreads();
    uint32_t* dh32 = (uint32_t*)(dh + (size_t)b * NN * CC);
    for (int idx = tid; idx < 32 * 16; idx += 256){
        int nr = idx >> 4, cu = idx & 15;
        uint32_t ph = (uint32_t)__half_as_ushort(__float2half_rn(t[2*cu][nr]))
                    | ((uint32_t)__half_as_ushort(__float2half_rn(t[2*cu+1][nr])) << 16);
        size_t o = ((size_t)(n0 + nr) * CC + c0) / 2 + cu;
        dh32[o] = ph;
    }
}

// ====== warp-mma fp16 GEMM (128x128 tile, 128 threads, 4 warps 2x2) ====
// NPROD=1: D = Ah*Bh^T (3-stage pipeline).  NPROD=2: D = (Ah+Al)*Bh^T (2-stage).
// MODE 0: h1(fp16) = gelu(acc/64 + b1[m]);  MODE 1: out(fp32) = acc/64 + b2[m] + ptok_bg
// MODE 2: qkv = acc/64 + qkv_b[n];          MODE 3: ptok = acc/64
#define LDS_B 80
#define EPITCH 132
#define MM_SMEM (128*EPITCH*4)       // 67584 B; covers 3 stages (NPROD=1) / 2 stages (NPROD=2)
#define JSTRIDE (32*CC*2)

template<int MODE, int NPROD>
__global__ void __launch_bounds__(128)
k_mm(const __half* __restrict__ Aph, const __half* __restrict__ Apl,
     const __half* __restrict__ Bh_,
     float* __restrict__ Out, const float* __restrict__ bias,
     int Mrows, int Nrows){
    constexpr int AR   = 128 * NPROD;          // A rows per stage
    constexpr int STGB = (AR + 128) * LDS_B;   // stage bytes
    constexpr int NSTG = (NPROD == 1) ? 3 : 2; // pipeline depth
    extern __shared__ char smem[];
    uint32_t sb = smem_to_u32(smem);
    int tid = threadIdx.x, wid = tid >> 5, lane = tid & 31;
    int m0 = blockIdx.x * 128, n0 = blockIdx.y * 128;
    int b = blockIdx.z;
    const __half* Bph = Bh_;
    if (MODE <= 1) Bph += (size_t)b * NN * CC;

    int r0 = tid >> 2, cu4 = tid & 3;
    const char* fAh = (const char*)Aph + ((size_t)(m0 + r0) * CC) * 2 + cu4 * 16;
    const char* fAl = (NPROD == 2)
        ? (const char*)Apl + ((size_t)(m0 + r0) * CC) * 2 + cu4 * 16 : (const char*)0;
    const char* fBh = (const char*)Bph + ((size_t)(n0 + r0) * CC) * 2 + cu4 * 16;
    uint32_t d0 = (uint32_t)(r0 * LDS_B + cu4 * 16);
    bool fast = (m0 + 128 <= Mrows) && (n0 + 128 <= Nrows);

    #define LOADC_F(ch, st) do {                                                  \
        uint32_t s0w = sb + (st) * STGB;                                          \
        int kb = (ch) * 64;                                                       \
        _Pragma("unroll")                                                         \
        for (int q = 0; q < 4; q++){                                              \
            CP_ASYNC16(s0w + d0 + q*(32*LDS_B),            fAh + kb + q*JSTRIDE, 16); \
            if (NPROD == 2)                                                       \
                CP_ASYNC16(s0w + d0 + q*(32*LDS_B) + 128*LDS_B, fAl + kb + q*JSTRIDE, 16); \
            CP_ASYNC16(s0w + d0 + q*(32*LDS_B) + AR*LDS_B, fBh + kb + q*JSTRIDE, 16); \
        }                                                                         \
        CP_ASYNC_COMMIT();                                                        \
    } while(0)

    #define LOADC_S(ch, st) do {                                                  \
        int k0 = (ch) * 32;                                                       \
        uint32_t s0w = sb + (st) * STGB;                                          \
        _Pragma("unroll")                                                         \
        for (int i = tid; i < (AR + 128) * 4; i += 128){                          \
            int r = i >> 2, cu = i & 3;                                           \
            uint32_t dst = s0w + (uint32_t)(r * LDS_B + cu * 16);                 \
            const char* src; uint32_t sz;                                         \
            if (r < AR){                                                          \
                int rr = r & 127;                                                 \
                int gm = m0 + rr;                                                 \
                sz = (gm < Mrows) ? 16u : 0u;                                     \
                int gmc = (gm < Mrows) ? gm : 0;                                  \
                const __half* base = (r < 128) ? Aph : Apl;                       \
                src = (const char*)(base + (size_t)gmc*CC + k0) + cu*16;          \
            } else {                                                              \
                int rr = (r - AR) & 127;                                          \
                int gn = n0 + rr;                                                 \
                sz = (gn < Nrows) ? 16u : 0u;                                     \
                int gnc = (gn < Nrows) ? gn : 0;                                  \
                src = (const char*)(Bph + (size_t)gnc*CC + k0) + cu*16;           \
            }                                                                     \
            CP_ASYNC16(dst, src, sz);                                             \
        }                                                                         \
        CP_ASYNC_COMMIT();                                                        \
    } while(0)

    float acc[4][8][4] = {};
    if (fast){
        LOADC_F(0, 0); LOADC_F(1, 1);
        if (NSTG == 3) LOADC_F(2, 2);
    } else {
        LOADC_S(0, 0); LOADC_S(1, 1);
        if (NSTG == 3) LOADC_S(2, 2);
    }

    int wm = (wid >> 1) * 64, wn = (wid & 1) * 64;
    uint32_t a_off = (uint32_t)(wm + (lane & 15)) * LDS_B + ((lane >> 4) & 1) * 16;
    uint32_t b_off = (uint32_t)(wn + (lane & 7) + ((lane >> 4) & 1) * 8) * LDS_B
                   + ((lane >> 3) & 1) * 16;

    #pragma unroll 1
    for (int c = 0; c < 12; c++){
        if (NSTG == 3) CP_ASYNC_WAIT(2);
        else           CP_ASYNC_WAIT(1);
        __syncthreads();
        uint32_t s0 = sb + (c % NSTG) * STGB;
        #pragma unroll
        for (int kk = 0; kk < 2; kk++){
            uint32_t ah[4][4], al[4][4];
            #pragma unroll
            for (int i = 0; i < 4; i++){
                uint32_t ra = s0 + a_off + (uint32_t)(i * 16 * LDS_B) + kk * 32;
                ldsm_x4(ah[i], ra);
                if (NPROD == 2) ldsm_x4(al[i], ra + 128 * LDS_B);
            }
            #pragma unroll
            for (int j = 0; j < 4; j++){
                uint32_t bh[4];
                uint32_t rb = s0 + AR * LDS_B + b_off + (uint32_t)(j * 16 * LDS_B) + kk * 32;
                ldsm_x4(bh, rb);
                #pragma unroll
                for (int i = 0; i < 4; i++) mma16816h(acc[i][j*2+0], ah[i], bh[0], bh[1]);
                #pragma unroll
                for (int i = 0; i < 4; i++) mma16816h(acc[i][j*2+1], ah[i], bh[2], bh[3]);
                if (NPROD == 2){
                    #pragma unroll
                    for (int i = 0; i < 4; i++) mma16816h(acc[i][j*2+0], al[i], bh[0], bh[1]);
                    #pragma unroll
                    for (int i = 0; i < 4; i++) mma16816h(acc[i][j*2+1], al[i], bh[2], bh[3]);
                }
            }
        }
        __syncthreads();
        if (c + NSTG < 12){
            if (fast) LOADC_F(c + NSTG, c % NSTG);
            else      LOADC_S(c + NSTG, c % NSTG);
        } else CP_ASYNC_COMMIT();
    }
    CP_ASYNC_WAIT(0);
    __syncthreads();

    // ---- stage accumulators in smem, then coalesced stores ----
    float* eps = (float*)smem;
    int rbase = wm + (lane >> 2);
    int cbase = wn + (lane & 3) * 2;
    #pragma unroll
    for (int i = 0; i < 4; i++)
        #pragma unroll
        for (int half = 0; half < 2; half++){
            int ml = rbase + i * 16 + half * 8;
            #pragma unroll
            for (int j = 0; j < 8; j++){
                int nl = cbase + j * 8;
                eps[ml * EPITCH + nl    ] = acc[i][j][half*2+0];
                eps[ml * EPITCH + nl + 1] = acc[i][j][half*2+1];
            }
        }
    __syncthreads();
    for (int idx = tid; idx < 128 * 32; idx += 128){
        int ml = idx >> 5, nl = (idx & 31) * 4;
        float4 v = *(const float4*)&eps[ml * EPITCH + nl];
        int m = m0 + ml, n = n0 + nl;
        v.x *= INVWSC; v.y *= INVWSC; v.z *= INVWSC; v.w *= INVWSC;
        if (MODE == 0){
            if (n >= Nrows) continue;
            float bs = bias[m];
            v.x = gelu_exact(v.x + bs); v.y = gelu_exact(v.y + bs);
            v.z = gelu_exact(v.z + bs); v.w = gelu_exact(v.w + bs);
            __half* hp = (__half*)Out + ((size_t)b*CC + m)*NN + n;
            *(__half2*)(hp    ) = __floats2half2_rn(v.x, v.y);
            *(__half2*)(hp + 2) = __floats2half2_rn(v.z, v.w);
        } else if (MODE == 1){
            if (n >= Nrows) continue;
            float bs = bias[m] + g_ptok[((size_t)b*NTOK + TOPK)*CC + m];
            v.x += bs; v.y += bs; v.z += bs; v.w += bs;
            *(float4*)&Out[((size_t)b*CC + m)*NN + n] = v;
        } else {
            if (m >= Mrows || n >= Nrows) continue;
            if (MODE == 2){
                v.x += bias[n]; v.y += bias[n+1]; v.z += bias[n+2]; v.w += bias[n+3];
            }
            *(float4*)&Out[(size_t)m * (MODE == 2 ? 3*CC : CC) + n] = v;
        }
    }
    #undef LOADC_F
    #undef LOADC_S
}

// ===================== scatter projected top tokens =====================
__global__ void k_scatter(float* __restrict__ out){
    int b = blockIdx.x / TOPK, j = blockIdx.x % TOPK;
    int o = threadIdx.x;
    int n = g_topidx[b*TOPK + j];
    float d = g_ptok[((size_t)b*NTOK + j   )*CC + o]
            - g_ptok[((size_t)b*NTOK + TOPK)*CC + o];
    out[((size_t)b*CC + o)*NN + n] += d;
}

// ===================== host launch =====================
extern "C" void kernel_launch(void* const* d_in, const int* in_sizes, int n_in,
                              void* d_out, int out_size){
    const float* x      = (const float*)d_in[0];
    const float* qkv_w  = (const float*)d_in[1];
    const float* qkv_b  = (const float*)d_in[2];
    const float* proj_w = (const float*)d_in[3];
    const float* proj_b = (const float*)d_in[4];
    const float* bn_g   = (const float*)d_in[5];
    const float* bn_b   = (const float*)d_in[6];
    const float* fc1_w  = (const float*)d_in[7];
    const float* fc1_b  = (const float*)d_in[8];
    const float* fc2_w  = (const float*)d_in[9];
    const float* fc2_b  = (const float*)d_in[10];
    const float* dw_w   = (const float*)d_in[11];
    const float* dw_b   = (const float*)d_in[12];
    float* out = (float*)d_out;

    float *p_qkv, *p_attnout, *p_ptok, *p_b1, *p_b2;
    __half *p_h1, *p_h2t, *p_W1h, *p_W2h, *p_xth;
    __half *p_tokh, *p_aoh, *p_aol, *p_qw16, *p_pw16;
    cudaGetSymbolAddress((void**)&p_qkv    , g_qkv);
    cudaGetSymbolAddress((void**)&p_attnout, g_attnout);
    cudaGetSymbolAddress((void**)&p_ptok   , g_ptok);
    cudaGetSymbolAddress((void**)&p_b1     , g_b1);
    cudaGetSymbolAddress((void**)&p_b2     , g_b2);
    cudaGetSymbolAddress((void**)&p_h1     , g_h1);
    cudaGetSymbolAddress((void**)&p_h2t    , g_h2t);
    cudaGetSymbolAddress((void**)&p_W1h    , g_W1h);
    cudaGetSymbolAddress((void**)&p_W2h    , g_W2h);
    cudaGetSymbolAddress((void**)&p_xth    , g_xth);
    cudaGetSymbolAddress((void**)&p_tokh   , g_tokh);
    cudaGetSymbolAddress((void**)&p_aoh    , g_aoh);
    cudaGetSymbolAddress((void**)&p_aol    , g_aol);
    cudaGetSymbolAddress((void**)&p_qw16   , g_qw16);
    cudaGetSymbolAddress((void**)&p_pw16   , g_pw16);

    cudaFuncSetAttribute((const void*)k_mm<0,1>, cudaFuncAttributeMaxDynamicSharedMemorySize, MM_SMEM);
    cudaFuncSetAttribute((const void*)k_mm<1,1>, cudaFuncAttributeMaxDynamicSharedMemorySize, MM_SMEM);
    cudaFuncSetAttribute((const void*)k_mm<2,1>, cudaFuncAttributeMaxDynamicSharedMemorySize, MM_SMEM);
    cudaFuncSetAttribute((const void*)k_mm<3,2>, cudaFuncAttributeMaxDynamicSharedMemorySize, MM_SMEM);

    cudaStream_t s2;
    cudaStreamCreateWithFlags(&s2, cudaStreamNonBlocking);
    cudaEvent_t evF, evJ;
    cudaEventCreateWithFlags(&evF, cudaEventDisableTiming);
    cudaEventCreateWithFlags(&evJ, cudaEventDisableTiming);

    // ---- stream 0: conv-mixer chain ----
    k_xpass   <<<dim3(NTIL, CTIL, BB), 256>>>(x, p_xth);
    k_redstats<<<(BB*CC + 255)/256, 256>>>();
    cudaEventRecord(evF, 0);
    cudaStreamWaitEvent(s2, evF, 0);
    k_prepW1  <<<CC, CC>>>(fc1_w, fc1_b, bn_g, bn_b);
    dim3 gbig(CC/128, (NN + 127)/128, BB);
    k_mm<0,1><<<gbig, 128, MM_SMEM>>>(p_W1h, (const __half*)nullptr, p_xth,
                                      (float*)p_h1, p_b1, CC, NN);
    k_dwconv_t<<<dim3(NN/32, CC/32, BB), dim3(32, 8)>>>(dw_w, dw_b, p_h2t);

    // ---- stream s2: salience branch (overlaps with k_mm<0> + dwconv) ----
    k_scores_red<<<(BB*NN + 255)/256, 256, 0, s2>>>();
    k_prepW2  <<<CC, CC, 0, s2>>>(proj_w, fc2_w, fc2_b, proj_b);
    k_prep_w16<<<(3*CC*CC + 255)/256, 256, 0, s2>>>(qkv_w,  p_qw16, 3*CC*CC);
    k_prep_w16<<<(CC*CC   + 255)/256, 256, 0, s2>>>(proj_w, p_pw16, CC*CC);
    k_topk      <<<BB, 256, 0, s2>>>();
    k_gather_tok<<<dim3(TOPK, BB), 192, 0, s2>>>(p_xth);
    k_bgtok     <<<BB, CC, 0, s2>>>();
    k_mm<2,1><<<dim3((MTOK + 127)/128, (3*CC + 127)/128, 1), 128, MM_SMEM, s2>>>(
        p_tokh, (const __half*)nullptr, p_qw16, p_qkv, qkv_b, MTOK, 3*CC);
    k_attention <<<BB*NHEAD, 128, 0, s2>>>();
    k_split_rows<<<(MTOK*CC + 255)/256, 256, 0, s2>>>(p_attnout, p_aoh, p_aol, MTOK*CC);
    k_mm<3,2><<<dim3((MTOK + 127)/128, CC/128, 1), 128, MM_SMEM, s2>>>(
        p_aoh, p_aol, p_pw16, p_ptok, (const float*)nullptr, MTOK, CC);
    cudaEventRecord(evJ, s2);
    cudaStreamWaitEvent(0, evJ, 0);

    // ---- stream 0: final GEMM + scatter ----
    k_mm<1,1><<<gbig, 128, MM_SMEM>>>(p_W2h, (const __half*)nullptr, p_h2t, out, p_b2, CC, NN);
    k_scatter<<<BB*TOPK, CC>>>(out);
}